// round 2
// baseline (speedup 1.0000x reference)
#include <cuda_runtime.h>
#include <cuda_bf16.h>

// Problem constants
#define SEQ    128
#define BATCH  64
#define EMB    512
#define HID    1024
#define VOCAB  10000
#define MB     (SEQ*BATCH)        // 8192 rows when time-batched
#define STEP   (BATCH*HID)        // 65536 floats per timestep slab

// Scratch (device globals: no allocation allowed in kernel_launch)
__device__ float g_X0[MB*HID];   // emb[tok]@W0x^T + b0   (all steps)
__device__ float g_H0[MB*HID];   // layer-0 hidden states (all steps)
__device__ float g_X1[MB*HID];   // H0@W1x^T + b1         (all steps)
__device__ float g_H1[MB*HID];   // layer-1 hidden states (all steps)

// ---------------------------------------------------------------------------
// Tiled SGEMM: C[M,N] = A[M,K] @ W[N,K]^T + bias[N]
// A rows optionally gathered through `rows` (embedding lookup).
// BM=BN=128, BK=8, 256 threads, 8x8 microtile. M must be a multiple of 128;
// K a multiple of 8; N a multiple of 4 (bounds-checked per 128-tile).
// ---------------------------------------------------------------------------
template<bool GATHER>
__global__ __launch_bounds__(256)
void sgemm_bias(const float* __restrict__ A, const int* __restrict__ rows,
                const float* __restrict__ W, const float* __restrict__ bias,
                float* __restrict__ C, int M, int N, int K)
{
    __shared__ float As[8][128];
    __shared__ float Ws[8][128];

    const int tid = threadIdx.x;
    const int m0 = blockIdx.y * 128;
    const int n0 = blockIdx.x * 128;

    const int lr = tid >> 1;          // 0..127 (tile row for loads)
    const int lc = (tid & 1) * 4;     // 0 or 4 (k sub-column, float4)

    const float* arow;
    {
        int m = m0 + lr;
        long r = GATHER ? (long)rows[m] : (long)m;
        arow = A + r * (long)K;
    }
    const bool wvalid = (n0 + lr) < N;
    const float* wrow = wvalid ? (W + (long)(n0 + lr) * K) : W;

    const int tm = (tid >> 4) * 8;    // microtile row offset
    const int tn = (tid & 15) * 8;    // microtile col offset

    float acc[8][8];
    #pragma unroll
    for (int i = 0; i < 8; i++)
        #pragma unroll
        for (int j = 0; j < 8; j++) acc[i][j] = 0.f;

    for (int kt = 0; kt < K; kt += 8) {
        float4 av = *reinterpret_cast<const float4*>(arow + kt + lc);
        float4 wv = make_float4(0.f, 0.f, 0.f, 0.f);
        if (wvalid) wv = *reinterpret_cast<const float4*>(wrow + kt + lc);

        __syncthreads();   // protect previous tile's reads
        As[lc+0][lr] = av.x; As[lc+1][lr] = av.y;
        As[lc+2][lr] = av.z; As[lc+3][lr] = av.w;
        Ws[lc+0][lr] = wv.x; Ws[lc+1][lr] = wv.y;
        Ws[lc+2][lr] = wv.z; Ws[lc+3][lr] = wv.w;
        __syncthreads();

        #pragma unroll
        for (int kk = 0; kk < 8; kk++) {
            float rm[8], rn[8];
            *reinterpret_cast<float4*>(&rm[0]) = *reinterpret_cast<const float4*>(&As[kk][tm]);
            *reinterpret_cast<float4*>(&rm[4]) = *reinterpret_cast<const float4*>(&As[kk][tm+4]);
            *reinterpret_cast<float4*>(&rn[0]) = *reinterpret_cast<const float4*>(&Ws[kk][tn]);
            *reinterpret_cast<float4*>(&rn[4]) = *reinterpret_cast<const float4*>(&Ws[kk][tn+4]);
            #pragma unroll
            for (int i = 0; i < 8; i++)
                #pragma unroll
                for (int j = 0; j < 8; j++)
                    acc[i][j] = fmaf(rm[i], rn[j], acc[i][j]);
        }
    }

    // Epilogue: + bias, bounds-checked float4 stores (N % 4 == 0)
    #pragma unroll
    for (int i = 0; i < 8; i++) {
        long r = m0 + tm + i;
        #pragma unroll
        for (int j = 0; j < 8; j += 4) {
            int c = n0 + tn + j;
            if (c < N) {
                float4 v;
                v.x = acc[i][j+0] + bias[c+0];
                v.y = acc[i][j+1] + bias[c+1];
                v.z = acc[i][j+2] + bias[c+2];
                v.w = acc[i][j+3] + bias[c+3];
                *reinterpret_cast<float4*>(C + r * N + c) = v;
            }
        }
    }
}

// ---------------------------------------------------------------------------
// One recurrence step: hout[b,j] = tanh(X[b,j] + sum_k hprev[b,k]*W[j,k])
// b in [0,64), j in [0,1024). Grid: 128 blocks x 8 j-columns; 256 threads;
// thread (b = tid&63, g = tid>>6) computes 2 adjacent j's. K tiled by 32
// through shared memory (hs padded to 33 -> conflict-free column reads).
// layer/t select the scratch slabs (device-global pointers not visible host-side
// via arithmetic, so slabs are resolved in-kernel).
// ---------------------------------------------------------------------------
__global__ __launch_bounds__(256)
void rnn_step(const float* __restrict__ hidden_init,
              const float* __restrict__ W,   // HID x HID
              int t, int layer)
{
    __shared__ float hs[64][33];
    __shared__ float ws[8][33];

    const float* X  = (layer == 0 ? g_X0 : g_X1) + (long)t * STEP;
    float*       Ho = (layer == 0 ? g_H0 : g_H1);
    const float* hprev = (t == 0)
        ? (hidden_init + (long)layer * STEP)
        : (Ho + (long)(t - 1) * STEP);
    float* hout = Ho + (long)t * STEP;

    const int tid = threadIdx.x;
    const int j0  = blockIdx.x * 8;
    const int b   = tid & 63;
    const int g   = tid >> 6;          // 0..3
    const int jg  = 2 * g;

    float acc0 = 0.f, acc1 = 0.f;

    for (int kt = 0; kt < HID; kt += 32) {
        // load hprev tile 64x32 (coalesced float4)
        {
            int r = tid >> 2;            // 0..63
            int c = (tid & 3) * 8;       // 0,8,16,24
            const float4* src = reinterpret_cast<const float4*>(hprev + (long)r * HID + kt + c);
            float4 v0 = src[0], v1 = src[1];
            hs[r][c+0] = v0.x; hs[r][c+1] = v0.y; hs[r][c+2] = v0.z; hs[r][c+3] = v0.w;
            hs[r][c+4] = v1.x; hs[r][c+5] = v1.y; hs[r][c+6] = v1.z; hs[r][c+7] = v1.w;
        }
        // load W tile 8x32
        {
            int r = tid >> 5;            // 0..7
            int c = tid & 31;
            ws[r][c] = W[(long)(j0 + r) * HID + kt + c];
        }
        __syncthreads();
        #pragma unroll
        for (int kk = 0; kk < 32; kk++) {
            float rh = hs[b][kk];
            acc0 = fmaf(rh, ws[jg  ][kk], acc0);
            acc1 = fmaf(rh, ws[jg+1][kk], acc1);
        }
        __syncthreads();
    }

    int j = j0 + jg;
    long base = (long)b * HID + j;
    hout[base    ] = tanhf(acc0 + X[base    ]);
    hout[base + 1] = tanhf(acc1 + X[base + 1]);
}

// ---------------------------------------------------------------------------
// final_hidden = stack([H0[last], H1[last]]) appended after the logits
// ---------------------------------------------------------------------------
__global__ void copy_tail(float* __restrict__ dst)
{
    int i = blockIdx.x * blockDim.x + threadIdx.x;
    if (i < STEP)          dst[i] = g_H0[(long)(SEQ - 1) * STEP + i];
    else if (i < 2 * STEP) dst[i] = g_H1[(long)(SEQ - 1) * STEP + (i - STEP)];
}

// ---------------------------------------------------------------------------
extern "C" void kernel_launch(void* const* d_in, const int* in_sizes, int n_in,
                              void* d_out, int out_size)
{
    const int*   tok    = (const int*)  d_in[0];
    const float* hidden = (const float*)d_in[1];
    const float* emb    = (const float*)d_in[2];
    const float* W0x    = (const float*)d_in[3];
    const float* W0h    = (const float*)d_in[4];
    const float* b0     = (const float*)d_in[5];
    const float* W1x    = (const float*)d_in[6];
    const float* W1h    = (const float*)d_in[7];
    const float* b1     = (const float*)d_in[8];
    const float* Wout   = (const float*)d_in[9];
    const float* bout   = (const float*)d_in[10];
    float* out = (float*)d_out;

    float *X0, *H0, *X1, *H1;
    cudaGetSymbolAddress((void**)&X0, g_X0);
    cudaGetSymbolAddress((void**)&H0, g_H0);
    cudaGetSymbolAddress((void**)&X1, g_X1);
    cudaGetSymbolAddress((void**)&H1, g_H1);

    dim3 blk(256);

    // Phase A: X0 = emb[tok] @ W0x^T + b0   (8192 x 1024 x 512, gathered A)
    sgemm_bias<true><<<dim3(HID/128, MB/128), blk>>>(emb, tok, W0x, b0, X0, MB, HID, EMB);

    // Phase B: layer-0 recurrence
    for (int t = 0; t < SEQ; t++)
        rnn_step<<<HID/8, 256>>>(hidden, W0h, t, 0);

    // Phase C: X1 = H0 @ W1x^T + b1   (8192 x 1024 x 1024)
    sgemm_bias<false><<<dim3(HID/128, MB/128), blk>>>(H0, nullptr, W1x, b1, X1, MB, HID, HID);

    // Phase D: layer-1 recurrence
    for (int t = 0; t < SEQ; t++)
        rnn_step<<<HID/8, 256>>>(hidden, W1h, t, 1);

    // Phase E: logits = H1 @ Wout^T + bout   (8192 x 10000 x 1024)
    sgemm_bias<false><<<dim3((VOCAB + 127)/128, MB/128), blk>>>(H1, nullptr, Wout, bout, out, MB, VOCAB, HID);

    // Tail: final hidden states
    copy_tail<<<(2*STEP + 255)/256, 256>>>(out + (long)SEQ * BATCH * VOCAB);
}

// round 3
// speedup vs baseline: 1.5110x; 1.5110x over previous
#include <cuda_runtime.h>
#include <cuda_bf16.h>
#include <cstdint>

// Problem constants
#define SEQ    128
#define BATCH  64
#define EMB    512
#define HID    1024
#define VOCAB  10000
#define MB     (SEQ*BATCH)        // 8192 rows when time-batched
#define STEP   (BATCH*HID)        // 65536 floats per timestep slab

// Scratch (device globals: no allocation allowed in kernel_launch)
__device__ float g_X0[MB*HID];   // emb[tok]@W0x^T + b0   (all steps)
__device__ float g_H0[MB*HID];   // layer-0 hidden states (all steps)
__device__ float g_X1[MB*HID];   // H0@W1x^T + b1         (all steps)
__device__ float g_H1[MB*HID];   // layer-1 hidden states (all steps)
__device__ unsigned g_cnt[128];  // per-step grid-barrier counters (rolling reset)

// ---------------------------------------------------------------------------
// Tiled SGEMM: C[M,N] = A[M,K] @ W[N,K]^T + bias[N]   (unchanged from R2)
// ---------------------------------------------------------------------------
template<bool GATHER>
__global__ __launch_bounds__(256)
void sgemm_bias(const float* __restrict__ A, const int* __restrict__ rows,
                const float* __restrict__ W, const float* __restrict__ bias,
                float* __restrict__ C, int M, int N, int K)
{
    __shared__ float As[8][128];
    __shared__ float Ws[8][128];

    const int tid = threadIdx.x;
    const int m0 = blockIdx.y * 128;
    const int n0 = blockIdx.x * 128;

    const int lr = tid >> 1;          // 0..127
    const int lc = (tid & 1) * 4;     // 0 or 4

    const float* arow;
    {
        int m = m0 + lr;
        long r = GATHER ? (long)rows[m] : (long)m;
        arow = A + r * (long)K;
    }
    const bool wvalid = (n0 + lr) < N;
    const float* wrow = wvalid ? (W + (long)(n0 + lr) * K) : W;

    const int tm = (tid >> 4) * 8;
    const int tn = (tid & 15) * 8;

    float acc[8][8];
    #pragma unroll
    for (int i = 0; i < 8; i++)
        #pragma unroll
        for (int j = 0; j < 8; j++) acc[i][j] = 0.f;

    for (int kt = 0; kt < K; kt += 8) {
        float4 av = *reinterpret_cast<const float4*>(arow + kt + lc);
        float4 wv = make_float4(0.f, 0.f, 0.f, 0.f);
        if (wvalid) wv = *reinterpret_cast<const float4*>(wrow + kt + lc);

        __syncthreads();
        As[lc+0][lr] = av.x; As[lc+1][lr] = av.y;
        As[lc+2][lr] = av.z; As[lc+3][lr] = av.w;
        Ws[lc+0][lr] = wv.x; Ws[lc+1][lr] = wv.y;
        Ws[lc+2][lr] = wv.z; Ws[lc+3][lr] = wv.w;
        __syncthreads();

        #pragma unroll
        for (int kk = 0; kk < 8; kk++) {
            float rm[8], rn[8];
            *reinterpret_cast<float4*>(&rm[0]) = *reinterpret_cast<const float4*>(&As[kk][tm]);
            *reinterpret_cast<float4*>(&rm[4]) = *reinterpret_cast<const float4*>(&As[kk][tm+4]);
            *reinterpret_cast<float4*>(&rn[0]) = *reinterpret_cast<const float4*>(&Ws[kk][tn]);
            *reinterpret_cast<float4*>(&rn[4]) = *reinterpret_cast<const float4*>(&Ws[kk][tn+4]);
            #pragma unroll
            for (int i = 0; i < 8; i++)
                #pragma unroll
                for (int j = 0; j < 8; j++)
                    acc[i][j] = fmaf(rm[i], rn[j], acc[i][j]);
        }
    }

    #pragma unroll
    for (int i = 0; i < 8; i++) {
        long r = m0 + tm + i;
        #pragma unroll
        for (int j = 0; j < 8; j += 4) {
            int c = n0 + tn + j;
            if (c < N) {
                float4 v;
                v.x = acc[i][j+0] + bias[c+0];
                v.y = acc[i][j+1] + bias[c+1];
                v.z = acc[i][j+2] + bias[c+2];
                v.w = acc[i][j+3] + bias[c+3];
                *reinterpret_cast<float4*>(C + r * N + c) = v;
            }
        }
    }
}

// ---------------------------------------------------------------------------
// Persistent per-layer recurrence kernel.
// Grid: 128 blocks x 128 threads. Block owns 8 output columns [j0, j0+8).
//   - W slice (8x1024 = 32KB) resident in smem for the whole layer.
//   - Per step: hprev (64x1024) staged through double-buffered k-transposed
//     smem tiles hs[k][b] (pitch 65 -> conflict-free), via 4B cp.async.
//   - Warps split k (warp w covers tile-local k in [32w,32w+32)); each thread
//     holds acc[2][8] for (b=lane, b=lane+32) x 8 columns. Cross-warp partial
//     sums reduced through padded smem, then tanh(acc + X) -> H[t].
//   - Software grid barrier per step using g_cnt[t] with rolling reset so
//     counters are zero again at the start of every launch/graph replay.
// ---------------------------------------------------------------------------
#define TK   128     // k-tile size
#define HSP  65      // hs row pitch (64 b + 1 pad)
#define RNB  128     // blocks
#define RNT  128     // threads per block

// dynamic smem partition (floats)
#define SM_WS   0
#define SM_HS   (8*1024)
#define SM_RED  (SM_HS + 2*TK*HSP)
#define SM_FLOATS (SM_RED + 4*2*32*9)
#define SM_BYTES  131072   // padded to 128KB so only one block fits per SM

__global__ __launch_bounds__(RNT, 1)
void rnn_layer(const float* __restrict__ h0init,
               const float* __restrict__ W,
               const float* __restrict__ X,
               float* __restrict__ H)
{
    extern __shared__ float sm[];
    float* Ws  = sm + SM_WS;    // [8][1024]
    float* hs  = sm + SM_HS;    // [2][TK][HSP]
    float* red = sm + SM_RED;   // [4][2][32][9]

    const int tid  = threadIdx.x;
    const int lane = tid & 31;
    const int warp = tid >> 5;
    const int j0   = blockIdx.x * 8;

    // Load W slice once (coalesced float4)
    for (int i = tid; i < 8*1024/4; i += RNT) {
        int j  = i >> 8;        // 0..7
        int kq = i & 255;       // float4 index within row
        float4 v = *reinterpret_cast<const float4*>(W + (long)(j0 + j) * HID + kq * 4);
        *reinterpret_cast<float4*>(Ws + j*1024 + kq*4) = v;
    }
    __syncthreads();

    const uint32_t hs_s = (uint32_t)__cvta_generic_to_shared(hs);

    for (int t = 0; t < SEQ; t++) {
        const float* hprev = (t == 0) ? h0init : (H + (long)(t-1) * STEP);

        float acc0[8], acc1[8];
        #pragma unroll
        for (int j = 0; j < 8; j++) { acc0[j] = 0.f; acc1[j] = 0.f; }

        // preload tile 0 into buffer 0 (thread tid owns k-column tid)
        {
            const float* src = hprev + tid;
            uint32_t dst = hs_s + (uint32_t)(tid * HSP) * 4u;
            #pragma unroll 16
            for (int b = 0; b < 64; b++)
                asm volatile("cp.async.ca.shared.global [%0], [%1], 4;"
                             :: "r"(dst + b*4u), "l"(src + (long)b*HID));
            asm volatile("cp.async.commit_group;");
        }

        int buf = 0;
        #pragma unroll 1
        for (int tile = 0; tile < 8; tile++) {
            if (tile < 7) {
                const float* src = hprev + (tile+1)*TK + tid;
                uint32_t dst = hs_s + (uint32_t)((((buf^1)*TK) + tid) * HSP) * 4u;
                #pragma unroll 16
                for (int b = 0; b < 64; b++)
                    asm volatile("cp.async.ca.shared.global [%0], [%1], 4;"
                                 :: "r"(dst + b*4u), "l"(src + (long)b*HID));
                asm volatile("cp.async.commit_group;");
                asm volatile("cp.async.wait_group 1;");
            } else {
                asm volatile("cp.async.wait_group 0;");
            }
            __syncthreads();   // tile `buf` fully visible to all threads

            const float* hb = hs + buf*TK*HSP;
            const int kwarp = warp * 32;
            #pragma unroll
            for (int q = 0; q < 8; q++) {
                const int kl = kwarp + q*4;          // tile-local k
                float h0[4], h1[4];
                #pragma unroll
                for (int i = 0; i < 4; i++) {
                    h0[i] = hb[(kl+i)*HSP + lane];
                    h1[i] = hb[(kl+i)*HSP + lane + 32];
                }
                const int kg = tile*TK + kl;         // global k (mult of 4)
                #pragma unroll
                for (int j = 0; j < 8; j++) {
                    float4 w = *reinterpret_cast<const float4*>(Ws + j*1024 + kg);
                    acc0[j] = fmaf(h0[0], w.x, acc0[j]);
                    acc0[j] = fmaf(h0[1], w.y, acc0[j]);
                    acc0[j] = fmaf(h0[2], w.z, acc0[j]);
                    acc0[j] = fmaf(h0[3], w.w, acc0[j]);
                    acc1[j] = fmaf(h1[0], w.x, acc1[j]);
                    acc1[j] = fmaf(h1[1], w.y, acc1[j]);
                    acc1[j] = fmaf(h1[2], w.z, acc1[j]);
                    acc1[j] = fmaf(h1[3], w.w, acc1[j]);
                }
            }
            __syncthreads();   // done reading `buf` before it is refilled
            buf ^= 1;
        }

        // cross-warp reduction (partial k-sums) through padded smem
        #pragma unroll
        for (int j = 0; j < 8; j++) {
            red[((warp*2 + 0)*32 + lane)*9 + j] = acc0[j];
            red[((warp*2 + 1)*32 + lane)*9 + j] = acc1[j];
        }
        __syncthreads();

        const float* Xt = X + (long)t * STEP;
        float*       Ht = H + (long)t * STEP;
        #pragma unroll
        for (int i = 0; i < 4; i++) {
            int o   = tid + i*128;       // 0..511
            int g   = o >> 8;            // b-half
            int rem = o & 255;
            int l   = rem >> 3;          // lane-b
            int j   = rem & 7;
            float s = red[((0*2+g)*32 + l)*9 + j]
                    + red[((1*2+g)*32 + l)*9 + j]
                    + red[((2*2+g)*32 + l)*9 + j]
                    + red[((3*2+g)*32 + l)*9 + j];
            int b   = g*32 + l;
            int col = j0 + j;
            Ht[(long)b*HID + col] = tanhf(s + Xt[(long)b*HID + col]);
        }

        // ---- software grid barrier (step t) ----
        __threadfence();      // make Ht stores GPU-visible before arrival
        __syncthreads();
        if (tid == 0) {
            atomicAdd(&g_cnt[t], 1u);
            while (*((volatile unsigned*)&g_cnt[t]) < (unsigned)RNB) {
                __nanosleep(40);
            }
            // rolling reset: counter (t+126)%128 provably drained by everyone
            if (blockIdx.x == 0)
                atomicExch(&g_cnt[(t + 126) & 127], 0u);
        }
        __syncthreads();
        __threadfence();      // acquire: other blocks' Ht visible before next reads
    }
}

// ---------------------------------------------------------------------------
// final_hidden = stack([H0[last], H1[last]]) appended after the logits
// ---------------------------------------------------------------------------
__global__ void copy_tail(float* __restrict__ dst)
{
    int i = blockIdx.x * blockDim.x + threadIdx.x;
    if (i < STEP)          dst[i] = g_H0[(long)(SEQ - 1) * STEP + i];
    else if (i < 2 * STEP) dst[i] = g_H1[(long)(SEQ - 1) * STEP + (i - STEP)];
}

// ---------------------------------------------------------------------------
extern "C" void kernel_launch(void* const* d_in, const int* in_sizes, int n_in,
                              void* d_out, int out_size)
{
    const int*   tok    = (const int*)  d_in[0];
    const float* hidden = (const float*)d_in[1];
    const float* emb    = (const float*)d_in[2];
    const float* W0x    = (const float*)d_in[3];
    const float* W0h    = (const float*)d_in[4];
    const float* b0     = (const float*)d_in[5];
    const float* W1x    = (const float*)d_in[6];
    const float* W1h    = (const float*)d_in[7];
    const float* b1     = (const float*)d_in[8];
    const float* Wout   = (const float*)d_in[9];
    const float* bout   = (const float*)d_in[10];
    float* out = (float*)d_out;

    float *X0, *H0, *X1, *H1;
    cudaGetSymbolAddress((void**)&X0, g_X0);
    cudaGetSymbolAddress((void**)&H0, g_H0);
    cudaGetSymbolAddress((void**)&X1, g_X1);
    cudaGetSymbolAddress((void**)&H1, g_H1);

    static bool attr_set = false;
    if (!attr_set) {
        cudaFuncSetAttribute(rnn_layer,
                             cudaFuncAttributeMaxDynamicSharedMemorySize, SM_BYTES);
        attr_set = true;
    }

    dim3 blk(256);

    // Phase A: X0 = emb[tok] @ W0x^T + b0   (8192 x 1024 x 512, gathered A)
    sgemm_bias<true><<<dim3(HID/128, MB/128), blk>>>(emb, tok, W0x, b0, X0, MB, HID, EMB);

    // Phase B: layer-0 recurrence (persistent, grid-synced)
    rnn_layer<<<RNB, RNT, SM_BYTES>>>(hidden, W0h, X0, H0);

    // Phase C: X1 = H0 @ W1x^T + b1   (8192 x 1024 x 1024)
    sgemm_bias<false><<<dim3(HID/128, MB/128), blk>>>(H0, nullptr, W1x, b1, X1, MB, HID, HID);

    // Phase D: layer-1 recurrence
    rnn_layer<<<RNB, RNT, SM_BYTES>>>(hidden + STEP, W1h, X1, H1);

    // Phase E: logits = H1 @ Wout^T + bout   (8192 x 10000 x 1024)
    sgemm_bias<false><<<dim3((VOCAB + 127)/128, MB/128), blk>>>(H1, nullptr, Wout, bout, out, MB, VOCAB, HID);

    // Tail: final hidden states
    copy_tail<<<(2*STEP + 255)/256, 256>>>(out + (long)SEQ * BATCH * VOCAB);
}

// round 5
// speedup vs baseline: 2.0261x; 1.3409x over previous
#include <cuda_runtime.h>
#include <cuda_bf16.h>
#include <cstdint>

// Problem constants
#define SEQ    128
#define BATCH  64
#define EMB    512
#define HID    1024
#define VOCAB  10000
#define MB     (SEQ*BATCH)        // 8192 rows when time-batched
#define STEP   (BATCH*HID)        // 65536 floats per timestep slab

// Scratch (device globals: no allocation allowed in kernel_launch)
__device__ float g_X0[MB*HID];
__device__ float g_H0[MB*HID];
__device__ float g_X1[MB*HID];
__device__ float g_H1[MB*HID];
__device__ unsigned g_cnt[128];
// bf16 split operands (hi/lo) for tensor-core GEMMs
__device__ __nv_bfloat16 g_EmbH[VOCAB*EMB], g_EmbL[VOCAB*EMB];
__device__ __nv_bfloat16 g_W0xH[HID*EMB],   g_W0xL[HID*EMB];
__device__ __nv_bfloat16 g_W1xH[HID*HID],   g_W1xL[HID*HID];
__device__ __nv_bfloat16 g_WoH[VOCAB*HID],  g_WoL[VOCAB*HID];
__device__ __nv_bfloat16 g_AH[MB*HID],      g_AL[MB*HID];   // reused H0 then H1

// ===========================================================================
// mma.sync bf16 GEMM with 3-way hi/lo split accumulation.
// C[M,N] = A[M,K] @ W[N,K]^T + bias[N], fp32 out, A optionally row-gathered.
// Block tile 128x128, BK=32, 256 threads (8 warps = 2m x 4n), double-buffered
// cp.async. smem tile pitch 80B (64B data + 16B pad) -> conflict-free ldmatrix.
// ===========================================================================
#define GPITCH 80                     // bytes per smem tile row
#define TILE_B (128*GPITCH)           // 10240 B per tile
#define BUF_B  (4*TILE_B)             // Ah,Al,Bh,Bl
#define GEMM_SMEM (2*BUF_B)           // double buffer = 81920 B

__device__ __forceinline__ void ldsm4(uint32_t* r, uint32_t addr) {
    asm volatile("ldmatrix.sync.aligned.m8n8.x4.shared.b16 {%0,%1,%2,%3}, [%4];"
                 : "=r"(r[0]), "=r"(r[1]), "=r"(r[2]), "=r"(r[3]) : "r"(addr));
}
__device__ __forceinline__ void mma16816(float* d, const uint32_t* a, uint32_t b0, uint32_t b1) {
    asm volatile(
        "mma.sync.aligned.m16n8k16.row.col.f32.bf16.bf16.f32 "
        "{%0,%1,%2,%3}, {%4,%5,%6,%7}, {%8,%9}, {%0,%1,%2,%3};"
        : "+f"(d[0]), "+f"(d[1]), "+f"(d[2]), "+f"(d[3])
        : "r"(a[0]), "r"(a[1]), "r"(a[2]), "r"(a[3]), "r"(b0), "r"(b1));
}
__device__ __forceinline__ void cpa16(uint32_t dst, const void* src) {
    asm volatile("cp.async.cg.shared.global [%0], [%1], 16;" :: "r"(dst), "l"(src));
}
__device__ __forceinline__ void cpa16z(uint32_t dst, const void* src, uint32_t sz) {
    asm volatile("cp.async.cg.shared.global [%0], [%1], 16, %2;" :: "r"(dst), "l"(src), "r"(sz));
}

template<bool GATHER>
__global__ __launch_bounds__(256, 1)
void mma_gemm(const __nv_bfloat16* __restrict__ Ah, const __nv_bfloat16* __restrict__ Al,
              const int* __restrict__ rows,
              const __nv_bfloat16* __restrict__ Bh, const __nv_bfloat16* __restrict__ Bl,
              const float* __restrict__ bias, float* __restrict__ C,
              int M, int N, int K)
{
    extern __shared__ char smem[];
    const int tid  = threadIdx.x;
    const int lane = tid & 31;
    const int wid  = tid >> 5;
    const int mw   = wid >> 2;        // 0..1
    const int nw   = wid & 3;         // 0..3
    const int m0   = blockIdx.y * 128;
    const int n0   = blockIdx.x * 128;

    const uint32_t sbase = (uint32_t)__cvta_generic_to_shared(smem);

    float acc[4][4][4];
    #pragma unroll
    for (int f = 0; f < 4; f++)
        #pragma unroll
        for (int g = 0; g < 4; g++)
            #pragma unroll
            for (int e = 0; e < 4; e++) acc[f][g][e] = 0.f;

    const int nchunks = K >> 5;

    // ---- loader: chunk starting at k=kt into buffer b ----
    auto load_chunk = [&](int kt, int b) {
        const uint32_t tb = sbase + (uint32_t)b * BUF_B;
        #pragma unroll
        for (int i = 0; i < 2; i++) {
            int l  = tid + i * 256;        // 0..511
            int r  = l & 127;
            int cb = l >> 7;               // 0..3
            uint32_t doff = (uint32_t)(r * GPITCH + cb * 16);
            // A rows (hi + lo share addressing)
            long ar = GATHER ? (long)rows[m0 + r] : (long)(m0 + r);
            const __nv_bfloat16* sa = Ah + ar * K + kt + cb * 8;
            const __nv_bfloat16* sl = Al + ar * K + kt + cb * 8;
            cpa16(tb + doff,              sa);
            cpa16(tb + TILE_B + doff,     sl);
            // B rows (zero-fill past N)
            int nr = n0 + r;
            uint32_t sz = (nr < N) ? 16u : 0u;
            long br = (nr < N) ? (long)nr : (long)(N - 1);
            const __nv_bfloat16* sbh = Bh + br * K + kt + cb * 8;
            const __nv_bfloat16* sbl = Bl + br * K + kt + cb * 8;
            cpa16z(tb + 2*TILE_B + doff,  sbh, sz);
            cpa16z(tb + 3*TILE_B + doff,  sbl, sz);
        }
        asm volatile("cp.async.commit_group;");
    };

    load_chunk(0, 0);

    #pragma unroll 1
    for (int c = 0; c < nchunks; c++) {
        if (c + 1 < nchunks) {
            load_chunk((c + 1) << 5, (c + 1) & 1);
            asm volatile("cp.async.wait_group 1;");
        } else {
            asm volatile("cp.async.wait_group 0;");
        }
        __syncthreads();

        const uint32_t tb = sbase + (uint32_t)(c & 1) * BUF_B;
        const uint32_t aoffs[3] = { tb, tb, tb + TILE_B };
        const uint32_t boffs[3] = { tb + 2*TILE_B, tb + 3*TILE_B, tb + 2*TILE_B };

        #pragma unroll
        for (int v = 0; v < 3; v++) {
            #pragma unroll
            for (int s = 0; s < 2; s++) {
                // A fragments: 4 m-frags of m16k16
                uint32_t a[4][4];
                uint32_t ab = aoffs[v]
                            + (uint32_t)((mw*64 + (lane & 15)) * GPITCH)
                            + (uint32_t)(s*32 + (lane >> 4)*16);
                #pragma unroll
                for (int f = 0; f < 4; f++)
                    ldsm4(a[f], ab + (uint32_t)(f * 16 * GPITCH));
                // B fragments + MMAs: 2 x4 loads cover 4 n-frags
                #pragma unroll
                for (int p = 0; p < 2; p++) {
                    uint32_t brow = (uint32_t)(nw*32 + p*16 + (lane & 7) + ((lane >> 4) & 1)*8);
                    uint32_t bb = boffs[v] + brow * GPITCH
                                + (uint32_t)(s*32 + ((lane >> 3) & 1)*16);
                    uint32_t b[4];
                    ldsm4(b, bb);
                    #pragma unroll
                    for (int f = 0; f < 4; f++) {
                        mma16816(acc[f][2*p    ], a[f], b[0], b[1]);
                        mma16816(acc[f][2*p + 1], a[f], b[2], b[3]);
                    }
                }
            }
        }
        __syncthreads();
    }

    // ---- epilogue: + bias, predicated float2 stores ----
    #pragma unroll
    for (int f = 0; f < 4; f++) {
        long row = m0 + mw*64 + f*16 + (lane >> 2);
        #pragma unroll
        for (int g = 0; g < 4; g++) {
            int col = n0 + nw*32 + g*8 + (lane & 3)*2;
            if (col < N) {
                float bx = bias[col], by = bias[col + 1];
                float2 v0 = make_float2(acc[f][g][0] + bx, acc[f][g][1] + by);
                float2 v1 = make_float2(acc[f][g][2] + bx, acc[f][g][3] + by);
                *reinterpret_cast<float2*>(C + row * N + col)       = v0;
                *reinterpret_cast<float2*>(C + (row + 8) * N + col) = v1;
            }
        }
    }
}

// ===========================================================================
// Persistent recurrence kernel (phases B, D) — unchanged from R3
// ===========================================================================
#define TK   128
#define HSP  65
#define RNB  128
#define RNT  128
#define SM_WS   0
#define SM_HS   (8*1024)
#define SM_RED  (SM_HS + 2*TK*HSP)
#define SM_BYTES  131072

__global__ __launch_bounds__(RNT, 1)
void rnn_layer(const float* __restrict__ h0init,
               const float* __restrict__ W,
               const float* __restrict__ X,
               float* __restrict__ H)
{
    extern __shared__ float sm[];
    float* Ws  = sm + SM_WS;
    float* hs  = sm + SM_HS;
    float* red = sm + SM_RED;

    const int tid  = threadIdx.x;
    const int lane = tid & 31;
    const int warp = tid >> 5;
    const int j0   = blockIdx.x * 8;

    for (int i = tid; i < 8*1024/4; i += RNT) {
        int j  = i >> 8;
        int kq = i & 255;
        float4 v = *reinterpret_cast<const float4*>(W + (long)(j0 + j) * HID + kq * 4);
        *reinterpret_cast<float4*>(Ws + j*1024 + kq*4) = v;
    }
    __syncthreads();

    const uint32_t hs_s = (uint32_t)__cvta_generic_to_shared(hs);

    for (int t = 0; t < SEQ; t++) {
        const float* hprev = (t == 0) ? h0init : (H + (long)(t-1) * STEP);

        float acc0[8], acc1[8];
        #pragma unroll
        for (int j = 0; j < 8; j++) { acc0[j] = 0.f; acc1[j] = 0.f; }

        {
            const float* src = hprev + tid;
            uint32_t dst = hs_s + (uint32_t)(tid * HSP) * 4u;
            #pragma unroll 16
            for (int b = 0; b < 64; b++)
                asm volatile("cp.async.ca.shared.global [%0], [%1], 4;"
                             :: "r"(dst + b*4u), "l"(src + (long)b*HID));
            asm volatile("cp.async.commit_group;");
        }

        int buf = 0;
        #pragma unroll 1
        for (int tile = 0; tile < 8; tile++) {
            if (tile < 7) {
                const float* src = hprev + (tile+1)*TK + tid;
                uint32_t dst = hs_s + (uint32_t)((((buf^1)*TK) + tid) * HSP) * 4u;
                #pragma unroll 16
                for (int b = 0; b < 64; b++)
                    asm volatile("cp.async.ca.shared.global [%0], [%1], 4;"
                                 :: "r"(dst + b*4u), "l"(src + (long)b*HID));
                asm volatile("cp.async.commit_group;");
                asm volatile("cp.async.wait_group 1;");
            } else {
                asm volatile("cp.async.wait_group 0;");
            }
            __syncthreads();

            const float* hb = hs + buf*TK*HSP;
            const int kwarp = warp * 32;
            #pragma unroll
            for (int q = 0; q < 8; q++) {
                const int kl = kwarp + q*4;
                float h0[4], h1[4];
                #pragma unroll
                for (int i = 0; i < 4; i++) {
                    h0[i] = hb[(kl+i)*HSP + lane];
                    h1[i] = hb[(kl+i)*HSP + lane + 32];
                }
                const int kg = tile*TK + kl;
                #pragma unroll
                for (int j = 0; j < 8; j++) {
                    float4 w = *reinterpret_cast<const float4*>(Ws + j*1024 + kg);
                    acc0[j] = fmaf(h0[0], w.x, acc0[j]);
                    acc0[j] = fmaf(h0[1], w.y, acc0[j]);
                    acc0[j] = fmaf(h0[2], w.z, acc0[j]);
                    acc0[j] = fmaf(h0[3], w.w, acc0[j]);
                    acc1[j] = fmaf(h1[0], w.x, acc1[j]);
                    acc1[j] = fmaf(h1[1], w.y, acc1[j]);
                    acc1[j] = fmaf(h1[2], w.z, acc1[j]);
                    acc1[j] = fmaf(h1[3], w.w, acc1[j]);
                }
            }
            __syncthreads();
            buf ^= 1;
        }

        #pragma unroll
        for (int j = 0; j < 8; j++) {
            red[((warp*2 + 0)*32 + lane)*9 + j] = acc0[j];
            red[((warp*2 + 1)*32 + lane)*9 + j] = acc1[j];
        }
        __syncthreads();

        const float* Xt = X + (long)t * STEP;
        float*       Ht = H + (long)t * STEP;
        #pragma unroll
        for (int i = 0; i < 4; i++) {
            int o   = tid + i*128;
            int g   = o >> 8;
            int rem = o & 255;
            int l   = rem >> 3;
            int j   = rem & 7;
            float s = red[((0*2+g)*32 + l)*9 + j]
                    + red[((1*2+g)*32 + l)*9 + j]
                    + red[((2*2+g)*32 + l)*9 + j]
                    + red[((3*2+g)*32 + l)*9 + j];
            int b   = g*32 + l;
            int col = j0 + j;
            Ht[(long)b*HID + col] = tanhf(s + Xt[(long)b*HID + col]);
        }

        __threadfence();
        __syncthreads();
        if (tid == 0) {
            atomicAdd(&g_cnt[t], 1u);
            while (*((volatile unsigned*)&g_cnt[t]) < (unsigned)RNB) {
                __nanosleep(40);
            }
            if (blockIdx.x == 0)
                atomicExch(&g_cnt[(t + 126) & 127], 0u);
        }
        __syncthreads();
        __threadfence();
    }
}

// ===========================================================================
// Split fp32 -> (bf16 hi, bf16 lo)
// ===========================================================================
__global__ void split_bf16(const float* __restrict__ src,
                           __nv_bfloat16* __restrict__ hi,
                           __nv_bfloat16* __restrict__ lo, int n)
{
    int i = blockIdx.x * blockDim.x + threadIdx.x;
    if (i < n) {
        float x = src[i];
        __nv_bfloat16 h = __float2bfloat16_rn(x);
        float r = x - __bfloat162float(h);
        hi[i] = h;
        lo[i] = __float2bfloat16_rn(r);
    }
}

// ---------------------------------------------------------------------------
__global__ void copy_tail(float* __restrict__ dst)
{
    int i = blockIdx.x * blockDim.x + threadIdx.x;
    if (i < STEP)          dst[i] = g_H0[(long)(SEQ - 1) * STEP + i];
    else if (i < 2 * STEP) dst[i] = g_H1[(long)(SEQ - 1) * STEP + (i - STEP)];
}

// ---------------------------------------------------------------------------
extern "C" void kernel_launch(void* const* d_in, const int* in_sizes, int n_in,
                              void* d_out, int out_size)
{
    const int*   tok    = (const int*)  d_in[0];
    const float* hidden = (const float*)d_in[1];
    const float* emb    = (const float*)d_in[2];
    const float* W0x    = (const float*)d_in[3];
    const float* W0h    = (const float*)d_in[4];
    const float* b0     = (const float*)d_in[5];
    const float* W1x    = (const float*)d_in[6];
    const float* W1h    = (const float*)d_in[7];
    const float* b1     = (const float*)d_in[8];
    const float* Wout   = (const float*)d_in[9];
    const float* bout   = (const float*)d_in[10];
    float* out = (float*)d_out;

    float *X0, *H0, *X1, *H1;
    __nv_bfloat16 *EmbH, *EmbL, *W0xH, *W0xL, *W1xH, *W1xL, *WoH, *WoL, *AH, *AL;
    cudaGetSymbolAddress((void**)&X0, g_X0);
    cudaGetSymbolAddress((void**)&H0, g_H0);
    cudaGetSymbolAddress((void**)&X1, g_X1);
    cudaGetSymbolAddress((void**)&H1, g_H1);
    cudaGetSymbolAddress((void**)&EmbH, g_EmbH);
    cudaGetSymbolAddress((void**)&EmbL, g_EmbL);
    cudaGetSymbolAddress((void**)&W0xH, g_W0xH);
    cudaGetSymbolAddress((void**)&W0xL, g_W0xL);
    cudaGetSymbolAddress((void**)&W1xH, g_W1xH);
    cudaGetSymbolAddress((void**)&W1xL, g_W1xL);
    cudaGetSymbolAddress((void**)&WoH, g_WoH);
    cudaGetSymbolAddress((void**)&WoL, g_WoL);
    cudaGetSymbolAddress((void**)&AH, g_AH);
    cudaGetSymbolAddress((void**)&AL, g_AL);

    static bool attr_set = false;
    if (!attr_set) {
        cudaFuncSetAttribute(rnn_layer,
                             cudaFuncAttributeMaxDynamicSharedMemorySize, SM_BYTES);
        cudaFuncSetAttribute(mma_gemm<true>,
                             cudaFuncAttributeMaxDynamicSharedMemorySize, GEMM_SMEM);
        cudaFuncSetAttribute(mma_gemm<false>,
                             cudaFuncAttributeMaxDynamicSharedMemorySize, GEMM_SMEM);
        attr_set = true;
    }

    // Upfront splits (weights + embedding)
    split_bf16<<<(VOCAB*HID + 255)/256, 256>>>(Wout, WoH, WoL, VOCAB*HID);
    split_bf16<<<(VOCAB*EMB + 255)/256, 256>>>(emb, EmbH, EmbL, VOCAB*EMB);
    split_bf16<<<(HID*EMB + 255)/256, 256>>>(W0x, W0xH, W0xL, HID*EMB);
    split_bf16<<<(HID*HID + 255)/256, 256>>>(W1x, W1xH, W1xL, HID*HID);

    // Phase A: X0 = emb[tok] @ W0x^T + b0   (gathered A, K=512)
    mma_gemm<true><<<dim3(HID/128, MB/128), 256, GEMM_SMEM>>>(
        EmbH, EmbL, tok, W0xH, W0xL, b0, X0, MB, HID, EMB);

    // Phase B: layer-0 recurrence
    rnn_layer<<<RNB, RNT, SM_BYTES>>>(hidden, W0h, X0, H0);

    // Phase C: X1 = H0 @ W1x^T + b1
    split_bf16<<<(MB*HID + 255)/256, 256>>>(H0, AH, AL, MB*HID);
    mma_gemm<false><<<dim3(HID/128, MB/128), 256, GEMM_SMEM>>>(
        AH, AL, nullptr, W1xH, W1xL, b1, X1, MB, HID, HID);

    // Phase D: layer-1 recurrence
    rnn_layer<<<RNB, RNT, SM_BYTES>>>(hidden + STEP, W1h, X1, H1);

    // Phase E: logits = H1 @ Wout^T + bout
    split_bf16<<<(MB*HID + 255)/256, 256>>>(H1, AH, AL, MB*HID);
    mma_gemm<false><<<dim3((VOCAB + 127)/128, MB/128), 256, GEMM_SMEM>>>(
        AH, AL, nullptr, WoH, WoL, bout, out, MB, VOCAB, HID);

    // Tail
    copy_tail<<<(2*STEP + 255)/256, 256>>>(out + (long)SEQ * BATCH * VOCAB);
}

// round 6
// speedup vs baseline: 2.1320x; 1.0523x over previous
#include <cuda_runtime.h>
#include <cuda_bf16.h>
#include <cstdint>

// Problem constants
#define SEQ    128
#define BATCH  64
#define EMB    512
#define HID    1024
#define VOCAB  10000
#define MB     (SEQ*BATCH)        // 8192 rows when time-batched
#define STEP   (BATCH*HID)        // 65536 floats per timestep slab

// Scratch (device globals: no allocation allowed in kernel_launch)
__device__ float g_X0[MB*HID];
__device__ float g_H0[MB*HID];
__device__ float g_X1[MB*HID];
__device__ float g_H1[MB*HID];
__device__ unsigned g_cnt[128];
// bf16 split operands (hi/lo) for tensor-core GEMMs
__device__ __nv_bfloat16 g_EmbH[VOCAB*EMB], g_EmbL[VOCAB*EMB];
__device__ __nv_bfloat16 g_W0xH[HID*EMB],   g_W0xL[HID*EMB];
__device__ __nv_bfloat16 g_W1xH[HID*HID],   g_W1xL[HID*HID];
__device__ __nv_bfloat16 g_WoH[VOCAB*HID],  g_WoL[VOCAB*HID];
__device__ __nv_bfloat16 g_A0H[MB*HID],     g_A0L[MB*HID];   // H0 splits
__device__ __nv_bfloat16 g_A1H[MB*HID],     g_A1L[MB*HID];   // H1 splits

// ===========================================================================
// mma.sync bf16 GEMM with 3-way hi/lo split accumulation.
// C[M,N] = A[M,K] @ W[N,K]^T + bias[N], fp32 out, A optionally row-gathered.
// Block tile 128x128, BK=32, 256 threads (8 warps = 2m x 4n), double-buffered
// cp.async. smem pitch 80B -> conflict-free ldmatrix. 2 CTAs/SM.
// ===========================================================================
#define GPITCH 80                     // bytes per smem tile row
#define TILE_B (128*GPITCH)           // 10240 B per tile
#define BUF_B  (4*TILE_B)             // Ah,Al,Bh,Bl
#define GEMM_SMEM (2*BUF_B)           // double buffer = 81920 B

__device__ __forceinline__ void ldsm4(uint32_t* r, uint32_t addr) {
    asm volatile("ldmatrix.sync.aligned.m8n8.x4.shared.b16 {%0,%1,%2,%3}, [%4];"
                 : "=r"(r[0]), "=r"(r[1]), "=r"(r[2]), "=r"(r[3]) : "r"(addr));
}
__device__ __forceinline__ void mma16816(float* d, const uint32_t* a, uint32_t b0, uint32_t b1) {
    asm volatile(
        "mma.sync.aligned.m16n8k16.row.col.f32.bf16.bf16.f32 "
        "{%0,%1,%2,%3}, {%4,%5,%6,%7}, {%8,%9}, {%0,%1,%2,%3};"
        : "+f"(d[0]), "+f"(d[1]), "+f"(d[2]), "+f"(d[3])
        : "r"(a[0]), "r"(a[1]), "r"(a[2]), "r"(a[3]), "r"(b0), "r"(b1));
}
__device__ __forceinline__ void cpa16(uint32_t dst, const void* src) {
    asm volatile("cp.async.cg.shared.global [%0], [%1], 16;" :: "r"(dst), "l"(src));
}
__device__ __forceinline__ void cpa16z(uint32_t dst, const void* src, uint32_t sz) {
    asm volatile("cp.async.cg.shared.global [%0], [%1], 16, %2;" :: "r"(dst), "l"(src), "r"(sz));
}

template<bool GATHER>
__global__ __launch_bounds__(256, 2)
void mma_gemm(const __nv_bfloat16* __restrict__ Ah, const __nv_bfloat16* __restrict__ Al,
              const int* __restrict__ rows,
              const __nv_bfloat16* __restrict__ Bh, const __nv_bfloat16* __restrict__ Bl,
              const float* __restrict__ bias, float* __restrict__ C,
              int M, int N, int K)
{
    extern __shared__ char smem[];
    const int tid  = threadIdx.x;
    const int lane = tid & 31;
    const int wid  = tid >> 5;
    const int mw   = wid >> 2;        // 0..1
    const int nw   = wid & 3;         // 0..3
    const int m0   = blockIdx.y * 128;
    const int n0   = blockIdx.x * 128;

    const uint32_t sbase = (uint32_t)__cvta_generic_to_shared(smem);

    float acc[4][4][4];
    #pragma unroll
    for (int f = 0; f < 4; f++)
        #pragma unroll
        for (int g = 0; g < 4; g++)
            #pragma unroll
            for (int e = 0; e < 4; e++) acc[f][g][e] = 0.f;

    const int nchunks = K >> 5;

    auto load_chunk = [&](int kt, int b) {
        const uint32_t tb = sbase + (uint32_t)b * BUF_B;
        #pragma unroll
        for (int i = 0; i < 2; i++) {
            int l  = tid + i * 256;        // 0..511
            int r  = l & 127;
            int cb = l >> 7;               // 0..3
            uint32_t doff = (uint32_t)(r * GPITCH + cb * 16);
            long ar = GATHER ? (long)rows[m0 + r] : (long)(m0 + r);
            const __nv_bfloat16* sa = Ah + ar * K + kt + cb * 8;
            const __nv_bfloat16* sl = Al + ar * K + kt + cb * 8;
            cpa16(tb + doff,              sa);
            cpa16(tb + TILE_B + doff,     sl);
            int nr = n0 + r;
            uint32_t sz = (nr < N) ? 16u : 0u;
            long br = (nr < N) ? (long)nr : (long)(N - 1);
            const __nv_bfloat16* sbh = Bh + br * K + kt + cb * 8;
            const __nv_bfloat16* sbl = Bl + br * K + kt + cb * 8;
            cpa16z(tb + 2*TILE_B + doff,  sbh, sz);
            cpa16z(tb + 3*TILE_B + doff,  sbl, sz);
        }
        asm volatile("cp.async.commit_group;");
    };

    load_chunk(0, 0);

    #pragma unroll 1
    for (int c = 0; c < nchunks; c++) {
        if (c + 1 < nchunks) {
            load_chunk((c + 1) << 5, (c + 1) & 1);
            asm volatile("cp.async.wait_group 1;");
        } else {
            asm volatile("cp.async.wait_group 0;");
        }
        __syncthreads();

        const uint32_t tb = sbase + (uint32_t)(c & 1) * BUF_B;
        const uint32_t aoffs[3] = { tb, tb, tb + TILE_B };
        const uint32_t boffs[3] = { tb + 2*TILE_B, tb + 3*TILE_B, tb + 2*TILE_B };

        #pragma unroll
        for (int v = 0; v < 3; v++) {
            #pragma unroll
            for (int s = 0; s < 2; s++) {
                uint32_t a[4][4];
                uint32_t ab = aoffs[v]
                            + (uint32_t)((mw*64 + (lane & 15)) * GPITCH)
                            + (uint32_t)(s*32 + (lane >> 4)*16);
                #pragma unroll
                for (int f = 0; f < 4; f++)
                    ldsm4(a[f], ab + (uint32_t)(f * 16 * GPITCH));
                #pragma unroll
                for (int p = 0; p < 2; p++) {
                    uint32_t brow = (uint32_t)(nw*32 + p*16 + (lane & 7) + ((lane >> 4) & 1)*8);
                    uint32_t bb = boffs[v] + brow * GPITCH
                                + (uint32_t)(s*32 + ((lane >> 3) & 1)*16);
                    uint32_t b[4];
                    ldsm4(b, bb);
                    #pragma unroll
                    for (int f = 0; f < 4; f++) {
                        mma16816(acc[f][2*p    ], a[f], b[0], b[1]);
                        mma16816(acc[f][2*p + 1], a[f], b[2], b[3]);
                    }
                }
            }
        }
        __syncthreads();
    }

    // ---- epilogue: + bias, predicated float2 stores ----
    #pragma unroll
    for (int f = 0; f < 4; f++) {
        long row = m0 + mw*64 + f*16 + (lane >> 2);
        #pragma unroll
        for (int g = 0; g < 4; g++) {
            int col = n0 + nw*32 + g*8 + (lane & 3)*2;
            if (col < N) {
                float bx = bias[col], by = bias[col + 1];
                float2 v0 = make_float2(acc[f][g][0] + bx, acc[f][g][1] + by);
                float2 v1 = make_float2(acc[f][g][2] + bx, acc[f][g][3] + by);
                *reinterpret_cast<float2*>(C + row * N + col)       = v0;
                *reinterpret_cast<float2*>(C + (row + 8) * N + col) = v1;
            }
        }
    }
}

// ===========================================================================
// Persistent recurrence kernel (phases B, D).
// R6: epilogue additionally emits bf16 hi/lo splits of H[t] (feeds the next
// tensor-core GEMM directly; removes standalone split kernels).
// ===========================================================================
#define TK   128
#define HSP  65
#define RNB  128
#define RNT  128
#define SM_WS   0
#define SM_HS   (8*1024)
#define SM_RED  (SM_HS + 2*TK*HSP)
#define SM_BYTES  131072

__global__ __launch_bounds__(RNT, 1)
void rnn_layer(const float* __restrict__ h0init,
               const float* __restrict__ W,
               const float* __restrict__ X,
               float* __restrict__ H,
               __nv_bfloat16* __restrict__ Hh,
               __nv_bfloat16* __restrict__ Hl)
{
    extern __shared__ float sm[];
    float* Ws  = sm + SM_WS;
    float* hs  = sm + SM_HS;
    float* red = sm + SM_RED;

    const int tid  = threadIdx.x;
    const int lane = tid & 31;
    const int warp = tid >> 5;
    const int j0   = blockIdx.x * 8;

    for (int i = tid; i < 8*1024/4; i += RNT) {
        int j  = i >> 8;
        int kq = i & 255;
        float4 v = *reinterpret_cast<const float4*>(W + (long)(j0 + j) * HID + kq * 4);
        *reinterpret_cast<float4*>(Ws + j*1024 + kq*4) = v;
    }
    __syncthreads();

    const uint32_t hs_s = (uint32_t)__cvta_generic_to_shared(hs);

    for (int t = 0; t < SEQ; t++) {
        const float* hprev = (t == 0) ? h0init : (H + (long)(t-1) * STEP);

        float acc0[8], acc1[8];
        #pragma unroll
        for (int j = 0; j < 8; j++) { acc0[j] = 0.f; acc1[j] = 0.f; }

        {
            const float* src = hprev + tid;
            uint32_t dst = hs_s + (uint32_t)(tid * HSP) * 4u;
            #pragma unroll 16
            for (int b = 0; b < 64; b++)
                asm volatile("cp.async.ca.shared.global [%0], [%1], 4;"
                             :: "r"(dst + b*4u), "l"(src + (long)b*HID));
            asm volatile("cp.async.commit_group;");
        }

        int buf = 0;
        #pragma unroll 1
        for (int tile = 0; tile < 8; tile++) {
            if (tile < 7) {
                const float* src = hprev + (tile+1)*TK + tid;
                uint32_t dst = hs_s + (uint32_t)((((buf^1)*TK) + tid) * HSP) * 4u;
                #pragma unroll 16
                for (int b = 0; b < 64; b++)
                    asm volatile("cp.async.ca.shared.global [%0], [%1], 4;"
                                 :: "r"(dst + b*4u), "l"(src + (long)b*HID));
                asm volatile("cp.async.commit_group;");
                asm volatile("cp.async.wait_group 1;");
            } else {
                asm volatile("cp.async.wait_group 0;");
            }
            __syncthreads();

            const float* hb = hs + buf*TK*HSP;
            const int kwarp = warp * 32;
            #pragma unroll
            for (int q = 0; q < 8; q++) {
                const int kl = kwarp + q*4;
                float h0[4], h1[4];
                #pragma unroll
                for (int i = 0; i < 4; i++) {
                    h0[i] = hb[(kl+i)*HSP + lane];
                    h1[i] = hb[(kl+i)*HSP + lane + 32];
                }
                const int kg = tile*TK + kl;
                #pragma unroll
                for (int j = 0; j < 8; j++) {
                    float4 w = *reinterpret_cast<const float4*>(Ws + j*1024 + kg);
                    acc0[j] = fmaf(h0[0], w.x, acc0[j]);
                    acc0[j] = fmaf(h0[1], w.y, acc0[j]);
                    acc0[j] = fmaf(h0[2], w.z, acc0[j]);
                    acc0[j] = fmaf(h0[3], w.w, acc0[j]);
                    acc1[j] = fmaf(h1[0], w.x, acc1[j]);
                    acc1[j] = fmaf(h1[1], w.y, acc1[j]);
                    acc1[j] = fmaf(h1[2], w.z, acc1[j]);
                    acc1[j] = fmaf(h1[3], w.w, acc1[j]);
                }
            }
            __syncthreads();
            buf ^= 1;
        }

        #pragma unroll
        for (int j = 0; j < 8; j++) {
            red[((warp*2 + 0)*32 + lane)*9 + j] = acc0[j];
            red[((warp*2 + 1)*32 + lane)*9 + j] = acc1[j];
        }
        __syncthreads();

        const float* Xt = X + (long)t * STEP;
        float*       Ht = H + (long)t * STEP;
        __nv_bfloat16* HhT = Hh + (long)t * STEP;
        __nv_bfloat16* HlT = Hl + (long)t * STEP;
        #pragma unroll
        for (int i = 0; i < 4; i++) {
            int o   = tid + i*128;
            int g   = o >> 8;
            int rem = o & 255;
            int l   = rem >> 3;
            int j   = rem & 7;
            float s = red[((0*2+g)*32 + l)*9 + j]
                    + red[((1*2+g)*32 + l)*9 + j]
                    + red[((2*2+g)*32 + l)*9 + j]
                    + red[((3*2+g)*32 + l)*9 + j];
            int b   = g*32 + l;
            int col = j0 + j;
            long idx = (long)b*HID + col;
            float hv = tanhf(s + Xt[idx]);
            Ht[idx] = hv;
            __nv_bfloat16 hi = __float2bfloat16_rn(hv);
            HhT[idx] = hi;
            HlT[idx] = __float2bfloat16_rn(hv - __bfloat162float(hi));
        }

        __threadfence();
        __syncthreads();
        if (tid == 0) {
            atomicAdd(&g_cnt[t], 1u);
            while (*((volatile unsigned*)&g_cnt[t]) < (unsigned)RNB) {
                __nanosleep(40);
            }
            if (blockIdx.x == 0)
                atomicExch(&g_cnt[(t + 126) & 127], 0u);
        }
        __syncthreads();
        __threadfence();
    }
}

// ===========================================================================
// Split fp32 -> (bf16 hi, bf16 lo)  (weights/embedding only now)
// ===========================================================================
__global__ void split_bf16(const float* __restrict__ src,
                           __nv_bfloat16* __restrict__ hi,
                           __nv_bfloat16* __restrict__ lo, int n)
{
    int i = blockIdx.x * blockDim.x + threadIdx.x;
    if (i < n) {
        float x = src[i];
        __nv_bfloat16 h = __float2bfloat16_rn(x);
        float r = x - __bfloat162float(h);
        hi[i] = h;
        lo[i] = __float2bfloat16_rn(r);
    }
}

// ---------------------------------------------------------------------------
__global__ void copy_tail(float* __restrict__ dst)
{
    int i = blockIdx.x * blockDim.x + threadIdx.x;
    if (i < STEP)          dst[i] = g_H0[(long)(SEQ - 1) * STEP + i];
    else if (i < 2 * STEP) dst[i] = g_H1[(long)(SEQ - 1) * STEP + (i - STEP)];
}

// ---------------------------------------------------------------------------
extern "C" void kernel_launch(void* const* d_in, const int* in_sizes, int n_in,
                              void* d_out, int out_size)
{
    const int*   tok    = (const int*)  d_in[0];
    const float* hidden = (const float*)d_in[1];
    const float* emb    = (const float*)d_in[2];
    const float* W0x    = (const float*)d_in[3];
    const float* W0h    = (const float*)d_in[4];
    const float* b0     = (const float*)d_in[5];
    const float* W1x    = (const float*)d_in[6];
    const float* W1h    = (const float*)d_in[7];
    const float* b1     = (const float*)d_in[8];
    const float* Wout   = (const float*)d_in[9];
    const float* bout   = (const float*)d_in[10];
    float* out = (float*)d_out;

    float *X0, *H0, *X1, *H1;
    __nv_bfloat16 *EmbH, *EmbL, *W0xH, *W0xL, *W1xH, *W1xL, *WoH, *WoL;
    __nv_bfloat16 *A0H, *A0L, *A1H, *A1L;
    cudaGetSymbolAddress((void**)&X0, g_X0);
    cudaGetSymbolAddress((void**)&H0, g_H0);
    cudaGetSymbolAddress((void**)&X1, g_X1);
    cudaGetSymbolAddress((void**)&H1, g_H1);
    cudaGetSymbolAddress((void**)&EmbH, g_EmbH);
    cudaGetSymbolAddress((void**)&EmbL, g_EmbL);
    cudaGetSymbolAddress((void**)&W0xH, g_W0xH);
    cudaGetSymbolAddress((void**)&W0xL, g_W0xL);
    cudaGetSymbolAddress((void**)&W1xH, g_W1xH);
    cudaGetSymbolAddress((void**)&W1xL, g_W1xL);
    cudaGetSymbolAddress((void**)&WoH, g_WoH);
    cudaGetSymbolAddress((void**)&WoL, g_WoL);
    cudaGetSymbolAddress((void**)&A0H, g_A0H);
    cudaGetSymbolAddress((void**)&A0L, g_A0L);
    cudaGetSymbolAddress((void**)&A1H, g_A1H);
    cudaGetSymbolAddress((void**)&A1L, g_A1L);

    static bool attr_set = false;
    if (!attr_set) {
        cudaFuncSetAttribute(rnn_layer,
                             cudaFuncAttributeMaxDynamicSharedMemorySize, SM_BYTES);
        cudaFuncSetAttribute(mma_gemm<true>,
                             cudaFuncAttributeMaxDynamicSharedMemorySize, GEMM_SMEM);
        cudaFuncSetAttribute(mma_gemm<false>,
                             cudaFuncAttributeMaxDynamicSharedMemorySize, GEMM_SMEM);
        attr_set = true;
    }

    // Upfront splits (weights + embedding)
    split_bf16<<<(VOCAB*HID + 255)/256, 256>>>(Wout, WoH, WoL, VOCAB*HID);
    split_bf16<<<(VOCAB*EMB + 255)/256, 256>>>(emb, EmbH, EmbL, VOCAB*EMB);
    split_bf16<<<(HID*EMB + 255)/256, 256>>>(W0x, W0xH, W0xL, HID*EMB);
    split_bf16<<<(HID*HID + 255)/256, 256>>>(W1x, W1xH, W1xL, HID*HID);

    // Phase A: X0 = emb[tok] @ W0x^T + b0   (gathered A, K=512)
    mma_gemm<true><<<dim3(HID/128, MB/128), 256, GEMM_SMEM>>>(
        EmbH, EmbL, tok, W0xH, W0xL, b0, X0, MB, HID, EMB);

    // Phase B: layer-0 recurrence (emits H0 + bf16 splits)
    rnn_layer<<<RNB, RNT, SM_BYTES>>>(hidden, W0h, X0, H0, A0H, A0L);

    // Phase C: X1 = H0 @ W1x^T + b1
    mma_gemm<false><<<dim3(HID/128, MB/128), 256, GEMM_SMEM>>>(
        A0H, A0L, nullptr, W1xH, W1xL, b1, X1, MB, HID, HID);

    // Phase D: layer-1 recurrence (emits H1 + bf16 splits)
    rnn_layer<<<RNB, RNT, SM_BYTES>>>(hidden + STEP, W1h, X1, H1, A1H, A1L);

    // Phase E: logits = H1 @ Wout^T + bout
    mma_gemm<false><<<dim3((VOCAB + 127)/128, MB/128), 256, GEMM_SMEM>>>(
        A1H, A1L, nullptr, WoH, WoL, bout, out, MB, VOCAB, HID);

    // Tail
    copy_tail<<<(2*STEP + 255)/256, 256>>>(out + (long)SEQ * BATCH * VOCAB);
}

// round 7
// speedup vs baseline: 2.1475x; 1.0073x over previous
#include <cuda_runtime.h>
#include <cuda_bf16.h>
#include <cstdint>

// Problem constants
#define SEQ    128
#define BATCH  64
#define EMB    512
#define HID    1024
#define VOCAB  10000
#define MB     (SEQ*BATCH)        // 8192 rows when time-batched
#define STEP   (BATCH*HID)        // 65536 floats per timestep slab

// Scratch (device globals: no allocation allowed in kernel_launch)
__device__ float g_X0[MB*HID];
__device__ float g_H0[MB*HID];
__device__ float g_X1[MB*HID];
__device__ float g_H1[MB*HID];
__device__ unsigned g_cnt[128];
// bf16 split operands (hi/lo) for tensor-core GEMMs
__device__ __nv_bfloat16 g_EmbH[VOCAB*EMB], g_EmbL[VOCAB*EMB];
__device__ __nv_bfloat16 g_W0xH[HID*EMB],   g_W0xL[HID*EMB];
__device__ __nv_bfloat16 g_W1xH[HID*HID],   g_W1xL[HID*HID];
__device__ __nv_bfloat16 g_WoH[VOCAB*HID],  g_WoL[VOCAB*HID];
__device__ __nv_bfloat16 g_A0H[MB*HID],     g_A0L[MB*HID];   // H0 splits
__device__ __nv_bfloat16 g_A1H[MB*HID],     g_A1L[MB*HID];   // H1 splits

// ===========================================================================
// mma.sync bf16 GEMM, 3-way hi/lo split, fragment-sharing inner loop.
// C[M,N] = A[M,K] @ W[N,K]^T + bias[N]; block tile 128x128, BK=32, 8 warps.
// Per k16 step: pass1 loads Ah once -> MMA vs Bh and Bl; pass2 loads Al ->
// MMA vs Bh. 14 ldsm.x4 per step (was 18+18), same 48 MMAs.
// ===========================================================================
#define GPITCH 80                     // bytes per smem tile row
#define TILE_B (128*GPITCH)           // 10240 B per tile
#define BUF_B  (4*TILE_B)             // Ah,Al,Bh,Bl
#define GEMM_SMEM (2*BUF_B)           // double buffer = 81920 B

__device__ __forceinline__ void ldsm4(uint32_t* r, uint32_t addr) {
    asm volatile("ldmatrix.sync.aligned.m8n8.x4.shared.b16 {%0,%1,%2,%3}, [%4];"
                 : "=r"(r[0]), "=r"(r[1]), "=r"(r[2]), "=r"(r[3]) : "r"(addr));
}
__device__ __forceinline__ void mma16816(float* d, const uint32_t* a, uint32_t b0, uint32_t b1) {
    asm volatile(
        "mma.sync.aligned.m16n8k16.row.col.f32.bf16.bf16.f32 "
        "{%0,%1,%2,%3}, {%4,%5,%6,%7}, {%8,%9}, {%0,%1,%2,%3};"
        : "+f"(d[0]), "+f"(d[1]), "+f"(d[2]), "+f"(d[3])
        : "r"(a[0]), "r"(a[1]), "r"(a[2]), "r"(a[3]), "r"(b0), "r"(b1));
}
__device__ __forceinline__ void cpa16(uint32_t dst, const void* src) {
    asm volatile("cp.async.cg.shared.global [%0], [%1], 16;" :: "r"(dst), "l"(src));
}
__device__ __forceinline__ void cpa16z(uint32_t dst, const void* src, uint32_t sz) {
    asm volatile("cp.async.cg.shared.global [%0], [%1], 16, %2;" :: "r"(dst), "l"(src), "r"(sz));
}

template<bool GATHER>
__global__ __launch_bounds__(256, 2)
void mma_gemm(const __nv_bfloat16* __restrict__ Ah, const __nv_bfloat16* __restrict__ Al,
              const int* __restrict__ rows,
              const __nv_bfloat16* __restrict__ Bh, const __nv_bfloat16* __restrict__ Bl,
              const float* __restrict__ bias, float* __restrict__ C,
              int M, int N, int K)
{
    extern __shared__ char smem[];
    const int tid  = threadIdx.x;
    const int lane = tid & 31;
    const int wid  = tid >> 5;
    const int mw   = wid >> 2;        // 0..1
    const int nw   = wid & 3;         // 0..3
    const int m0   = blockIdx.y * 128;
    const int n0   = blockIdx.x * 128;

    const uint32_t sbase = (uint32_t)__cvta_generic_to_shared(smem);

    float acc[4][4][4];
    #pragma unroll
    for (int f = 0; f < 4; f++)
        #pragma unroll
        for (int g = 0; g < 4; g++)
            #pragma unroll
            for (int e = 0; e < 4; e++) acc[f][g][e] = 0.f;

    const int nchunks = K >> 5;

    auto load_chunk = [&](int kt, int b) {
        const uint32_t tb = sbase + (uint32_t)b * BUF_B;
        #pragma unroll
        for (int i = 0; i < 2; i++) {
            int l  = tid + i * 256;        // 0..511
            int r  = l & 127;
            int cb = l >> 7;               // 0..3
            uint32_t doff = (uint32_t)(r * GPITCH + cb * 16);
            long ar = GATHER ? (long)rows[m0 + r] : (long)(m0 + r);
            const __nv_bfloat16* sa = Ah + ar * K + kt + cb * 8;
            const __nv_bfloat16* sl = Al + ar * K + kt + cb * 8;
            cpa16(tb + doff,              sa);
            cpa16(tb + TILE_B + doff,     sl);
            int nr = n0 + r;
            uint32_t sz = (nr < N) ? 16u : 0u;
            long br = (nr < N) ? (long)nr : (long)(N - 1);
            const __nv_bfloat16* sbh = Bh + br * K + kt + cb * 8;
            const __nv_bfloat16* sbl = Bl + br * K + kt + cb * 8;
            cpa16z(tb + 2*TILE_B + doff,  sbh, sz);
            cpa16z(tb + 3*TILE_B + doff,  sbl, sz);
        }
        asm volatile("cp.async.commit_group;");
    };

    load_chunk(0, 0);

    #pragma unroll 1
    for (int c = 0; c < nchunks; c++) {
        if (c + 1 < nchunks) {
            load_chunk((c + 1) << 5, (c + 1) & 1);
            asm volatile("cp.async.wait_group 1;");
        } else {
            asm volatile("cp.async.wait_group 0;");
        }
        __syncthreads();

        const uint32_t tb = sbase + (uint32_t)(c & 1) * BUF_B;

        #pragma unroll
        for (int s = 0; s < 2; s++) {
            const uint32_t abase = tb
                + (uint32_t)((mw*64 + (lane & 15)) * GPITCH)
                + (uint32_t)(s*32 + (lane >> 4)*16);
            uint32_t bb[2];
            #pragma unroll
            for (int p = 0; p < 2; p++) {
                uint32_t brow = (uint32_t)(nw*32 + p*16 + (lane & 7) + ((lane >> 4) & 1)*8);
                bb[p] = tb + 2*TILE_B + brow * GPITCH
                      + (uint32_t)(s*32 + ((lane >> 3) & 1)*16);
            }

            uint32_t aF[4][4];
            // ---- pass 1: Ah vs (Bh, Bl) ----
            #pragma unroll
            for (int f = 0; f < 4; f++)
                ldsm4(aF[f], abase + (uint32_t)(f * 16 * GPITCH));
            #pragma unroll
            for (int p = 0; p < 2; p++) {
                uint32_t bh[4], bl[4];
                ldsm4(bh, bb[p]);
                ldsm4(bl, bb[p] + TILE_B);
                #pragma unroll
                for (int f = 0; f < 4; f++) {
                    mma16816(acc[f][2*p    ], aF[f], bh[0], bh[1]);
                    mma16816(acc[f][2*p + 1], aF[f], bh[2], bh[3]);
                    mma16816(acc[f][2*p    ], aF[f], bl[0], bl[1]);
                    mma16816(acc[f][2*p + 1], aF[f], bl[2], bl[3]);
                }
            }
            // ---- pass 2: Al vs Bh ----
            #pragma unroll
            for (int f = 0; f < 4; f++)
                ldsm4(aF[f], abase + TILE_B + (uint32_t)(f * 16 * GPITCH));
            #pragma unroll
            for (int p = 0; p < 2; p++) {
                uint32_t bh[4];
                ldsm4(bh, bb[p]);
                #pragma unroll
                for (int f = 0; f < 4; f++) {
                    mma16816(acc[f][2*p    ], aF[f], bh[0], bh[1]);
                    mma16816(acc[f][2*p + 1], aF[f], bh[2], bh[3]);
                }
            }
        }
        __syncthreads();
    }

    // ---- epilogue: + bias, predicated float2 stores ----
    #pragma unroll
    for (int f = 0; f < 4; f++) {
        long row = m0 + mw*64 + f*16 + (lane >> 2);
        #pragma unroll
        for (int g = 0; g < 4; g++) {
            int col = n0 + nw*32 + g*8 + (lane & 3)*2;
            if (col < N) {
                float bx = bias[col], by = bias[col + 1];
                float2 v0 = make_float2(acc[f][g][0] + bx, acc[f][g][1] + by);
                float2 v1 = make_float2(acc[f][g][2] + bx, acc[f][g][3] + by);
                *reinterpret_cast<float2*>(C + row * N + col)       = v0;
                *reinterpret_cast<float2*>(C + (row + 8) * N + col) = v1;
            }
        }
    }
}

// ===========================================================================
// Persistent recurrence kernel (phases B, D).
// R7: 256 threads (8 warps, 2/SMSP) — warp w owns tile-local k [16w,16w+16).
// Epilogue emits H[t] fp32 + bf16 hi/lo splits.
// ===========================================================================
#define TK   128
#define HSP  65
#define RNB  128
#define RNT  256
#define SM_WS   0
#define SM_HS   (8*1024)
#define SM_RED  (SM_HS + 2*TK*HSP)        // red: [8][2][32][9] floats
#define SM_BYTES  131072                   // 1 block per SM

__global__ __launch_bounds__(RNT, 1)
void rnn_layer(const float* __restrict__ h0init,
               const float* __restrict__ W,
               const float* __restrict__ X,
               float* __restrict__ H,
               __nv_bfloat16* __restrict__ Hh,
               __nv_bfloat16* __restrict__ Hl)
{
    extern __shared__ float sm[];
    float* Ws  = sm + SM_WS;
    float* hs  = sm + SM_HS;
    float* red = sm + SM_RED;

    const int tid  = threadIdx.x;
    const int lane = tid & 31;
    const int warp = tid >> 5;         // 0..7
    const int j0   = blockIdx.x * 8;

    for (int i = tid; i < 8*1024/4; i += RNT) {
        int j  = i >> 8;
        int kq = i & 255;
        float4 v = *reinterpret_cast<const float4*>(W + (long)(j0 + j) * HID + kq * 4);
        *reinterpret_cast<float4*>(Ws + j*1024 + kq*4) = v;
    }
    __syncthreads();

    const uint32_t hs_s = (uint32_t)__cvta_generic_to_shared(hs);
    const int lc   = tid >> 1;          // k-column owned by this thread pair
    const int lh   = (tid & 1) * 32;    // row half

    for (int t = 0; t < SEQ; t++) {
        const float* hprev = (t == 0) ? h0init : (H + (long)(t-1) * STEP);

        float acc0[8], acc1[8];
        #pragma unroll
        for (int j = 0; j < 8; j++) { acc0[j] = 0.f; acc1[j] = 0.f; }

        {
            const float* src = hprev + (long)lh * HID + lc;
            uint32_t dst = hs_s + (uint32_t)(lc * HSP + lh) * 4u;
            #pragma unroll 16
            for (int b = 0; b < 32; b++)
                asm volatile("cp.async.ca.shared.global [%0], [%1], 4;"
                             :: "r"(dst + b*4u), "l"(src + (long)b*HID));
            asm volatile("cp.async.commit_group;");
        }

        int buf = 0;
        #pragma unroll 1
        for (int tile = 0; tile < 8; tile++) {
            if (tile < 7) {
                const float* src = hprev + (long)lh * HID + (tile+1)*TK + lc;
                uint32_t dst = hs_s + (uint32_t)(((buf^1)*TK + lc) * HSP + lh) * 4u;
                #pragma unroll 16
                for (int b = 0; b < 32; b++)
                    asm volatile("cp.async.ca.shared.global [%0], [%1], 4;"
                                 :: "r"(dst + b*4u), "l"(src + (long)b*HID));
                asm volatile("cp.async.commit_group;");
                asm volatile("cp.async.wait_group 1;");
            } else {
                asm volatile("cp.async.wait_group 0;");
            }
            __syncthreads();

            const float* hb = hs + buf*TK*HSP;
            const int kwarp = warp * 16;
            #pragma unroll
            for (int q = 0; q < 4; q++) {
                const int kl = kwarp + q*4;
                float h0[4], h1[4];
                #pragma unroll
                for (int i = 0; i < 4; i++) {
                    h0[i] = hb[(kl+i)*HSP + lane];
                    h1[i] = hb[(kl+i)*HSP + lane + 32];
                }
                const int kg = tile*TK + kl;
                #pragma unroll
                for (int j = 0; j < 8; j++) {
                    float4 w = *reinterpret_cast<const float4*>(Ws + j*1024 + kg);
                    acc0[j] = fmaf(h0[0], w.x, acc0[j]);
                    acc0[j] = fmaf(h0[1], w.y, acc0[j]);
                    acc0[j] = fmaf(h0[2], w.z, acc0[j]);
                    acc0[j] = fmaf(h0[3], w.w, acc0[j]);
                    acc1[j] = fmaf(h1[0], w.x, acc1[j]);
                    acc1[j] = fmaf(h1[1], w.y, acc1[j]);
                    acc1[j] = fmaf(h1[2], w.z, acc1[j]);
                    acc1[j] = fmaf(h1[3], w.w, acc1[j]);
                }
            }
            __syncthreads();
            buf ^= 1;
        }

        #pragma unroll
        for (int j = 0; j < 8; j++) {
            red[((warp*2 + 0)*32 + lane)*9 + j] = acc0[j];
            red[((warp*2 + 1)*32 + lane)*9 + j] = acc1[j];
        }
        __syncthreads();

        const float* Xt = X + (long)t * STEP;
        float*       Ht = H + (long)t * STEP;
        __nv_bfloat16* HhT = Hh + (long)t * STEP;
        __nv_bfloat16* HlT = Hl + (long)t * STEP;
        #pragma unroll
        for (int i = 0; i < 2; i++) {
            int o   = tid + i*256;       // 0..511
            int g   = o >> 8;            // b-half
            int rem = o & 255;
            int l   = rem >> 3;          // lane-b
            int j   = rem & 7;
            float s = 0.f;
            #pragma unroll
            for (int w = 0; w < 8; w++)
                s += red[((w*2 + g)*32 + l)*9 + j];
            int b   = g*32 + l;
            int col = j0 + j;
            long idx = (long)b*HID + col;
            float hv = tanhf(s + Xt[idx]);
            Ht[idx] = hv;
            __nv_bfloat16 hi = __float2bfloat16_rn(hv);
            HhT[idx] = hi;
            HlT[idx] = __float2bfloat16_rn(hv - __bfloat162float(hi));
        }

        __threadfence();
        __syncthreads();
        if (tid == 0) {
            atomicAdd(&g_cnt[t], 1u);
            while (*((volatile unsigned*)&g_cnt[t]) < (unsigned)RNB) {
                __nanosleep(40);
            }
            if (blockIdx.x == 0)
                atomicExch(&g_cnt[(t + 126) & 127], 0u);
        }
        __syncthreads();
        __threadfence();
    }
}

// ===========================================================================
// Split fp32 -> (bf16 hi, bf16 lo)  (weights/embedding only)
// ===========================================================================
__global__ void split_bf16(const float* __restrict__ src,
                           __nv_bfloat16* __restrict__ hi,
                           __nv_bfloat16* __restrict__ lo, int n)
{
    int i = blockIdx.x * blockDim.x + threadIdx.x;
    if (i < n) {
        float x = src[i];
        __nv_bfloat16 h = __float2bfloat16_rn(x);
        float r = x - __bfloat162float(h);
        hi[i] = h;
        lo[i] = __float2bfloat16_rn(r);
    }
}

// ---------------------------------------------------------------------------
__global__ void copy_tail(float* __restrict__ dst)
{
    int i = blockIdx.x * blockDim.x + threadIdx.x;
    if (i < STEP)          dst[i] = g_H0[(long)(SEQ - 1) * STEP + i];
    else if (i < 2 * STEP) dst[i] = g_H1[(long)(SEQ - 1) * STEP + (i - STEP)];
}

// ---------------------------------------------------------------------------
extern "C" void kernel_launch(void* const* d_in, const int* in_sizes, int n_in,
                              void* d_out, int out_size)
{
    const int*   tok    = (const int*)  d_in[0];
    const float* hidden = (const float*)d_in[1];
    const float* emb    = (const float*)d_in[2];
    const float* W0x    = (const float*)d_in[3];
    const float* W0h    = (const float*)d_in[4];
    const float* b0     = (const float*)d_in[5];
    const float* W1x    = (const float*)d_in[6];
    const float* W1h    = (const float*)d_in[7];
    const float* b1     = (const float*)d_in[8];
    const float* Wout   = (const float*)d_in[9];
    const float* bout   = (const float*)d_in[10];
    float* out = (float*)d_out;

    float *X0, *H0, *X1, *H1;
    __nv_bfloat16 *EmbH, *EmbL, *W0xH, *W0xL, *W1xH, *W1xL, *WoH, *WoL;
    __nv_bfloat16 *A0H, *A0L, *A1H, *A1L;
    cudaGetSymbolAddress((void**)&X0, g_X0);
    cudaGetSymbolAddress((void**)&H0, g_H0);
    cudaGetSymbolAddress((void**)&X1, g_X1);
    cudaGetSymbolAddress((void**)&H1, g_H1);
    cudaGetSymbolAddress((void**)&EmbH, g_EmbH);
    cudaGetSymbolAddress((void**)&EmbL, g_EmbL);
    cudaGetSymbolAddress((void**)&W0xH, g_W0xH);
    cudaGetSymbolAddress((void**)&W0xL, g_W0xL);
    cudaGetSymbolAddress((void**)&W1xH, g_W1xH);
    cudaGetSymbolAddress((void**)&W1xL, g_W1xL);
    cudaGetSymbolAddress((void**)&WoH, g_WoH);
    cudaGetSymbolAddress((void**)&WoL, g_WoL);
    cudaGetSymbolAddress((void**)&A0H, g_A0H);
    cudaGetSymbolAddress((void**)&A0L, g_A0L);
    cudaGetSymbolAddress((void**)&A1H, g_A1H);
    cudaGetSymbolAddress((void**)&A1L, g_A1L);

    static bool attr_set = false;
    if (!attr_set) {
        cudaFuncSetAttribute(rnn_layer,
                             cudaFuncAttributeMaxDynamicSharedMemorySize, SM_BYTES);
        cudaFuncSetAttribute(mma_gemm<true>,
                             cudaFuncAttributeMaxDynamicSharedMemorySize, GEMM_SMEM);
        cudaFuncSetAttribute(mma_gemm<false>,
                             cudaFuncAttributeMaxDynamicSharedMemorySize, GEMM_SMEM);
        attr_set = true;
    }

    // Upfront splits (weights + embedding)
    split_bf16<<<(VOCAB*HID + 255)/256, 256>>>(Wout, WoH, WoL, VOCAB*HID);
    split_bf16<<<(VOCAB*EMB + 255)/256, 256>>>(emb, EmbH, EmbL, VOCAB*EMB);
    split_bf16<<<(HID*EMB + 255)/256, 256>>>(W0x, W0xH, W0xL, HID*EMB);
    split_bf16<<<(HID*HID + 255)/256, 256>>>(W1x, W1xH, W1xL, HID*HID);

    // Phase A: X0 = emb[tok] @ W0x^T + b0   (gathered A, K=512)
    mma_gemm<true><<<dim3(HID/128, MB/128), 256, GEMM_SMEM>>>(
        EmbH, EmbL, tok, W0xH, W0xL, b0, X0, MB, HID, EMB);

    // Phase B: layer-0 recurrence (emits H0 + bf16 splits)
    rnn_layer<<<RNB, RNT, SM_BYTES>>>(hidden, W0h, X0, H0, A0H, A0L);

    // Phase C: X1 = H0 @ W1x^T + b1
    mma_gemm<false><<<dim3(HID/128, MB/128), 256, GEMM_SMEM>>>(
        A0H, A0L, nullptr, W1xH, W1xL, b1, X1, MB, HID, HID);

    // Phase D: layer-1 recurrence (emits H1 + bf16 splits)
    rnn_layer<<<RNB, RNT, SM_BYTES>>>(hidden + STEP, W1h, X1, H1, A1H, A1L);

    // Phase E: logits = H1 @ Wout^T + bout
    mma_gemm<false><<<dim3((VOCAB + 127)/128, MB/128), 256, GEMM_SMEM>>>(
        A1H, A1L, nullptr, WoH, WoL, bout, out, MB, VOCAB, HID);

    // Tail
    copy_tail<<<(2*STEP + 255)/256, 256>>>(out + (long)SEQ * BATCH * VOCAB);
}

// round 8
// speedup vs baseline: 2.3563x; 1.0973x over previous
#include <cuda_runtime.h>
#include <cuda_fp16.h>
#include <cstdint>

// Problem constants
#define SEQ    128
#define BATCH  64
#define EMB    512
#define HID    1024
#define VOCAB  10000
#define MB     (SEQ*BATCH)        // 8192 rows when time-batched
#define STEP   (BATCH*HID)        // 65536 floats per timestep slab

// Scratch (device globals)
__device__ float g_X0[MB*HID];
__device__ float g_H0[MB*HID];
__device__ float g_X1[MB*HID];
__device__ float g_H1[MB*HID];
__device__ unsigned g_cnt[128];
// fp16 split operands for tensor-core GEMMs
__device__ __half g_EmbH[VOCAB*EMB], g_EmbL[VOCAB*EMB];
__device__ __half g_W0xH[HID*EMB],   g_W0xL[HID*EMB];
__device__ __half g_W1xH[HID*HID],   g_W1xL[HID*HID];
__device__ __half g_WoH[VOCAB*HID];                      // single fp16 (2-term path)
__device__ __half g_A0H[MB*HID],     g_A0L[MB*HID];      // H0 splits
__device__ __half g_A1H[MB*HID],     g_A1L[MB*HID];      // H1 splits

// ===========================================================================
// mma.sync fp16 GEMM, TERMS-way split accumulation.
//   TERMS=3: (Ah+Al)(Bh+Bl) minus AlBl  -> AhBh + AhBl + AlBh   (~2^-22 err)
//   TERMS=2: (Ah+Al)Bh                                          (~eps_fp16 err)
// C[M,N] = A[M,K] @ W[N,K]^T + bias[N]; tile 128x128, BK=32, 8 warps.
// ===========================================================================
#define GPITCH 80                     // bytes per smem tile row
#define TILE_B (128*GPITCH)           // 10240 B per tile
#define GEMM_SMEM_MAX (2*4*TILE_B)    // 3-term double buffer = 81920 B

__device__ __forceinline__ void ldsm4(uint32_t* r, uint32_t addr) {
    asm volatile("ldmatrix.sync.aligned.m8n8.x4.shared.b16 {%0,%1,%2,%3}, [%4];"
                 : "=r"(r[0]), "=r"(r[1]), "=r"(r[2]), "=r"(r[3]) : "r"(addr));
}
__device__ __forceinline__ void mma16816(float* d, const uint32_t* a, uint32_t b0, uint32_t b1) {
    asm volatile(
        "mma.sync.aligned.m16n8k16.row.col.f32.f16.f16.f32 "
        "{%0,%1,%2,%3}, {%4,%5,%6,%7}, {%8,%9}, {%0,%1,%2,%3};"
        : "+f"(d[0]), "+f"(d[1]), "+f"(d[2]), "+f"(d[3])
        : "r"(a[0]), "r"(a[1]), "r"(a[2]), "r"(a[3]), "r"(b0), "r"(b1));
}
__device__ __forceinline__ void cpa16(uint32_t dst, const void* src) {
    asm volatile("cp.async.cg.shared.global [%0], [%1], 16;" :: "r"(dst), "l"(src));
}
__device__ __forceinline__ void cpa16z(uint32_t dst, const void* src, uint32_t sz) {
    asm volatile("cp.async.cg.shared.global [%0], [%1], 16, %2;" :: "r"(dst), "l"(src), "r"(sz));
}

template<bool GATHER, int TERMS>
__global__ __launch_bounds__(256, 2)
void mma_gemm(const __half* __restrict__ Ah, const __half* __restrict__ Al,
              const int* __restrict__ rows,
              const __half* __restrict__ Bh, const __half* __restrict__ Bl,
              const float* __restrict__ bias, float* __restrict__ C,
              int M, int N, int K)
{
    constexpr uint32_t BUF_B = (TERMS == 3 ? 4 : 3) * TILE_B;
    extern __shared__ char smem[];
    const int tid  = threadIdx.x;
    const int lane = tid & 31;
    const int wid  = tid >> 5;
    const int mw   = wid >> 2;        // 0..1
    const int nw   = wid & 3;         // 0..3
    const int m0   = blockIdx.y * 128;
    const int n0   = blockIdx.x * 128;

    const uint32_t sbase = (uint32_t)__cvta_generic_to_shared(smem);

    float acc[4][4][4];
    #pragma unroll
    for (int f = 0; f < 4; f++)
        #pragma unroll
        for (int g = 0; g < 4; g++)
            #pragma unroll
            for (int e = 0; e < 4; e++) acc[f][g][e] = 0.f;

    const int nchunks = K >> 5;

    auto load_chunk = [&](int kt, int b) {
        const uint32_t tb = sbase + (uint32_t)b * BUF_B;
        #pragma unroll
        for (int i = 0; i < 2; i++) {
            int l  = tid + i * 256;        // 0..511
            int r  = l & 127;
            int cb = l >> 7;               // 0..3
            uint32_t doff = (uint32_t)(r * GPITCH + cb * 16);
            long ar = GATHER ? (long)rows[m0 + r] : (long)(m0 + r);
            cpa16(tb + doff,          Ah + ar * K + kt + cb * 8);
            cpa16(tb + TILE_B + doff, Al + ar * K + kt + cb * 8);
            int nr = n0 + r;
            uint32_t sz = (nr < N) ? 16u : 0u;
            long br = (nr < N) ? (long)nr : (long)(N - 1);
            cpa16z(tb + 2*TILE_B + doff, Bh + br * K + kt + cb * 8, sz);
            if (TERMS == 3)
                cpa16z(tb + 3*TILE_B + doff, Bl + br * K + kt + cb * 8, sz);
        }
        asm volatile("cp.async.commit_group;");
    };

    load_chunk(0, 0);

    #pragma unroll 1
    for (int c = 0; c < nchunks; c++) {
        if (c + 1 < nchunks) {
            load_chunk((c + 1) << 5, (c + 1) & 1);
            asm volatile("cp.async.wait_group 1;");
        } else {
            asm volatile("cp.async.wait_group 0;");
        }
        __syncthreads();

        const uint32_t tb = sbase + (uint32_t)(c & 1) * BUF_B;

        #pragma unroll
        for (int s = 0; s < 2; s++) {
            const uint32_t abase = tb
                + (uint32_t)((mw*64 + (lane & 15)) * GPITCH)
                + (uint32_t)(s*32 + (lane >> 4)*16);
            uint32_t bb[2];
            #pragma unroll
            for (int p = 0; p < 2; p++) {
                uint32_t brow = (uint32_t)(nw*32 + p*16 + (lane & 7) + ((lane >> 4) & 1)*8);
                bb[p] = tb + 2*TILE_B + brow * GPITCH
                      + (uint32_t)(s*32 + ((lane >> 3) & 1)*16);
            }

            uint32_t aF[4][4];
            if (TERMS == 3) {
                // pass 1: Ah vs (Bh, Bl)
                #pragma unroll
                for (int f = 0; f < 4; f++)
                    ldsm4(aF[f], abase + (uint32_t)(f * 16 * GPITCH));
                #pragma unroll
                for (int p = 0; p < 2; p++) {
                    uint32_t bh[4], bl[4];
                    ldsm4(bh, bb[p]);
                    ldsm4(bl, bb[p] + TILE_B);
                    #pragma unroll
                    for (int f = 0; f < 4; f++) {
                        mma16816(acc[f][2*p    ], aF[f], bh[0], bh[1]);
                        mma16816(acc[f][2*p + 1], aF[f], bh[2], bh[3]);
                        mma16816(acc[f][2*p    ], aF[f], bl[0], bl[1]);
                        mma16816(acc[f][2*p + 1], aF[f], bl[2], bl[3]);
                    }
                }
                // pass 2: Al vs Bh
                #pragma unroll
                for (int f = 0; f < 4; f++)
                    ldsm4(aF[f], abase + TILE_B + (uint32_t)(f * 16 * GPITCH));
                #pragma unroll
                for (int p = 0; p < 2; p++) {
                    uint32_t bh[4];
                    ldsm4(bh, bb[p]);
                    #pragma unroll
                    for (int f = 0; f < 4; f++) {
                        mma16816(acc[f][2*p    ], aF[f], bh[0], bh[1]);
                        mma16816(acc[f][2*p + 1], aF[f], bh[2], bh[3]);
                    }
                }
            } else {
                // TERMS == 2: (Ah + Al) vs Bh, B fragments loaded once
                uint32_t bh0[4], bh1[4];
                ldsm4(bh0, bb[0]);
                ldsm4(bh1, bb[1]);
                #pragma unroll
                for (int f = 0; f < 4; f++)
                    ldsm4(aF[f], abase + (uint32_t)(f * 16 * GPITCH));
                #pragma unroll
                for (int f = 0; f < 4; f++) {
                    mma16816(acc[f][0], aF[f], bh0[0], bh0[1]);
                    mma16816(acc[f][1], aF[f], bh0[2], bh0[3]);
                    mma16816(acc[f][2], aF[f], bh1[0], bh1[1]);
                    mma16816(acc[f][3], aF[f], bh1[2], bh1[3]);
                }
                #pragma unroll
                for (int f = 0; f < 4; f++)
                    ldsm4(aF[f], abase + TILE_B + (uint32_t)(f * 16 * GPITCH));
                #pragma unroll
                for (int f = 0; f < 4; f++) {
                    mma16816(acc[f][0], aF[f], bh0[0], bh0[1]);
                    mma16816(acc[f][1], aF[f], bh0[2], bh0[3]);
                    mma16816(acc[f][2], aF[f], bh1[0], bh1[1]);
                    mma16816(acc[f][3], aF[f], bh1[2], bh1[3]);
                }
            }
        }
        __syncthreads();
    }

    // ---- epilogue: + bias, predicated float2 stores ----
    #pragma unroll
    for (int f = 0; f < 4; f++) {
        long row = m0 + mw*64 + f*16 + (lane >> 2);
        #pragma unroll
        for (int g = 0; g < 4; g++) {
            int col = n0 + nw*32 + g*8 + (lane & 3)*2;
            if (col < N) {
                float bx = bias[col], by = bias[col + 1];
                float2 v0 = make_float2(acc[f][g][0] + bx, acc[f][g][1] + by);
                float2 v1 = make_float2(acc[f][g][2] + bx, acc[f][g][3] + by);
                *reinterpret_cast<float2*>(C + row * N + col)       = v0;
                *reinterpret_cast<float2*>(C + (row + 8) * N + col) = v1;
            }
        }
    }
}

// ===========================================================================
// Persistent recurrence kernel (phases B, D). 256 threads, 8 k-split warps.
// Epilogue emits H[t] fp32 + fp16 hi/lo splits.
// ===========================================================================
#define TK   128
#define HSP  65
#define RNB  128
#define RNT  256
#define SM_WS   0
#define SM_HS   (8*1024)
#define SM_RED  (SM_HS + 2*TK*HSP)
#define SM_BYTES  131072

__global__ __launch_bounds__(RNT, 1)
void rnn_layer(const float* __restrict__ h0init,
               const float* __restrict__ W,
               const float* __restrict__ X,
               float* __restrict__ H,
               __half* __restrict__ Hh,
               __half* __restrict__ Hl)
{
    extern __shared__ float sm[];
    float* Ws  = sm + SM_WS;
    float* hs  = sm + SM_HS;
    float* red = sm + SM_RED;

    const int tid  = threadIdx.x;
    const int lane = tid & 31;
    const int warp = tid >> 5;
    const int j0   = blockIdx.x * 8;

    for (int i = tid; i < 8*1024/4; i += RNT) {
        int j  = i >> 8;
        int kq = i & 255;
        float4 v = *reinterpret_cast<const float4*>(W + (long)(j0 + j) * HID + kq * 4);
        *reinterpret_cast<float4*>(Ws + j*1024 + kq*4) = v;
    }
    __syncthreads();

    const uint32_t hs_s = (uint32_t)__cvta_generic_to_shared(hs);
    const int lc = tid >> 1;
    const int lh = (tid & 1) * 32;

    for (int t = 0; t < SEQ; t++) {
        const float* hprev = (t == 0) ? h0init : (H + (long)(t-1) * STEP);

        float acc0[8], acc1[8];
        #pragma unroll
        for (int j = 0; j < 8; j++) { acc0[j] = 0.f; acc1[j] = 0.f; }

        {
            const float* src = hprev + (long)lh * HID + lc;
            uint32_t dst = hs_s + (uint32_t)(lc * HSP + lh) * 4u;
            #pragma unroll 16
            for (int b = 0; b < 32; b++)
                asm volatile("cp.async.ca.shared.global [%0], [%1], 4;"
                             :: "r"(dst + b*4u), "l"(src + (long)b*HID));
            asm volatile("cp.async.commit_group;");
        }

        int buf = 0;
        #pragma unroll 1
        for (int tile = 0; tile < 8; tile++) {
            if (tile < 7) {
                const float* src = hprev + (long)lh * HID + (tile+1)*TK + lc;
                uint32_t dst = hs_s + (uint32_t)(((buf^1)*TK + lc) * HSP + lh) * 4u;
                #pragma unroll 16
                for (int b = 0; b < 32; b++)
                    asm volatile("cp.async.ca.shared.global [%0], [%1], 4;"
                                 :: "r"(dst + b*4u), "l"(src + (long)b*HID));
                asm volatile("cp.async.commit_group;");
                asm volatile("cp.async.wait_group 1;");
            } else {
                asm volatile("cp.async.wait_group 0;");
            }
            __syncthreads();

            const float* hb = hs + buf*TK*HSP;
            const int kwarp = warp * 16;
            #pragma unroll
            for (int q = 0; q < 4; q++) {
                const int kl = kwarp + q*4;
                float h0[4], h1[4];
                #pragma unroll
                for (int i = 0; i < 4; i++) {
                    h0[i] = hb[(kl+i)*HSP + lane];
                    h1[i] = hb[(kl+i)*HSP + lane + 32];
                }
                const int kg = tile*TK + kl;
                #pragma unroll
                for (int j = 0; j < 8; j++) {
                    float4 w = *reinterpret_cast<const float4*>(Ws + j*1024 + kg);
                    acc0[j] = fmaf(h0[0], w.x, acc0[j]);
                    acc0[j] = fmaf(h0[1], w.y, acc0[j]);
                    acc0[j] = fmaf(h0[2], w.z, acc0[j]);
                    acc0[j] = fmaf(h0[3], w.w, acc0[j]);
                    acc1[j] = fmaf(h1[0], w.x, acc1[j]);
                    acc1[j] = fmaf(h1[1], w.y, acc1[j]);
                    acc1[j] = fmaf(h1[2], w.z, acc1[j]);
                    acc1[j] = fmaf(h1[3], w.w, acc1[j]);
                }
            }
            __syncthreads();
            buf ^= 1;
        }

        #pragma unroll
        for (int j = 0; j < 8; j++) {
            red[((warp*2 + 0)*32 + lane)*9 + j] = acc0[j];
            red[((warp*2 + 1)*32 + lane)*9 + j] = acc1[j];
        }
        __syncthreads();

        const float* Xt = X + (long)t * STEP;
        float*       Ht = H + (long)t * STEP;
        __half* HhT = Hh + (long)t * STEP;
        __half* HlT = Hl + (long)t * STEP;
        #pragma unroll
        for (int i = 0; i < 2; i++) {
            int o   = tid + i*256;
            int g   = o >> 8;
            int rem = o & 255;
            int l   = rem >> 3;
            int j   = rem & 7;
            float s = 0.f;
            #pragma unroll
            for (int w = 0; w < 8; w++)
                s += red[((w*2 + g)*32 + l)*9 + j];
            int b   = g*32 + l;
            int col = j0 + j;
            long idx = (long)b*HID + col;
            float hv = tanhf(s + Xt[idx]);
            Ht[idx] = hv;
            __half hi = __float2half_rn(hv);
            HhT[idx] = hi;
            HlT[idx] = __float2half_rn(hv - __half2float(hi));
        }

        __threadfence();
        __syncthreads();
        if (tid == 0) {
            atomicAdd(&g_cnt[t], 1u);
            while (*((volatile unsigned*)&g_cnt[t]) < (unsigned)RNB) {
                __nanosleep(40);
            }
            if (blockIdx.x == 0)
                atomicExch(&g_cnt[(t + 126) & 127], 0u);
        }
        __syncthreads();
        __threadfence();
    }
}

// ===========================================================================
// One merged prep kernel: all weight/embedding fp16 conversions.
// ===========================================================================
#define N_EMBV (VOCAB*EMB)
#define N_W0X  (HID*EMB)
#define N_W1X  (HID*HID)
#define N_WO   (VOCAB*HID)
#define N_PREP (N_EMBV + N_W0X + N_W1X + N_WO)

__global__ void prep_weights(const float* __restrict__ emb, const float* __restrict__ W0x,
                             const float* __restrict__ W1x, const float* __restrict__ Wout,
                             __half* __restrict__ EmbH, __half* __restrict__ EmbL,
                             __half* __restrict__ W0xH, __half* __restrict__ W0xL,
                             __half* __restrict__ W1xH, __half* __restrict__ W1xL,
                             __half* __restrict__ WoH)
{
    long i = (long)blockIdx.x * blockDim.x + threadIdx.x;
    if (i < N_EMBV) {
        float x = emb[i];
        __half h = __float2half_rn(x);
        EmbH[i] = h;
        EmbL[i] = __float2half_rn(x - __half2float(h));
    } else if (i < N_EMBV + N_W0X) {
        long k = i - N_EMBV;
        float x = W0x[k];
        __half h = __float2half_rn(x);
        W0xH[k] = h;
        W0xL[k] = __float2half_rn(x - __half2float(h));
    } else if (i < N_EMBV + N_W0X + N_W1X) {
        long k = i - N_EMBV - N_W0X;
        float x = W1x[k];
        __half h = __float2half_rn(x);
        W1xH[k] = h;
        W1xL[k] = __float2half_rn(x - __half2float(h));
    } else if (i < N_PREP) {
        long k = i - N_EMBV - N_W0X - N_W1X;
        WoH[k] = __float2half_rn(Wout[k]);
    }
}

// ---------------------------------------------------------------------------
__global__ void copy_tail(float* __restrict__ dst)
{
    int i = blockIdx.x * blockDim.x + threadIdx.x;
    if (i < STEP)          dst[i] = g_H0[(long)(SEQ - 1) * STEP + i];
    else if (i < 2 * STEP) dst[i] = g_H1[(long)(SEQ - 1) * STEP + (i - STEP)];
}

// ---------------------------------------------------------------------------
extern "C" void kernel_launch(void* const* d_in, const int* in_sizes, int n_in,
                              void* d_out, int out_size)
{
    const int*   tok    = (const int*)  d_in[0];
    const float* hidden = (const float*)d_in[1];
    const float* emb    = (const float*)d_in[2];
    const float* W0x    = (const float*)d_in[3];
    const float* W0h    = (const float*)d_in[4];
    const float* b0     = (const float*)d_in[5];
    const float* W1x    = (const float*)d_in[6];
    const float* W1h    = (const float*)d_in[7];
    const float* b1     = (const float*)d_in[8];
    const float* Wout   = (const float*)d_in[9];
    const float* bout   = (const float*)d_in[10];
    float* out = (float*)d_out;

    float *X0, *H0, *X1, *H1;
    __half *EmbH, *EmbL, *W0xH, *W0xL, *W1xH, *W1xL, *WoH;
    __half *A0H, *A0L, *A1H, *A1L;
    cudaGetSymbolAddress((void**)&X0, g_X0);
    cudaGetSymbolAddress((void**)&H0, g_H0);
    cudaGetSymbolAddress((void**)&X1, g_X1);
    cudaGetSymbolAddress((void**)&H1, g_H1);
    cudaGetSymbolAddress((void**)&EmbH, g_EmbH);
    cudaGetSymbolAddress((void**)&EmbL, g_EmbL);
    cudaGetSymbolAddress((void**)&W0xH, g_W0xH);
    cudaGetSymbolAddress((void**)&W0xL, g_W0xL);
    cudaGetSymbolAddress((void**)&W1xH, g_W1xH);
    cudaGetSymbolAddress((void**)&W1xL, g_W1xL);
    cudaGetSymbolAddress((void**)&WoH, g_WoH);
    cudaGetSymbolAddress((void**)&A0H, g_A0H);
    cudaGetSymbolAddress((void**)&A0L, g_A0L);
    cudaGetSymbolAddress((void**)&A1H, g_A1H);
    cudaGetSymbolAddress((void**)&A1L, g_A1L);

    static bool attr_set = false;
    if (!attr_set) {
        cudaFuncSetAttribute(rnn_layer,
                             cudaFuncAttributeMaxDynamicSharedMemorySize, SM_BYTES);
        cudaFuncSetAttribute(mma_gemm<true, 3>,
                             cudaFuncAttributeMaxDynamicSharedMemorySize, GEMM_SMEM_MAX);
        cudaFuncSetAttribute(mma_gemm<false, 3>,
                             cudaFuncAttributeMaxDynamicSharedMemorySize, GEMM_SMEM_MAX);
        cudaFuncSetAttribute(mma_gemm<false, 2>,
                             cudaFuncAttributeMaxDynamicSharedMemorySize, GEMM_SMEM_MAX);
        attr_set = true;
    }

    // Prep: all weight/embedding conversions in one launch
    prep_weights<<<(N_PREP + 255)/256, 256>>>(emb, W0x, W1x, Wout,
        EmbH, EmbL, W0xH, W0xL, W1xH, W1xL, WoH);

    // Phase A: X0 = emb[tok] @ W0x^T + b0   (3-term, gathered)
    mma_gemm<true, 3><<<dim3(HID/128, MB/128), 256, 2*4*TILE_B>>>(
        EmbH, EmbL, tok, W0xH, W0xL, b0, X0, MB, HID, EMB);

    // Phase B: layer-0 recurrence (emits H0 + fp16 splits)
    rnn_layer<<<RNB, RNT, SM_BYTES>>>(hidden, W0h, X0, H0, A0H, A0L);

    // Phase C: X1 = H0 @ W1x^T + b1   (3-term)
    mma_gemm<false, 3><<<dim3(HID/128, MB/128), 256, 2*4*TILE_B>>>(
        A0H, A0L, nullptr, W1xH, W1xL, b1, X1, MB, HID, HID);

    // Phase D: layer-1 recurrence (emits H1 + fp16 splits)
    rnn_layer<<<RNB, RNT, SM_BYTES>>>(hidden + STEP, W1h, X1, H1, A1H, A1L);

    // Phase E: logits = H1 @ Wout^T + bout   (2-term: A split, B single fp16)
    mma_gemm<false, 2><<<dim3((VOCAB + 127)/128, MB/128), 256, 2*3*TILE_B>>>(
        A1H, A1L, nullptr, WoH, nullptr, bout, out, MB, VOCAB, HID);

    // Tail
    copy_tail<<<(2*STEP + 255)/256, 256>>>(out + (long)SEQ * BATCH * VOCAB);
}

// round 9
// speedup vs baseline: 2.3854x; 1.0123x over previous
#include <cuda_runtime.h>
#include <cuda_fp16.h>
#include <cstdint>

// Problem constants
#define SEQ    128
#define BATCH  64
#define EMB    512
#define HID    1024
#define VOCAB  10000
#define MB     (SEQ*BATCH)        // 8192 rows when time-batched
#define STEP   (BATCH*HID)        // 65536 floats per timestep slab

// Scratch (device globals)
__device__ float g_X0[MB*HID];
__device__ float g_H0[MB*HID];
__device__ float g_X1[MB*HID];
__device__ float g_H1[MB*HID];
__device__ unsigned g_cnt[128];
// fp16 split operands for tensor-core GEMMs
__device__ __half g_EmbH[VOCAB*EMB], g_EmbL[VOCAB*EMB];
__device__ __half g_W0xH[HID*EMB],   g_W0xL[HID*EMB];
__device__ __half g_W1xH[HID*HID],   g_W1xL[HID*HID];
__device__ __half g_WoH[VOCAB*HID];                      // single fp16 (2-term path)
__device__ __half g_A0H[MB*HID],     g_A0L[MB*HID];      // H0 splits
__device__ __half g_A1H[MB*HID],     g_A1L[MB*HID];      // H1 splits

// ===========================================================================
// mma.sync fp16 GEMM, TERMS-way split, STAGES-deep cp.async pipeline.
//   TERMS=3: AhBh + AhBl + AlBh   (~2^-22 err)    stage = 4 tiles
//   TERMS=2: (Ah+Al)Bh            (~eps_fp16 err) stage = 3 tiles
// C[M,N] = A[M,K] @ W[N,K]^T + bias[N]; tile 128x128, BK=32, 8 warps.
// One __syncthreads per chunk; buffer reuse protected by next iter's sync.
// ===========================================================================
#define GPITCH 80                     // bytes per smem tile row
#define TILE_B (128*GPITCH)           // 10240 B per tile

__device__ __forceinline__ void ldsm4(uint32_t* r, uint32_t addr) {
    asm volatile("ldmatrix.sync.aligned.m8n8.x4.shared.b16 {%0,%1,%2,%3}, [%4];"
                 : "=r"(r[0]), "=r"(r[1]), "=r"(r[2]), "=r"(r[3]) : "r"(addr));
}
__device__ __forceinline__ void mma16816(float* d, const uint32_t* a, uint32_t b0, uint32_t b1) {
    asm volatile(
        "mma.sync.aligned.m16n8k16.row.col.f32.f16.f16.f32 "
        "{%0,%1,%2,%3}, {%4,%5,%6,%7}, {%8,%9}, {%0,%1,%2,%3};"
        : "+f"(d[0]), "+f"(d[1]), "+f"(d[2]), "+f"(d[3])
        : "r"(a[0]), "r"(a[1]), "r"(a[2]), "r"(a[3]), "r"(b0), "r"(b1));
}
__device__ __forceinline__ void cpa16(uint32_t dst, const void* src) {
    asm volatile("cp.async.cg.shared.global [%0], [%1], 16;" :: "r"(dst), "l"(src));
}
__device__ __forceinline__ void cpa16z(uint32_t dst, const void* src, uint32_t sz) {
    asm volatile("cp.async.cg.shared.global [%0], [%1], 16, %2;" :: "r"(dst), "l"(src), "r"(sz));
}

template<bool GATHER, int TERMS, int STAGES>
__global__ __launch_bounds__(256, 2)
void mma_gemm(const __half* __restrict__ Ah, const __half* __restrict__ Al,
              const int* __restrict__ rows,
              const __half* __restrict__ Bh, const __half* __restrict__ Bl,
              const float* __restrict__ bias, float* __restrict__ C,
              int M, int N, int K)
{
    constexpr uint32_t BUF_B = (TERMS == 3 ? 4 : 3) * TILE_B;
    extern __shared__ char smem[];
    const int tid  = threadIdx.x;
    const int lane = tid & 31;
    const int wid  = tid >> 5;
    const int mw   = wid >> 2;        // 0..1
    const int nw   = wid & 3;         // 0..3
    const int m0   = blockIdx.y * 128;
    const int n0   = blockIdx.x * 128;

    const uint32_t sbase = (uint32_t)__cvta_generic_to_shared(smem);

    float acc[4][4][4];
    #pragma unroll
    for (int f = 0; f < 4; f++)
        #pragma unroll
        for (int g = 0; g < 4; g++)
            #pragma unroll
            for (int e = 0; e < 4; e++) acc[f][g][e] = 0.f;

    const int nchunks = K >> 5;

    auto load_chunk = [&](int kt, int b) {
        const uint32_t tb = sbase + (uint32_t)b * BUF_B;
        #pragma unroll
        for (int i = 0; i < 2; i++) {
            int l  = tid + i * 256;        // 0..511
            int r  = l & 127;
            int cb = l >> 7;               // 0..3
            uint32_t doff = (uint32_t)(r * GPITCH + cb * 16);
            long ar = GATHER ? (long)rows[m0 + r] : (long)(m0 + r);
            cpa16(tb + doff,          Ah + ar * K + kt + cb * 8);
            cpa16(tb + TILE_B + doff, Al + ar * K + kt + cb * 8);
            int nr = n0 + r;
            uint32_t sz = (nr < N) ? 16u : 0u;
            long br = (nr < N) ? (long)nr : (long)(N - 1);
            cpa16z(tb + 2*TILE_B + doff, Bh + br * K + kt + cb * 8, sz);
            if (TERMS == 3)
                cpa16z(tb + 3*TILE_B + doff, Bl + br * K + kt + cb * 8, sz);
        }
        asm volatile("cp.async.commit_group;");
    };

    // prologue: stages 0..STAGES-2
    #pragma unroll
    for (int s = 0; s < STAGES - 1; s++)
        load_chunk(s << 5, s);

    #pragma unroll 1
    for (int c = 0; c < nchunks; c++) {
        if (c + STAGES - 1 < nchunks) {
            asm volatile("cp.async.wait_group %0;" :: "n"(STAGES - 2));
            __syncthreads();
            load_chunk((c + STAGES - 1) << 5, (c + STAGES - 1) % STAGES);
        } else {
            asm volatile("cp.async.wait_group 0;");
            __syncthreads();
        }

        const uint32_t tb = sbase + (uint32_t)(c % STAGES) * BUF_B;

        #pragma unroll
        for (int s = 0; s < 2; s++) {
            const uint32_t abase = tb
                + (uint32_t)((mw*64 + (lane & 15)) * GPITCH)
                + (uint32_t)(s*32 + (lane >> 4)*16);
            uint32_t bb[2];
            #pragma unroll
            for (int p = 0; p < 2; p++) {
                uint32_t brow = (uint32_t)(nw*32 + p*16 + (lane & 7) + ((lane >> 4) & 1)*8);
                bb[p] = tb + 2*TILE_B + brow * GPITCH
                      + (uint32_t)(s*32 + ((lane >> 3) & 1)*16);
            }

            uint32_t aF[4][4];
            if (TERMS == 3) {
                // pass 1: Ah vs (Bh, Bl)
                #pragma unroll
                for (int f = 0; f < 4; f++)
                    ldsm4(aF[f], abase + (uint32_t)(f * 16 * GPITCH));
                #pragma unroll
                for (int p = 0; p < 2; p++) {
                    uint32_t bh[4], bl[4];
                    ldsm4(bh, bb[p]);
                    ldsm4(bl, bb[p] + TILE_B);
                    #pragma unroll
                    for (int f = 0; f < 4; f++) {
                        mma16816(acc[f][2*p    ], aF[f], bh[0], bh[1]);
                        mma16816(acc[f][2*p + 1], aF[f], bh[2], bh[3]);
                        mma16816(acc[f][2*p    ], aF[f], bl[0], bl[1]);
                        mma16816(acc[f][2*p + 1], aF[f], bl[2], bl[3]);
                    }
                }
                // pass 2: Al vs Bh
                #pragma unroll
                for (int f = 0; f < 4; f++)
                    ldsm4(aF[f], abase + TILE_B + (uint32_t)(f * 16 * GPITCH));
                #pragma unroll
                for (int p = 0; p < 2; p++) {
                    uint32_t bh[4];
                    ldsm4(bh, bb[p]);
                    #pragma unroll
                    for (int f = 0; f < 4; f++) {
                        mma16816(acc[f][2*p    ], aF[f], bh[0], bh[1]);
                        mma16816(acc[f][2*p + 1], aF[f], bh[2], bh[3]);
                    }
                }
            } else {
                // TERMS == 2: (Ah + Al) vs Bh, B fragments loaded once
                uint32_t bh0[4], bh1[4];
                ldsm4(bh0, bb[0]);
                ldsm4(bh1, bb[1]);
                #pragma unroll
                for (int f = 0; f < 4; f++)
                    ldsm4(aF[f], abase + (uint32_t)(f * 16 * GPITCH));
                #pragma unroll
                for (int f = 0; f < 4; f++) {
                    mma16816(acc[f][0], aF[f], bh0[0], bh0[1]);
                    mma16816(acc[f][1], aF[f], bh0[2], bh0[3]);
                    mma16816(acc[f][2], aF[f], bh1[0], bh1[1]);
                    mma16816(acc[f][3], aF[f], bh1[2], bh1[3]);
                }
                #pragma unroll
                for (int f = 0; f < 4; f++)
                    ldsm4(aF[f], abase + TILE_B + (uint32_t)(f * 16 * GPITCH));
                #pragma unroll
                for (int f = 0; f < 4; f++) {
                    mma16816(acc[f][0], aF[f], bh0[0], bh0[1]);
                    mma16816(acc[f][1], aF[f], bh0[2], bh0[3]);
                    mma16816(acc[f][2], aF[f], bh1[0], bh1[1]);
                    mma16816(acc[f][3], aF[f], bh1[2], bh1[3]);
                }
            }
        }
        // no trailing sync: next iteration's sync precedes any buffer overwrite
    }

    // ---- epilogue: + bias, predicated float2 stores ----
    #pragma unroll
    for (int f = 0; f < 4; f++) {
        long row = m0 + mw*64 + f*16 + (lane >> 2);
        #pragma unroll
        for (int g = 0; g < 4; g++) {
            int col = n0 + nw*32 + g*8 + (lane & 3)*2;
            if (col < N) {
                float bx = bias[col], by = bias[col + 1];
                float2 v0 = make_float2(acc[f][g][0] + bx, acc[f][g][1] + by);
                float2 v1 = make_float2(acc[f][g][2] + bx, acc[f][g][3] + by);
                *reinterpret_cast<float2*>(C + row * N + col)       = v0;
                *reinterpret_cast<float2*>(C + (row + 8) * N + col) = v1;
            }
        }
    }
}

// ===========================================================================
// Persistent recurrence kernel (phases B, D). 256 threads, 8 k-split warps.
// Epilogue emits H[t] fp32 + fp16 hi/lo splits.
// ===========================================================================
#define TK   128
#define HSP  65
#define RNB  128
#define RNT  256
#define SM_WS   0
#define SM_HS   (8*1024)
#define SM_RED  (SM_HS + 2*TK*HSP)
#define SM_BYTES  131072

__global__ __launch_bounds__(RNT, 1)
void rnn_layer(const float* __restrict__ h0init,
               const float* __restrict__ W,
               const float* __restrict__ X,
               float* __restrict__ H,
               __half* __restrict__ Hh,
               __half* __restrict__ Hl)
{
    extern __shared__ float sm[];
    float* Ws  = sm + SM_WS;
    float* hs  = sm + SM_HS;
    float* red = sm + SM_RED;

    const int tid  = threadIdx.x;
    const int lane = tid & 31;
    const int warp = tid >> 5;
    const int j0   = blockIdx.x * 8;

    for (int i = tid; i < 8*1024/4; i += RNT) {
        int j  = i >> 8;
        int kq = i & 255;
        float4 v = *reinterpret_cast<const float4*>(W + (long)(j0 + j) * HID + kq * 4);
        *reinterpret_cast<float4*>(Ws + j*1024 + kq*4) = v;
    }
    __syncthreads();

    const uint32_t hs_s = (uint32_t)__cvta_generic_to_shared(hs);
    const int lc = tid >> 1;
    const int lh = (tid & 1) * 32;

    for (int t = 0; t < SEQ; t++) {
        const float* hprev = (t == 0) ? h0init : (H + (long)(t-1) * STEP);

        float acc0[8], acc1[8];
        #pragma unroll
        for (int j = 0; j < 8; j++) { acc0[j] = 0.f; acc1[j] = 0.f; }

        {
            const float* src = hprev + (long)lh * HID + lc;
            uint32_t dst = hs_s + (uint32_t)(lc * HSP + lh) * 4u;
            #pragma unroll 16
            for (int b = 0; b < 32; b++)
                asm volatile("cp.async.ca.shared.global [%0], [%1], 4;"
                             :: "r"(dst + b*4u), "l"(src + (long)b*HID));
            asm volatile("cp.async.commit_group;");
        }

        int buf = 0;
        #pragma unroll 1
        for (int tile = 0; tile < 8; tile++) {
            if (tile < 7) {
                const float* src = hprev + (long)lh * HID + (tile+1)*TK + lc;
                uint32_t dst = hs_s + (uint32_t)(((buf^1)*TK + lc) * HSP + lh) * 4u;
                #pragma unroll 16
                for (int b = 0; b < 32; b++)
                    asm volatile("cp.async.ca.shared.global [%0], [%1], 4;"
                                 :: "r"(dst + b*4u), "l"(src + (long)b*HID));
                asm volatile("cp.async.commit_group;");
                asm volatile("cp.async.wait_group 1;");
            } else {
                asm volatile("cp.async.wait_group 0;");
            }
            __syncthreads();

            const float* hb = hs + buf*TK*HSP;
            const int kwarp = warp * 16;
            #pragma unroll
            for (int q = 0; q < 4; q++) {
                const int kl = kwarp + q*4;
                float h0[4], h1[4];
                #pragma unroll
                for (int i = 0; i < 4; i++) {
                    h0[i] = hb[(kl+i)*HSP + lane];
                    h1[i] = hb[(kl+i)*HSP + lane + 32];
                }
                const int kg = tile*TK + kl;
                #pragma unroll
                for (int j = 0; j < 8; j++) {
                    float4 w = *reinterpret_cast<const float4*>(Ws + j*1024 + kg);
                    acc0[j] = fmaf(h0[0], w.x, acc0[j]);
                    acc0[j] = fmaf(h0[1], w.y, acc0[j]);
                    acc0[j] = fmaf(h0[2], w.z, acc0[j]);
                    acc0[j] = fmaf(h0[3], w.w, acc0[j]);
                    acc1[j] = fmaf(h1[0], w.x, acc1[j]);
                    acc1[j] = fmaf(h1[1], w.y, acc1[j]);
                    acc1[j] = fmaf(h1[2], w.z, acc1[j]);
                    acc1[j] = fmaf(h1[3], w.w, acc1[j]);
                }
            }
            __syncthreads();
            buf ^= 1;
        }

        #pragma unroll
        for (int j = 0; j < 8; j++) {
            red[((warp*2 + 0)*32 + lane)*9 + j] = acc0[j];
            red[((warp*2 + 1)*32 + lane)*9 + j] = acc1[j];
        }
        __syncthreads();

        const float* Xt = X + (long)t * STEP;
        float*       Ht = H + (long)t * STEP;
        __half* HhT = Hh + (long)t * STEP;
        __half* HlT = Hl + (long)t * STEP;
        #pragma unroll
        for (int i = 0; i < 2; i++) {
            int o   = tid + i*256;
            int g   = o >> 8;
            int rem = o & 255;
            int l   = rem >> 3;
            int j   = rem & 7;
            float s = 0.f;
            #pragma unroll
            for (int w = 0; w < 8; w++)
                s += red[((w*2 + g)*32 + l)*9 + j];
            int b   = g*32 + l;
            int col = j0 + j;
            long idx = (long)b*HID + col;
            float hv = tanhf(s + Xt[idx]);
            Ht[idx] = hv;
            __half hi = __float2half_rn(hv);
            HhT[idx] = hi;
            HlT[idx] = __float2half_rn(hv - __half2float(hi));
        }

        __threadfence();
        __syncthreads();
        if (tid == 0) {
            atomicAdd(&g_cnt[t], 1u);
            while (*((volatile unsigned*)&g_cnt[t]) < (unsigned)RNB) {
                __nanosleep(40);
            }
            if (blockIdx.x == 0)
                atomicExch(&g_cnt[(t + 126) & 127], 0u);
        }
        __syncthreads();
        __threadfence();
    }
}

// ===========================================================================
// One merged prep kernel: all weight/embedding fp16 conversions.
// ===========================================================================
#define N_EMBV (VOCAB*EMB)
#define N_W0X  (HID*EMB)
#define N_W1X  (HID*HID)
#define N_WO   (VOCAB*HID)
#define N_PREP (N_EMBV + N_W0X + N_W1X + N_WO)

__global__ void prep_weights(const float* __restrict__ emb, const float* __restrict__ W0x,
                             const float* __restrict__ W1x, const float* __restrict__ Wout,
                             __half* __restrict__ EmbH, __half* __restrict__ EmbL,
                             __half* __restrict__ W0xH, __half* __restrict__ W0xL,
                             __half* __restrict__ W1xH, __half* __restrict__ W1xL,
                             __half* __restrict__ WoH)
{
    long i = (long)blockIdx.x * blockDim.x + threadIdx.x;
    if (i < N_EMBV) {
        float x = emb[i];
        __half h = __float2half_rn(x);
        EmbH[i] = h;
        EmbL[i] = __float2half_rn(x - __half2float(h));
    } else if (i < N_EMBV + N_W0X) {
        long k = i - N_EMBV;
        float x = W0x[k];
        __half h = __float2half_rn(x);
        W0xH[k] = h;
        W0xL[k] = __float2half_rn(x - __half2float(h));
    } else if (i < N_EMBV + N_W0X + N_W1X) {
        long k = i - N_EMBV - N_W0X;
        float x = W1x[k];
        __half h = __float2half_rn(x);
        W1xH[k] = h;
        W1xL[k] = __float2half_rn(x - __half2float(h));
    } else if (i < N_PREP) {
        long k = i - N_EMBV - N_W0X - N_W1X;
        WoH[k] = __float2half_rn(Wout[k]);
    }
}

// ---------------------------------------------------------------------------
__global__ void copy_tail(float* __restrict__ dst)
{
    int i = blockIdx.x * blockDim.x + threadIdx.x;
    if (i < STEP)          dst[i] = g_H0[(long)(SEQ - 1) * STEP + i];
    else if (i < 2 * STEP) dst[i] = g_H1[(long)(SEQ - 1) * STEP + (i - STEP)];
}

// ---------------------------------------------------------------------------
extern "C" void kernel_launch(void* const* d_in, const int* in_sizes, int n_in,
                              void* d_out, int out_size)
{
    const int*   tok    = (const int*)  d_in[0];
    const float* hidden = (const float*)d_in[1];
    const float* emb    = (const float*)d_in[2];
    const float* W0x    = (const float*)d_in[3];
    const float* W0h    = (const float*)d_in[4];
    const float* b0     = (const float*)d_in[5];
    const float* W1x    = (const float*)d_in[6];
    const float* W1h    = (const float*)d_in[7];
    const float* b1     = (const float*)d_in[8];
    const float* Wout   = (const float*)d_in[9];
    const float* bout   = (const float*)d_in[10];
    float* out = (float*)d_out;

    float *X0, *H0, *X1, *H1;
    __half *EmbH, *EmbL, *W0xH, *W0xL, *W1xH, *W1xL, *WoH;
    __half *A0H, *A0L, *A1H, *A1L;
    cudaGetSymbolAddress((void**)&X0, g_X0);
    cudaGetSymbolAddress((void**)&H0, g_H0);
    cudaGetSymbolAddress((void**)&X1, g_X1);
    cudaGetSymbolAddress((void**)&H1, g_H1);
    cudaGetSymbolAddress((void**)&EmbH, g_EmbH);
    cudaGetSymbolAddress((void**)&EmbL, g_EmbL);
    cudaGetSymbolAddress((void**)&W0xH, g_W0xH);
    cudaGetSymbolAddress((void**)&W0xL, g_W0xL);
    cudaGetSymbolAddress((void**)&W1xH, g_W1xH);
    cudaGetSymbolAddress((void**)&W1xL, g_W1xL);
    cudaGetSymbolAddress((void**)&WoH, g_WoH);
    cudaGetSymbolAddress((void**)&A0H, g_A0H);
    cudaGetSymbolAddress((void**)&A0L, g_A0L);
    cudaGetSymbolAddress((void**)&A1H, g_A1H);
    cudaGetSymbolAddress((void**)&A1L, g_A1L);

    static bool attr_set = false;
    if (!attr_set) {
        cudaFuncSetAttribute(rnn_layer,
                             cudaFuncAttributeMaxDynamicSharedMemorySize, SM_BYTES);
        cudaFuncSetAttribute(mma_gemm<true, 3, 2>,
                             cudaFuncAttributeMaxDynamicSharedMemorySize, 2*4*TILE_B);
        cudaFuncSetAttribute(mma_gemm<false, 3, 2>,
                             cudaFuncAttributeMaxDynamicSharedMemorySize, 2*4*TILE_B);
        cudaFuncSetAttribute(mma_gemm<false, 2, 3>,
                             cudaFuncAttributeMaxDynamicSharedMemorySize, 3*3*TILE_B);
        attr_set = true;
    }

    // Prep: all weight/embedding conversions in one launch
    prep_weights<<<(N_PREP + 255)/256, 256>>>(emb, W0x, W1x, Wout,
        EmbH, EmbL, W0xH, W0xL, W1xH, W1xL, WoH);

    // Phase A: X0 = emb[tok] @ W0x^T + b0   (3-term, gathered, 2-stage)
    mma_gemm<true, 3, 2><<<dim3(HID/128, MB/128), 256, 2*4*TILE_B>>>(
        EmbH, EmbL, tok, W0xH, W0xL, b0, X0, MB, HID, EMB);

    // Phase B: layer-0 recurrence (emits H0 + fp16 splits)
    rnn_layer<<<RNB, RNT, SM_BYTES>>>(hidden, W0h, X0, H0, A0H, A0L);

    // Phase C: X1 = H0 @ W1x^T + b1   (3-term, 2-stage)
    mma_gemm<false, 3, 2><<<dim3(HID/128, MB/128), 256, 2*4*TILE_B>>>(
        A0H, A0L, nullptr, W1xH, W1xL, b1, X1, MB, HID, HID);

    // Phase D: layer-1 recurrence (emits H1 + fp16 splits)
    rnn_layer<<<RNB, RNT, SM_BYTES>>>(hidden + STEP, W1h, X1, H1, A1H, A1L);

    // Phase E: logits = H1 @ Wout^T + bout   (2-term, 3-stage pipeline)
    mma_gemm<false, 2, 3><<<dim3((VOCAB + 127)/128, MB/128), 256, 3*3*TILE_B>>>(
        A1H, A1L, nullptr, WoH, nullptr, bout, out, MB, VOCAB, HID);

    // Tail
    copy_tail<<<(2*STEP + 255)/256, 256>>>(out + (long)SEQ * BATCH * VOCAB);
}

// round 11
// speedup vs baseline: 2.5945x; 1.0877x over previous
#include <cuda_runtime.h>
#include <cuda_fp16.h>
#include <cstdint>

// Problem constants
#define SEQ    128
#define BATCH  64
#define EMB    512
#define HID    1024
#define VOCAB  10000
#define MB     (SEQ*BATCH)        // 8192 rows when time-batched
#define STEP   (BATCH*HID)        // 65536 floats per timestep slab

// Scratch (device globals)
__device__ float g_X0[MB*HID];
__device__ float g_H0[MB*HID];
__device__ float g_X1[MB*HID];
__device__ float g_H1[MB*HID];
__device__ unsigned g_cnt[128];
// fp16 split operands for tensor-core GEMMs
__device__ __half g_EmbH[VOCAB*EMB], g_EmbL[VOCAB*EMB];
__device__ __half g_W0xH[HID*EMB],   g_W0xL[HID*EMB];
__device__ __half g_W1xH[HID*HID],   g_W1xL[HID*HID];
__device__ __half g_WoH[VOCAB*HID];                      // single fp16 (2-term path)
__device__ __half g_A0H[MB*HID],     g_A0L[MB*HID];      // H0 splits
__device__ __half g_A1H[MB*HID],     g_A1L[MB*HID];      // H1 splits

#define GPITCH 80                     // bytes per smem tile row
#define TILE_B (128*GPITCH)           // 10240 B per 128-row tile

__device__ __forceinline__ void ldsm4(uint32_t* r, uint32_t addr) {
    asm volatile("ldmatrix.sync.aligned.m8n8.x4.shared.b16 {%0,%1,%2,%3}, [%4];"
                 : "=r"(r[0]), "=r"(r[1]), "=r"(r[2]), "=r"(r[3]) : "r"(addr));
}
__device__ __forceinline__ void mma16816(float* d, const uint32_t* a, uint32_t b0, uint32_t b1) {
    asm volatile(
        "mma.sync.aligned.m16n8k16.row.col.f32.f16.f16.f32 "
        "{%0,%1,%2,%3}, {%4,%5,%6,%7}, {%8,%9}, {%0,%1,%2,%3};"
        : "+f"(d[0]), "+f"(d[1]), "+f"(d[2]), "+f"(d[3])
        : "r"(a[0]), "r"(a[1]), "r"(a[2]), "r"(a[3]), "r"(b0), "r"(b1));
}
__device__ __forceinline__ void cpa16(uint32_t dst, const void* src) {
    asm volatile("cp.async.cg.shared.global [%0], [%1], 16;" :: "r"(dst), "l"(src));
}
__device__ __forceinline__ void cpa16z(uint32_t dst, const void* src, uint32_t sz) {
    asm volatile("cp.async.cg.shared.global [%0], [%1], 16, %2;" :: "r"(dst), "l"(src), "r"(sz));
}

// ===========================================================================
// 3-term GEMM (phases A, C): tile 128x128, BK=32, 8 warps (2m x 4n),
// 2-stage pipeline. Term-major MMA order (acc reuse distance 16).
// ===========================================================================
template<bool GATHER>
__global__ __launch_bounds__(256, 2)
void mma_gemm3(const __half* __restrict__ Ah, const __half* __restrict__ Al,
               const int* __restrict__ rows,
               const __half* __restrict__ Bh, const __half* __restrict__ Bl,
               const float* __restrict__ bias, float* __restrict__ C,
               int M, int N, int K)
{
    constexpr uint32_t BUF_B = 4 * TILE_B;
    extern __shared__ char smem[];
    const int tid  = threadIdx.x;
    const int lane = tid & 31;
    const int wid  = tid >> 5;
    const int mw   = wid >> 2;        // 0..1
    const int nw   = wid & 3;         // 0..3
    const int m0   = blockIdx.y * 128;
    const int n0   = blockIdx.x * 128;

    const uint32_t sbase = (uint32_t)__cvta_generic_to_shared(smem);

    float acc[4][4][4];
    #pragma unroll
    for (int f = 0; f < 4; f++)
        #pragma unroll
        for (int g = 0; g < 4; g++)
            #pragma unroll
            for (int e = 0; e < 4; e++) acc[f][g][e] = 0.f;

    const int nchunks = K >> 5;

    auto load_chunk = [&](int kt, int b) {
        const uint32_t tb = sbase + (uint32_t)b * BUF_B;
        #pragma unroll
        for (int i = 0; i < 2; i++) {
            int l  = tid + i * 256;        // 0..511
            int r  = l & 127;
            int cb = l >> 7;               // 0..3
            uint32_t doff = (uint32_t)(r * GPITCH + cb * 16);
            long ar = GATHER ? (long)rows[m0 + r] : (long)(m0 + r);
            cpa16(tb + doff,          Ah + ar * K + kt + cb * 8);
            cpa16(tb + TILE_B + doff, Al + ar * K + kt + cb * 8);
            int nr = n0 + r;
            uint32_t sz = (nr < N) ? 16u : 0u;
            long br = (nr < N) ? (long)nr : (long)(N - 1);
            cpa16z(tb + 2*TILE_B + doff, Bh + br * K + kt + cb * 8, sz);
            cpa16z(tb + 3*TILE_B + doff, Bl + br * K + kt + cb * 8, sz);
        }
        asm volatile("cp.async.commit_group;");
    };

    load_chunk(0, 0);

    #pragma unroll 1
    for (int c = 0; c < nchunks; c++) {
        asm volatile("cp.async.wait_group 0;");
        __syncthreads();
        if (c + 1 < nchunks)
            load_chunk((c + 1) << 5, (c + 1) & 1);

        const uint32_t tb = sbase + (uint32_t)(c & 1) * BUF_B;

        #pragma unroll
        for (int s = 0; s < 2; s++) {
            const uint32_t abase = tb
                + (uint32_t)((mw*64 + (lane & 15)) * GPITCH)
                + (uint32_t)(s*32 + (lane >> 4)*16);
            uint32_t bb[2];
            #pragma unroll
            for (int p = 0; p < 2; p++) {
                uint32_t brow = (uint32_t)(nw*32 + p*16 + (lane & 7) + ((lane >> 4) & 1)*8);
                bb[p] = tb + 2*TILE_B + brow * GPITCH
                      + (uint32_t)(s*32 + ((lane >> 3) & 1)*16);
            }

            uint32_t bh0[4], bh1[4], bl0[4], bl1[4];
            ldsm4(bh0, bb[0]);
            ldsm4(bh1, bb[1]);
            ldsm4(bl0, bb[0] + TILE_B);
            ldsm4(bl1, bb[1] + TILE_B);

            uint32_t aF[4][4];
            #pragma unroll
            for (int f = 0; f < 4; f++)
                ldsm4(aF[f], abase + (uint32_t)(f * 16 * GPITCH));

            // Term 1: Ah x Bh
            #pragma unroll
            for (int f = 0; f < 4; f++) {
                mma16816(acc[f][0], aF[f], bh0[0], bh0[1]);
                mma16816(acc[f][1], aF[f], bh0[2], bh0[3]);
                mma16816(acc[f][2], aF[f], bh1[0], bh1[1]);
                mma16816(acc[f][3], aF[f], bh1[2], bh1[3]);
            }
            // Term 2: Ah x Bl
            #pragma unroll
            for (int f = 0; f < 4; f++) {
                mma16816(acc[f][0], aF[f], bl0[0], bl0[1]);
                mma16816(acc[f][1], aF[f], bl0[2], bl0[3]);
                mma16816(acc[f][2], aF[f], bl1[0], bl1[1]);
                mma16816(acc[f][3], aF[f], bl1[2], bl1[3]);
            }
            // Term 3: Al x Bh
            #pragma unroll
            for (int f = 0; f < 4; f++)
                ldsm4(aF[f], abase + TILE_B + (uint32_t)(f * 16 * GPITCH));
            #pragma unroll
            for (int f = 0; f < 4; f++) {
                mma16816(acc[f][0], aF[f], bh0[0], bh0[1]);
                mma16816(acc[f][1], aF[f], bh0[2], bh0[3]);
                mma16816(acc[f][2], aF[f], bh1[0], bh1[1]);
                mma16816(acc[f][3], aF[f], bh1[2], bh1[3]);
            }
        }
    }

    #pragma unroll
    for (int f = 0; f < 4; f++) {
        long row = m0 + mw*64 + f*16 + (lane >> 2);
        #pragma unroll
        for (int g = 0; g < 4; g++) {
            int col = n0 + nw*32 + g*8 + (lane & 3)*2;
            if (col < N) {
                float bx = bias[col], by = bias[col + 1];
                float2 v0 = make_float2(acc[f][g][0] + bx, acc[f][g][1] + by);
                float2 v1 = make_float2(acc[f][g][2] + bx, acc[f][g][3] + by);
                *reinterpret_cast<float2*>(C + row * N + col)       = v0;
                *reinterpret_cast<float2*>(C + (row + 8) * N + col) = v1;
            }
        }
    }
}

// ===========================================================================
// 2-term GEMM (phase E): CTA tile 64x128, 256 threads, warp tile 32x32
// (2m x 4n warps), acc = 32 regs/thread -> 3 CTAs/SM (24 warps).
// 3-stage cp.async pipeline. Stage = Ah(64) + Al(64) + Bh(128) rows.
// Loader: 4 x 16B transfers per 64B row (1024 transfers = 4 loops).
// ===========================================================================
#define ETILE_A (64*GPITCH)           // 5120 B
#define ESTAGE  (2*ETILE_A + TILE_B)  // 20480 B
#define ESTAGES 3

__global__ __launch_bounds__(256, 3)
void mma_gemm2(const __half* __restrict__ Ah, const __half* __restrict__ Al,
               const __half* __restrict__ Bh,
               const float* __restrict__ bias, float* __restrict__ C,
               int M, int N, int K)
{
    extern __shared__ char smem[];
    const int tid  = threadIdx.x;
    const int lane = tid & 31;
    const int wid  = tid >> 5;
    const int mw   = wid >> 2;        // 0..1 (m-warp)
    const int nw   = wid & 3;         // 0..3 (n-warp)
    const int m0   = blockIdx.y * 64;
    const int n0   = blockIdx.x * 128;

    const uint32_t sbase = (uint32_t)__cvta_generic_to_shared(smem);

    float acc[2][4][4];
    #pragma unroll
    for (int f = 0; f < 2; f++)
        #pragma unroll
        for (int g = 0; g < 4; g++)
            #pragma unroll
            for (int e = 0; e < 4; e++) acc[f][g][e] = 0.f;

    const int nchunks = K >> 5;

    // 1024 16B-transfers per stage: [0,256) Ah, [256,512) Al, [512,1024) Bh
    auto load_chunk = [&](int kt, int b) {
        const uint32_t tb = sbase + (uint32_t)b * ESTAGE;
        #pragma unroll
        for (int i = 0; i < 4; i++) {
            int idx = tid + i * 256;       // 0..1023
            if (idx < 256) {
                int r = idx >> 2, cb = idx & 3;
                cpa16(tb + (uint32_t)(r * GPITCH + cb * 16),
                      Ah + (long)(m0 + r) * K + kt + cb * 8);
            } else if (idx < 512) {
                int j = idx - 256;
                int r = j >> 2, cb = j & 3;
                cpa16(tb + ETILE_A + (uint32_t)(r * GPITCH + cb * 16),
                      Al + (long)(m0 + r) * K + kt + cb * 8);
            } else {
                int j = idx - 512;             // 0..511
                int r = j >> 2, cb = j & 3;
                int nr = n0 + r;
                uint32_t sz = (nr < N) ? 16u : 0u;
                long br = (nr < N) ? (long)nr : (long)(N - 1);
                cpa16z(tb + 2*ETILE_A + (uint32_t)(r * GPITCH + cb * 16),
                       Bh + br * K + kt + cb * 8, sz);
            }
        }
        asm volatile("cp.async.commit_group;");
    };

    #pragma unroll
    for (int s = 0; s < ESTAGES - 1; s++)
        load_chunk(s << 5, s);

    #pragma unroll 1
    for (int c = 0; c < nchunks; c++) {
        if (c + ESTAGES - 1 < nchunks) {
            asm volatile("cp.async.wait_group %0;" :: "n"(ESTAGES - 2));
            __syncthreads();
            load_chunk((c + ESTAGES - 1) << 5, (c + ESTAGES - 1) % ESTAGES);
        } else {
            asm volatile("cp.async.wait_group 0;");
            __syncthreads();
        }

        const uint32_t tb = sbase + (uint32_t)(c % ESTAGES) * ESTAGE;

        #pragma unroll
        for (int s = 0; s < 2; s++) {
            const uint32_t abase = tb
                + (uint32_t)((mw*32 + (lane & 15)) * GPITCH)
                + (uint32_t)(s*32 + (lane >> 4)*16);
            uint32_t bb[2];
            #pragma unroll
            for (int p = 0; p < 2; p++) {
                uint32_t brow = (uint32_t)(nw*32 + p*16 + (lane & 7) + ((lane >> 4) & 1)*8);
                bb[p] = tb + 2*ETILE_A + brow * GPITCH
                      + (uint32_t)(s*32 + ((lane >> 3) & 1)*16);
            }

            uint32_t b0[4], b1[4];
            ldsm4(b0, bb[0]);
            ldsm4(b1, bb[1]);

            uint32_t aF[2][4];
            // Term 1: Ah
            ldsm4(aF[0], abase);
            ldsm4(aF[1], abase + (uint32_t)(16 * GPITCH));
            #pragma unroll
            for (int f = 0; f < 2; f++) {
                mma16816(acc[f][0], aF[f], b0[0], b0[1]);
                mma16816(acc[f][1], aF[f], b0[2], b0[3]);
                mma16816(acc[f][2], aF[f], b1[0], b1[1]);
                mma16816(acc[f][3], aF[f], b1[2], b1[3]);
            }
            // Term 2: Al
            ldsm4(aF[0], abase + ETILE_A);
            ldsm4(aF[1], abase + ETILE_A + (uint32_t)(16 * GPITCH));
            #pragma unroll
            for (int f = 0; f < 2; f++) {
                mma16816(acc[f][0], aF[f], b0[0], b0[1]);
                mma16816(acc[f][1], aF[f], b0[2], b0[3]);
                mma16816(acc[f][2], aF[f], b1[0], b1[1]);
                mma16816(acc[f][3], aF[f], b1[2], b1[3]);
            }
        }
    }

    #pragma unroll
    for (int f = 0; f < 2; f++) {
        long row = m0 + mw*32 + f*16 + (lane >> 2);
        #pragma unroll
        for (int g = 0; g < 4; g++) {
            int col = n0 + nw*32 + g*8 + (lane & 3)*2;
            if (col < N) {
                float bx = bias[col], by = bias[col + 1];
                float2 v0 = make_float2(acc[f][g][0] + bx, acc[f][g][1] + by);
                float2 v1 = make_float2(acc[f][g][2] + bx, acc[f][g][3] + by);
                *reinterpret_cast<float2*>(C + row * N + col)       = v0;
                *reinterpret_cast<float2*>(C + (row + 8) * N + col) = v1;
            }
        }
    }
}

// ===========================================================================
// Persistent recurrence kernel (phases B, D). 256 threads, 8 k-split warps.
// Epilogue emits H[t] fp32 + fp16 hi/lo splits.
// ===========================================================================
#define TK   128
#define HSP  65
#define RNB  128
#define RNT  256
#define SM_WS   0
#define SM_HS   (8*1024)
#define SM_RED  (SM_HS + 2*TK*HSP)
#define SM_BYTES  131072

__global__ __launch_bounds__(RNT, 1)
void rnn_layer(const float* __restrict__ h0init,
               const float* __restrict__ W,
               const float* __restrict__ X,
               float* __restrict__ H,
               __half* __restrict__ Hh,
               __half* __restrict__ Hl)
{
    extern __shared__ float sm[];
    float* Ws  = sm + SM_WS;
    float* hs  = sm + SM_HS;
    float* red = sm + SM_RED;

    const int tid  = threadIdx.x;
    const int lane = tid & 31;
    const int warp = tid >> 5;
    const int j0   = blockIdx.x * 8;

    for (int i = tid; i < 8*1024/4; i += RNT) {
        int j  = i >> 8;
        int kq = i & 255;
        float4 v = *reinterpret_cast<const float4*>(W + (long)(j0 + j) * HID + kq * 4);
        *reinterpret_cast<float4*>(Ws + j*1024 + kq*4) = v;
    }
    __syncthreads();

    const uint32_t hs_s = (uint32_t)__cvta_generic_to_shared(hs);
    const int lc = tid >> 1;
    const int lh = (tid & 1) * 32;

    for (int t = 0; t < SEQ; t++) {
        const float* hprev = (t == 0) ? h0init : (H + (long)(t-1) * STEP);

        float acc0[8], acc1[8];
        #pragma unroll
        for (int j = 0; j < 8; j++) { acc0[j] = 0.f; acc1[j] = 0.f; }

        {
            const float* src = hprev + (long)lh * HID + lc;
            uint32_t dst = hs_s + (uint32_t)(lc * HSP + lh) * 4u;
            #pragma unroll 16
            for (int b = 0; b < 32; b++)
                asm volatile("cp.async.ca.shared.global [%0], [%1], 4;"
                             :: "r"(dst + b*4u), "l"(src + (long)b*HID));
            asm volatile("cp.async.commit_group;");
        }

        int buf = 0;
        #pragma unroll 1
        for (int tile = 0; tile < 8; tile++) {
            if (tile < 7) {
                const float* src = hprev + (long)lh * HID + (tile+1)*TK + lc;
                uint32_t dst = hs_s + (uint32_t)(((buf^1)*TK + lc) * HSP + lh) * 4u;
                #pragma unroll 16
                for (int b = 0; b < 32; b++)
                    asm volatile("cp.async.ca.shared.global [%0], [%1], 4;"
                                 :: "r"(dst + b*4u), "l"(src + (long)b*HID));
                asm volatile("cp.async.commit_group;");
                asm volatile("cp.async.wait_group 1;");
            } else {
                asm volatile("cp.async.wait_group 0;");
            }
            __syncthreads();

            const float* hb = hs + buf*TK*HSP;
            const int kwarp = warp * 16;
            #pragma unroll
            for (int q = 0; q < 4; q++) {
                const int kl = kwarp + q*4;
                float h0[4], h1[4];
                #pragma unroll
                for (int i = 0; i < 4; i++) {
                    h0[i] = hb[(kl+i)*HSP + lane];
                    h1[i] = hb[(kl+i)*HSP + lane + 32];
                }
                const int kg = tile*TK + kl;
                #pragma unroll
                for (int j = 0; j < 8; j++) {
                    float4 w = *reinterpret_cast<const float4*>(Ws + j*1024 + kg);
                    acc0[j] = fmaf(h0[0], w.x, acc0[j]);
                    acc0[j] = fmaf(h0[1], w.y, acc0[j]);
                    acc0[j] = fmaf(h0[2], w.z, acc0[j]);
                    acc0[j] = fmaf(h0[3], w.w, acc0[j]);
                    acc1[j] = fmaf(h1[0], w.x, acc1[j]);
                    acc1[j] = fmaf(h1[1], w.y, acc1[j]);
                    acc1[j] = fmaf(h1[2], w.z, acc1[j]);
                    acc1[j] = fmaf(h1[3], w.w, acc1[j]);
                }
            }
            __syncthreads();
            buf ^= 1;
        }

        #pragma unroll
        for (int j = 0; j < 8; j++) {
            red[((warp*2 + 0)*32 + lane)*9 + j] = acc0[j];
            red[((warp*2 + 1)*32 + lane)*9 + j] = acc1[j];
        }
        __syncthreads();

        const float* Xt = X + (long)t * STEP;
        float*       Ht = H + (long)t * STEP;
        __half* HhT = Hh + (long)t * STEP;
        __half* HlT = Hl + (long)t * STEP;
        #pragma unroll
        for (int i = 0; i < 2; i++) {
            int o   = tid + i*256;
            int g   = o >> 8;
            int rem = o & 255;
            int l   = rem >> 3;
            int j   = rem & 7;
            float s = 0.f;
            #pragma unroll
            for (int w = 0; w < 8; w++)
                s += red[((w*2 + g)*32 + l)*9 + j];
            int b   = g*32 + l;
            int col = j0 + j;
            long idx = (long)b*HID + col;
            float hv = tanhf(s + Xt[idx]);
            Ht[idx] = hv;
            __half hi = __float2half_rn(hv);
            HhT[idx] = hi;
            HlT[idx] = __float2half_rn(hv - __half2float(hi));
        }

        __threadfence();
        __syncthreads();
        if (tid == 0) {
            atomicAdd(&g_cnt[t], 1u);
            while (*((volatile unsigned*)&g_cnt[t]) < (unsigned)RNB) {
                __nanosleep(40);
            }
            if (blockIdx.x == 0)
                atomicExch(&g_cnt[(t + 126) & 127], 0u);
        }
        __syncthreads();
        __threadfence();
    }
}

// ===========================================================================
// One merged prep kernel: all weight/embedding fp16 conversions.
// ===========================================================================
#define N_EMBV (VOCAB*EMB)
#define N_W0X  (HID*EMB)
#define N_W1X  (HID*HID)
#define N_WO   (VOCAB*HID)
#define N_PREP (N_EMBV + N_W0X + N_W1X + N_WO)

__global__ void prep_weights(const float* __restrict__ emb, const float* __restrict__ W0x,
                             const float* __restrict__ W1x, const float* __restrict__ Wout,
                             __half* __restrict__ EmbH, __half* __restrict__ EmbL,
                             __half* __restrict__ W0xH, __half* __restrict__ W0xL,
                             __half* __restrict__ W1xH, __half* __restrict__ W1xL,
                             __half* __restrict__ WoH)
{
    long i = (long)blockIdx.x * blockDim.x + threadIdx.x;
    if (i < N_EMBV) {
        float x = emb[i];
        __half h = __float2half_rn(x);
        EmbH[i] = h;
        EmbL[i] = __float2half_rn(x - __half2float(h));
    } else if (i < N_EMBV + N_W0X) {
        long k = i - N_EMBV;
        float x = W0x[k];
        __half h = __float2half_rn(x);
        W0xH[k] = h;
        W0xL[k] = __float2half_rn(x - __half2float(h));
    } else if (i < N_EMBV + N_W0X + N_W1X) {
        long k = i - N_EMBV - N_W0X;
        float x = W1x[k];
        __half h = __float2half_rn(x);
        W1xH[k] = h;
        W1xL[k] = __float2half_rn(x - __half2float(h));
    } else if (i < N_PREP) {
        long k = i - N_EMBV - N_W0X - N_W1X;
        WoH[k] = __float2half_rn(Wout[k]);
    }
}

// ---------------------------------------------------------------------------
__global__ void copy_tail(float* __restrict__ dst)
{
    int i = blockIdx.x * blockDim.x + threadIdx.x;
    if (i < STEP)          dst[i] = g_H0[(long)(SEQ - 1) * STEP + i];
    else if (i < 2 * STEP) dst[i] = g_H1[(long)(SEQ - 1) * STEP + (i - STEP)];
}

// ---------------------------------------------------------------------------
extern "C" void kernel_launch(void* const* d_in, const int* in_sizes, int n_in,
                              void* d_out, int out_size)
{
    const int*   tok    = (const int*)  d_in[0];
    const float* hidden = (const float*)d_in[1];
    const float* emb    = (const float*)d_in[2];
    const float* W0x    = (const float*)d_in[3];
    const float* W0h    = (const float*)d_in[4];
    const float* b0     = (const float*)d_in[5];
    const float* W1x    = (const float*)d_in[6];
    const float* W1h    = (const float*)d_in[7];
    const float* b1     = (const float*)d_in[8];
    const float* Wout   = (const float*)d_in[9];
    const float* bout   = (const float*)d_in[10];
    float* out = (float*)d_out;

    float *X0, *H0, *X1, *H1;
    __half *EmbH, *EmbL, *W0xH, *W0xL, *W1xH, *W1xL, *WoH;
    __half *A0H, *A0L, *A1H, *A1L;
    cudaGetSymbolAddress((void**)&X0, g_X0);
    cudaGetSymbolAddress((void**)&H0, g_H0);
    cudaGetSymbolAddress((void**)&X1, g_X1);
    cudaGetSymbolAddress((void**)&H1, g_H1);
    cudaGetSymbolAddress((void**)&EmbH, g_EmbH);
    cudaGetSymbolAddress((void**)&EmbL, g_EmbL);
    cudaGetSymbolAddress((void**)&W0xH, g_W0xH);
    cudaGetSymbolAddress((void**)&W0xL, g_W0xL);
    cudaGetSymbolAddress((void**)&W1xH, g_W1xH);
    cudaGetSymbolAddress((void**)&W1xL, g_W1xL);
    cudaGetSymbolAddress((void**)&WoH, g_WoH);
    cudaGetSymbolAddress((void**)&A0H, g_A0H);
    cudaGetSymbolAddress((void**)&A0L, g_A0L);
    cudaGetSymbolAddress((void**)&A1H, g_A1H);
    cudaGetSymbolAddress((void**)&A1L, g_A1L);

    static bool attr_set = false;
    if (!attr_set) {
        cudaFuncSetAttribute(rnn_layer,
                             cudaFuncAttributeMaxDynamicSharedMemorySize, SM_BYTES);
        cudaFuncSetAttribute(mma_gemm3<true>,
                             cudaFuncAttributeMaxDynamicSharedMemorySize, 2*4*TILE_B);
        cudaFuncSetAttribute(mma_gemm3<false>,
                             cudaFuncAttributeMaxDynamicSharedMemorySize, 2*4*TILE_B);
        cudaFuncSetAttribute(mma_gemm2,
                             cudaFuncAttributeMaxDynamicSharedMemorySize, ESTAGES*ESTAGE);
        attr_set = true;
    }

    // Prep: all weight/embedding conversions in one launch
    prep_weights<<<(N_PREP + 255)/256, 256>>>(emb, W0x, W1x, Wout,
        EmbH, EmbL, W0xH, W0xL, W1xH, W1xL, WoH);

    // Phase A: X0 = emb[tok] @ W0x^T + b0   (3-term, gathered)
    mma_gemm3<true><<<dim3(HID/128, MB/128), 256, 2*4*TILE_B>>>(
        EmbH, EmbL, tok, W0xH, W0xL, b0, X0, MB, HID, EMB);

    // Phase B: layer-0 recurrence (emits H0 + fp16 splits)
    rnn_layer<<<RNB, RNT, SM_BYTES>>>(hidden, W0h, X0, H0, A0H, A0L);

    // Phase C: X1 = H0 @ W1x^T + b1   (3-term)
    mma_gemm3<false><<<dim3(HID/128, MB/128), 256, 2*4*TILE_B>>>(
        A0H, A0L, nullptr, W1xH, W1xL, b1, X1, MB, HID, HID);

    // Phase D: layer-1 recurrence (emits H1 + fp16 splits)
    rnn_layer<<<RNB, RNT, SM_BYTES>>>(hidden + STEP, W1h, X1, H1, A1H, A1L);

    // Phase E: logits = H1 @ Wout^T + bout   (2-term, 64x128 tiles, 3 CTA/SM)
    mma_gemm2<<<dim3((VOCAB + 127)/128, MB/64), 256, ESTAGES*ESTAGE>>>(
        A1H, A1L, WoH, bout, out, MB, VOCAB, HID);

    // Tail
    copy_tail<<<(2*STEP + 255)/256, 256>>>(out + (long)SEQ * BATCH * VOCAB);
}

// round 12
// speedup vs baseline: 2.8188x; 1.0865x over previous
#include <cuda_runtime.h>
#include <cuda_fp16.h>
#include <cstdint>

// Problem constants
#define SEQ    128
#define BATCH  64
#define EMB    512
#define HID    1024
#define VOCAB  10000
#define MB     (SEQ*BATCH)        // 8192 rows when time-batched
#define STEP   (BATCH*HID)        // 65536 floats per timestep slab

// Scratch (device globals)
__device__ float g_X0[MB*HID];
__device__ float g_H0[MB*HID];
__device__ float g_X1[MB*HID];
__device__ float g_H1[MB*HID];
__device__ unsigned g_cnt[128];
// fp16 split operands for tensor-core GEMMs
__device__ __half g_EmbH[VOCAB*EMB], g_EmbL[VOCAB*EMB];
__device__ __half g_W0xH[HID*EMB],   g_W0xL[HID*EMB];
__device__ __half g_W1xH[HID*HID],   g_W1xL[HID*HID];
__device__ __half g_WoH[VOCAB*HID];                      // single fp16 (1-term path)
__device__ __half g_A0H[MB*HID],     g_A0L[MB*HID];      // H0 splits
__device__ __half g_A1H[MB*HID],     g_A1L[MB*HID];      // H1 splits

#define GPITCH 80                     // bytes per smem tile row
#define TILE_B (128*GPITCH)           // 10240 B per 128-row tile

__device__ __forceinline__ void ldsm4(uint32_t* r, uint32_t addr) {
    asm volatile("ldmatrix.sync.aligned.m8n8.x4.shared.b16 {%0,%1,%2,%3}, [%4];"
                 : "=r"(r[0]), "=r"(r[1]), "=r"(r[2]), "=r"(r[3]) : "r"(addr));
}
__device__ __forceinline__ void mma16816(float* d, const uint32_t* a, uint32_t b0, uint32_t b1) {
    asm volatile(
        "mma.sync.aligned.m16n8k16.row.col.f32.f16.f16.f32 "
        "{%0,%1,%2,%3}, {%4,%5,%6,%7}, {%8,%9}, {%0,%1,%2,%3};"
        : "+f"(d[0]), "+f"(d[1]), "+f"(d[2]), "+f"(d[3])
        : "r"(a[0]), "r"(a[1]), "r"(a[2]), "r"(a[3]), "r"(b0), "r"(b1));
}
__device__ __forceinline__ void cpa16(uint32_t dst, const void* src) {
    asm volatile("cp.async.cg.shared.global [%0], [%1], 16;" :: "r"(dst), "l"(src));
}
__device__ __forceinline__ void cpa16z(uint32_t dst, const void* src, uint32_t sz) {
    asm volatile("cp.async.cg.shared.global [%0], [%1], 16, %2;" :: "r"(dst), "l"(src), "r"(sz));
}

// ===========================================================================
// 3-term GEMM (phases A, C): tile 128x128, BK=32, 8 warps (2m x 4n),
// 2-stage pipeline. Term-major MMA order.
// ===========================================================================
template<bool GATHER>
__global__ __launch_bounds__(256, 2)
void mma_gemm3(const __half* __restrict__ Ah, const __half* __restrict__ Al,
               const int* __restrict__ rows,
               const __half* __restrict__ Bh, const __half* __restrict__ Bl,
               const float* __restrict__ bias, float* __restrict__ C,
               int M, int N, int K)
{
    constexpr uint32_t BUF_B = 4 * TILE_B;
    extern __shared__ char smem[];
    const int tid  = threadIdx.x;
    const int lane = tid & 31;
    const int wid  = tid >> 5;
    const int mw   = wid >> 2;        // 0..1
    const int nw   = wid & 3;         // 0..3
    const int m0   = blockIdx.y * 128;
    const int n0   = blockIdx.x * 128;

    const uint32_t sbase = (uint32_t)__cvta_generic_to_shared(smem);

    float acc[4][4][4];
    #pragma unroll
    for (int f = 0; f < 4; f++)
        #pragma unroll
        for (int g = 0; g < 4; g++)
            #pragma unroll
            for (int e = 0; e < 4; e++) acc[f][g][e] = 0.f;

    const int nchunks = K >> 5;

    auto load_chunk = [&](int kt, int b) {
        const uint32_t tb = sbase + (uint32_t)b * BUF_B;
        #pragma unroll
        for (int i = 0; i < 2; i++) {
            int l  = tid + i * 256;        // 0..511
            int r  = l & 127;
            int cb = l >> 7;               // 0..3
            uint32_t doff = (uint32_t)(r * GPITCH + cb * 16);
            long ar = GATHER ? (long)rows[m0 + r] : (long)(m0 + r);
            cpa16(tb + doff,          Ah + ar * K + kt + cb * 8);
            cpa16(tb + TILE_B + doff, Al + ar * K + kt + cb * 8);
            int nr = n0 + r;
            uint32_t sz = (nr < N) ? 16u : 0u;
            long br = (nr < N) ? (long)nr : (long)(N - 1);
            cpa16z(tb + 2*TILE_B + doff, Bh + br * K + kt + cb * 8, sz);
            cpa16z(tb + 3*TILE_B + doff, Bl + br * K + kt + cb * 8, sz);
        }
        asm volatile("cp.async.commit_group;");
    };

    load_chunk(0, 0);

    #pragma unroll 1
    for (int c = 0; c < nchunks; c++) {
        asm volatile("cp.async.wait_group 0;");
        __syncthreads();
        if (c + 1 < nchunks)
            load_chunk((c + 1) << 5, (c + 1) & 1);

        const uint32_t tb = sbase + (uint32_t)(c & 1) * BUF_B;

        #pragma unroll
        for (int s = 0; s < 2; s++) {
            const uint32_t abase = tb
                + (uint32_t)((mw*64 + (lane & 15)) * GPITCH)
                + (uint32_t)(s*32 + (lane >> 4)*16);
            uint32_t bb[2];
            #pragma unroll
            for (int p = 0; p < 2; p++) {
                uint32_t brow = (uint32_t)(nw*32 + p*16 + (lane & 7) + ((lane >> 4) & 1)*8);
                bb[p] = tb + 2*TILE_B + brow * GPITCH
                      + (uint32_t)(s*32 + ((lane >> 3) & 1)*16);
            }

            uint32_t bh0[4], bh1[4], bl0[4], bl1[4];
            ldsm4(bh0, bb[0]);
            ldsm4(bh1, bb[1]);
            ldsm4(bl0, bb[0] + TILE_B);
            ldsm4(bl1, bb[1] + TILE_B);

            uint32_t aF[4][4];
            #pragma unroll
            for (int f = 0; f < 4; f++)
                ldsm4(aF[f], abase + (uint32_t)(f * 16 * GPITCH));

            // Term 1: Ah x Bh
            #pragma unroll
            for (int f = 0; f < 4; f++) {
                mma16816(acc[f][0], aF[f], bh0[0], bh0[1]);
                mma16816(acc[f][1], aF[f], bh0[2], bh0[3]);
                mma16816(acc[f][2], aF[f], bh1[0], bh1[1]);
                mma16816(acc[f][3], aF[f], bh1[2], bh1[3]);
            }
            // Term 2: Ah x Bl
            #pragma unroll
            for (int f = 0; f < 4; f++) {
                mma16816(acc[f][0], aF[f], bl0[0], bl0[1]);
                mma16816(acc[f][1], aF[f], bl0[2], bl0[3]);
                mma16816(acc[f][2], aF[f], bl1[0], bl1[1]);
                mma16816(acc[f][3], aF[f], bl1[2], bl1[3]);
            }
            // Term 3: Al x Bh
            #pragma unroll
            for (int f = 0; f < 4; f++)
                ldsm4(aF[f], abase + TILE_B + (uint32_t)(f * 16 * GPITCH));
            #pragma unroll
            for (int f = 0; f < 4; f++) {
                mma16816(acc[f][0], aF[f], bh0[0], bh0[1]);
                mma16816(acc[f][1], aF[f], bh0[2], bh0[3]);
                mma16816(acc[f][2], aF[f], bh1[0], bh1[1]);
                mma16816(acc[f][3], aF[f], bh1[2], bh1[3]);
            }
        }
    }

    #pragma unroll
    for (int f = 0; f < 4; f++) {
        long row = m0 + mw*64 + f*16 + (lane >> 2);
        #pragma unroll
        for (int g = 0; g < 4; g++) {
            int col = n0 + nw*32 + g*8 + (lane & 3)*2;
            if (col < N) {
                float bx = bias[col], by = bias[col + 1];
                float2 v0 = make_float2(acc[f][g][0] + bx, acc[f][g][1] + by);
                float2 v1 = make_float2(acc[f][g][2] + bx, acc[f][g][3] + by);
                *reinterpret_cast<float2*>(C + row * N + col)       = v0;
                *reinterpret_cast<float2*>(C + (row + 8) * N + col) = v1;
            }
        }
    }
}

// ===========================================================================
// 1-term GEMM (phase E): C = Ah @ Bh^T + bias. CTA tile 64x128, 256 threads,
// warp tile 32x32 (2m x 4n), acc = 32 regs -> 3 CTAs/SM. 4-stage pipeline.
// Stage = Ah(64 rows) + Bh(128 rows) = 15360 B.
// ===========================================================================
#define ETILE_A (64*GPITCH)           // 5120 B
#define ESTAGE  (ETILE_A + TILE_B)    // 15360 B
#define ESTAGES 4

__global__ __launch_bounds__(256, 3)
void mma_gemm1(const __half* __restrict__ Ah,
               const __half* __restrict__ Bh,
               const float* __restrict__ bias, float* __restrict__ C,
               int M, int N, int K)
{
    extern __shared__ char smem[];
    const int tid  = threadIdx.x;
    const int lane = tid & 31;
    const int wid  = tid >> 5;
    const int mw   = wid >> 2;        // 0..1 (m-warp)
    const int nw   = wid & 3;         // 0..3 (n-warp)
    const int m0   = blockIdx.y * 64;
    const int n0   = blockIdx.x * 128;

    const uint32_t sbase = (uint32_t)__cvta_generic_to_shared(smem);

    float acc[2][4][4];
    #pragma unroll
    for (int f = 0; f < 2; f++)
        #pragma unroll
        for (int g = 0; g < 4; g++)
            #pragma unroll
            for (int e = 0; e < 4; e++) acc[f][g][e] = 0.f;

    const int nchunks = K >> 5;

    // 768 16B-transfers per stage: [0,256) Ah, [256,768) Bh
    auto load_chunk = [&](int kt, int b) {
        const uint32_t tb = sbase + (uint32_t)b * ESTAGE;
        #pragma unroll
        for (int i = 0; i < 3; i++) {
            int idx = tid + i * 256;       // 0..767
            if (idx < 256) {
                int r = idx >> 2, cb = idx & 3;
                cpa16(tb + (uint32_t)(r * GPITCH + cb * 16),
                      Ah + (long)(m0 + r) * K + kt + cb * 8);
            } else {
                int j = idx - 256;             // 0..511
                int r = j >> 2, cb = j & 3;
                int nr = n0 + r;
                uint32_t sz = (nr < N) ? 16u : 0u;
                long br = (nr < N) ? (long)nr : (long)(N - 1);
                cpa16z(tb + ETILE_A + (uint32_t)(r * GPITCH + cb * 16),
                       Bh + br * K + kt + cb * 8, sz);
            }
        }
        asm volatile("cp.async.commit_group;");
    };

    #pragma unroll
    for (int s = 0; s < ESTAGES - 1; s++)
        load_chunk(s << 5, s);

    #pragma unroll 1
    for (int c = 0; c < nchunks; c++) {
        if (c + ESTAGES - 1 < nchunks) {
            asm volatile("cp.async.wait_group %0;" :: "n"(ESTAGES - 2));
            __syncthreads();
            load_chunk((c + ESTAGES - 1) << 5, (c + ESTAGES - 1) % ESTAGES);
        } else {
            asm volatile("cp.async.wait_group 0;");
            __syncthreads();
        }

        const uint32_t tb = sbase + (uint32_t)(c % ESTAGES) * ESTAGE;

        #pragma unroll
        for (int s = 0; s < 2; s++) {
            const uint32_t abase = tb
                + (uint32_t)((mw*32 + (lane & 15)) * GPITCH)
                + (uint32_t)(s*32 + (lane >> 4)*16);
            uint32_t bb[2];
            #pragma unroll
            for (int p = 0; p < 2; p++) {
                uint32_t brow = (uint32_t)(nw*32 + p*16 + (lane & 7) + ((lane >> 4) & 1)*8);
                bb[p] = tb + ETILE_A + brow * GPITCH
                      + (uint32_t)(s*32 + ((lane >> 3) & 1)*16);
            }

            uint32_t b0[4], b1[4];
            ldsm4(b0, bb[0]);
            ldsm4(b1, bb[1]);

            uint32_t aF[2][4];
            ldsm4(aF[0], abase);
            ldsm4(aF[1], abase + (uint32_t)(16 * GPITCH));
            #pragma unroll
            for (int f = 0; f < 2; f++) {
                mma16816(acc[f][0], aF[f], b0[0], b0[1]);
                mma16816(acc[f][1], aF[f], b0[2], b0[3]);
                mma16816(acc[f][2], aF[f], b1[0], b1[1]);
                mma16816(acc[f][3], aF[f], b1[2], b1[3]);
            }
        }
    }

    #pragma unroll
    for (int f = 0; f < 2; f++) {
        long row = m0 + mw*32 + f*16 + (lane >> 2);
        #pragma unroll
        for (int g = 0; g < 4; g++) {
            int col = n0 + nw*32 + g*8 + (lane & 3)*2;
            if (col < N) {
                float bx = bias[col], by = bias[col + 1];
                float2 v0 = make_float2(acc[f][g][0] + bx, acc[f][g][1] + by);
                float2 v1 = make_float2(acc[f][g][2] + bx, acc[f][g][3] + by);
                *reinterpret_cast<float2*>(C + row * N + col)       = v0;
                *reinterpret_cast<float2*>(C + (row + 8) * N + col) = v1;
            }
        }
    }
}

// ===========================================================================
// Persistent recurrence kernel (phases B, D). 256 threads, 8 k-split warps.
// Epilogue emits H[t] fp32 + fp16 hi/lo splits.
// ===========================================================================
#define TK   128
#define HSP  65
#define RNB  128
#define RNT  256
#define SM_WS   0
#define SM_HS   (8*1024)
#define SM_RED  (SM_HS + 2*TK*HSP)
#define SM_BYTES  131072

__global__ __launch_bounds__(RNT, 1)
void rnn_layer(const float* __restrict__ h0init,
               const float* __restrict__ W,
               const float* __restrict__ X,
               float* __restrict__ H,
               __half* __restrict__ Hh,
               __half* __restrict__ Hl)
{
    extern __shared__ float sm[];
    float* Ws  = sm + SM_WS;
    float* hs  = sm + SM_HS;
    float* red = sm + SM_RED;

    const int tid  = threadIdx.x;
    const int lane = tid & 31;
    const int warp = tid >> 5;
    const int j0   = blockIdx.x * 8;

    for (int i = tid; i < 8*1024/4; i += RNT) {
        int j  = i >> 8;
        int kq = i & 255;
        float4 v = *reinterpret_cast<const float4*>(W + (long)(j0 + j) * HID + kq * 4);
        *reinterpret_cast<float4*>(Ws + j*1024 + kq*4) = v;
    }
    __syncthreads();

    const uint32_t hs_s = (uint32_t)__cvta_generic_to_shared(hs);
    const int lc = tid >> 1;
    const int lh = (tid & 1) * 32;

    for (int t = 0; t < SEQ; t++) {
        const float* hprev = (t == 0) ? h0init : (H + (long)(t-1) * STEP);

        float acc0[8], acc1[8];
        #pragma unroll
        for (int j = 0; j < 8; j++) { acc0[j] = 0.f; acc1[j] = 0.f; }

        {
            const float* src = hprev + (long)lh * HID + lc;
            uint32_t dst = hs_s + (uint32_t)(lc * HSP + lh) * 4u;
            #pragma unroll 16
            for (int b = 0; b < 32; b++)
                asm volatile("cp.async.ca.shared.global [%0], [%1], 4;"
                             :: "r"(dst + b*4u), "l"(src + (long)b*HID));
            asm volatile("cp.async.commit_group;");
        }

        int buf = 0;
        #pragma unroll 1
        for (int tile = 0; tile < 8; tile++) {
            if (tile < 7) {
                const float* src = hprev + (long)lh * HID + (tile+1)*TK + lc;
                uint32_t dst = hs_s + (uint32_t)(((buf^1)*TK + lc) * HSP + lh) * 4u;
                #pragma unroll 16
                for (int b = 0; b < 32; b++)
                    asm volatile("cp.async.ca.shared.global [%0], [%1], 4;"
                                 :: "r"(dst + b*4u), "l"(src + (long)b*HID));
                asm volatile("cp.async.commit_group;");
                asm volatile("cp.async.wait_group 1;");
            } else {
                asm volatile("cp.async.wait_group 0;");
            }
            __syncthreads();

            const float* hb = hs + buf*TK*HSP;
            const int kwarp = warp * 16;
            #pragma unroll
            for (int q = 0; q < 4; q++) {
                const int kl = kwarp + q*4;
                float h0[4], h1[4];
                #pragma unroll
                for (int i = 0; i < 4; i++) {
                    h0[i] = hb[(kl+i)*HSP + lane];
                    h1[i] = hb[(kl+i)*HSP + lane + 32];
                }
                const int kg = tile*TK + kl;
                #pragma unroll
                for (int j = 0; j < 8; j++) {
                    float4 w = *reinterpret_cast<const float4*>(Ws + j*1024 + kg);
                    acc0[j] = fmaf(h0[0], w.x, acc0[j]);
                    acc0[j] = fmaf(h0[1], w.y, acc0[j]);
                    acc0[j] = fmaf(h0[2], w.z, acc0[j]);
                    acc0[j] = fmaf(h0[3], w.w, acc0[j]);
                    acc1[j] = fmaf(h1[0], w.x, acc1[j]);
                    acc1[j] = fmaf(h1[1], w.y, acc1[j]);
                    acc1[j] = fmaf(h1[2], w.z, acc1[j]);
                    acc1[j] = fmaf(h1[3], w.w, acc1[j]);
                }
            }
            __syncthreads();
            buf ^= 1;
        }

        #pragma unroll
        for (int j = 0; j < 8; j++) {
            red[((warp*2 + 0)*32 + lane)*9 + j] = acc0[j];
            red[((warp*2 + 1)*32 + lane)*9 + j] = acc1[j];
        }
        __syncthreads();

        const float* Xt = X + (long)t * STEP;
        float*       Ht = H + (long)t * STEP;
        __half* HhT = Hh + (long)t * STEP;
        __half* HlT = Hl + (long)t * STEP;
        #pragma unroll
        for (int i = 0; i < 2; i++) {
            int o   = tid + i*256;
            int g   = o >> 8;
            int rem = o & 255;
            int l   = rem >> 3;
            int j   = rem & 7;
            float s = 0.f;
            #pragma unroll
            for (int w = 0; w < 8; w++)
                s += red[((w*2 + g)*32 + l)*9 + j];
            int b   = g*32 + l;
            int col = j0 + j;
            long idx = (long)b*HID + col;
            float hv = tanhf(s + Xt[idx]);
            Ht[idx] = hv;
            __half hi = __float2half_rn(hv);
            HhT[idx] = hi;
            HlT[idx] = __float2half_rn(hv - __half2float(hi));
        }

        __threadfence();
        __syncthreads();
        if (tid == 0) {
            atomicAdd(&g_cnt[t], 1u);
            while (*((volatile unsigned*)&g_cnt[t]) < (unsigned)RNB) {
                __nanosleep(40);
            }
            if (blockIdx.x == 0)
                atomicExch(&g_cnt[(t + 126) & 127], 0u);
        }
        __syncthreads();
        __threadfence();
    }
}

// ===========================================================================
// One merged prep kernel: all weight/embedding fp16 conversions.
// ===========================================================================
#define N_EMBV (VOCAB*EMB)
#define N_W0X  (HID*EMB)
#define N_W1X  (HID*HID)
#define N_WO   (VOCAB*HID)
#define N_PREP (N_EMBV + N_W0X + N_W1X + N_WO)

__global__ void prep_weights(const float* __restrict__ emb, const float* __restrict__ W0x,
                             const float* __restrict__ W1x, const float* __restrict__ Wout,
                             __half* __restrict__ EmbH, __half* __restrict__ EmbL,
                             __half* __restrict__ W0xH, __half* __restrict__ W0xL,
                             __half* __restrict__ W1xH, __half* __restrict__ W1xL,
                             __half* __restrict__ WoH)
{
    long i = (long)blockIdx.x * blockDim.x + threadIdx.x;
    if (i < N_EMBV) {
        float x = emb[i];
        __half h = __float2half_rn(x);
        EmbH[i] = h;
        EmbL[i] = __float2half_rn(x - __half2float(h));
    } else if (i < N_EMBV + N_W0X) {
        long k = i - N_EMBV;
        float x = W0x[k];
        __half h = __float2half_rn(x);
        W0xH[k] = h;
        W0xL[k] = __float2half_rn(x - __half2float(h));
    } else if (i < N_EMBV + N_W0X + N_W1X) {
        long k = i - N_EMBV - N_W0X;
        float x = W1x[k];
        __half h = __float2half_rn(x);
        W1xH[k] = h;
        W1xL[k] = __float2half_rn(x - __half2float(h));
    } else if (i < N_PREP) {
        long k = i - N_EMBV - N_W0X - N_W1X;
        WoH[k] = __float2half_rn(Wout[k]);
    }
}

// ---------------------------------------------------------------------------
__global__ void copy_tail(float* __restrict__ dst)
{
    int i = blockIdx.x * blockDim.x + threadIdx.x;
    if (i < STEP)          dst[i] = g_H0[(long)(SEQ - 1) * STEP + i];
    else if (i < 2 * STEP) dst[i] = g_H1[(long)(SEQ - 1) * STEP + (i - STEP)];
}

// ---------------------------------------------------------------------------
extern "C" void kernel_launch(void* const* d_in, const int* in_sizes, int n_in,
                              void* d_out, int out_size)
{
    const int*   tok    = (const int*)  d_in[0];
    const float* hidden = (const float*)d_in[1];
    const float* emb    = (const float*)d_in[2];
    const float* W0x    = (const float*)d_in[3];
    const float* W0h    = (const float*)d_in[4];
    const float* b0     = (const float*)d_in[5];
    const float* W1x    = (const float*)d_in[6];
    const float* W1h    = (const float*)d_in[7];
    const float* b1     = (const float*)d_in[8];
    const float* Wout   = (const float*)d_in[9];
    const float* bout   = (const float*)d_in[10];
    float* out = (float*)d_out;

    float *X0, *H0, *X1, *H1;
    __half *EmbH, *EmbL, *W0xH, *W0xL, *W1xH, *W1xL, *WoH;
    __half *A0H, *A0L, *A1H, *A1L;
    cudaGetSymbolAddress((void**)&X0, g_X0);
    cudaGetSymbolAddress((void**)&H0, g_H0);
    cudaGetSymbolAddress((void**)&X1, g_X1);
    cudaGetSymbolAddress((void**)&H1, g_H1);
    cudaGetSymbolAddress((void**)&EmbH, g_EmbH);
    cudaGetSymbolAddress((void**)&EmbL, g_EmbL);
    cudaGetSymbolAddress((void**)&W0xH, g_W0xH);
    cudaGetSymbolAddress((void**)&W0xL, g_W0xL);
    cudaGetSymbolAddress((void**)&W1xH, g_W1xH);
    cudaGetSymbolAddress((void**)&W1xL, g_W1xL);
    cudaGetSymbolAddress((void**)&WoH, g_WoH);
    cudaGetSymbolAddress((void**)&A0H, g_A0H);
    cudaGetSymbolAddress((void**)&A0L, g_A0L);
    cudaGetSymbolAddress((void**)&A1H, g_A1H);
    cudaGetSymbolAddress((void**)&A1L, g_A1L);

    static bool attr_set = false;
    if (!attr_set) {
        cudaFuncSetAttribute(rnn_layer,
                             cudaFuncAttributeMaxDynamicSharedMemorySize, SM_BYTES);
        cudaFuncSetAttribute(mma_gemm3<true>,
                             cudaFuncAttributeMaxDynamicSharedMemorySize, 2*4*TILE_B);
        cudaFuncSetAttribute(mma_gemm3<false>,
                             cudaFuncAttributeMaxDynamicSharedMemorySize, 2*4*TILE_B);
        cudaFuncSetAttribute(mma_gemm1,
                             cudaFuncAttributeMaxDynamicSharedMemorySize, ESTAGES*ESTAGE);
        attr_set = true;
    }

    // Prep: all weight/embedding conversions in one launch
    prep_weights<<<(N_PREP + 255)/256, 256>>>(emb, W0x, W1x, Wout,
        EmbH, EmbL, W0xH, W0xL, W1xH, W1xL, WoH);

    // Phase A: X0 = emb[tok] @ W0x^T + b0   (3-term, gathered)
    mma_gemm3<true><<<dim3(HID/128, MB/128), 256, 2*4*TILE_B>>>(
        EmbH, EmbL, tok, W0xH, W0xL, b0, X0, MB, HID, EMB);

    // Phase B: layer-0 recurrence (emits H0 + fp16 splits)
    rnn_layer<<<RNB, RNT, SM_BYTES>>>(hidden, W0h, X0, H0, A0H, A0L);

    // Phase C: X1 = H0 @ W1x^T + b1   (3-term)
    mma_gemm3<false><<<dim3(HID/128, MB/128), 256, 2*4*TILE_B>>>(
        A0H, A0L, nullptr, W1xH, W1xL, b1, X1, MB, HID, HID);

    // Phase D: layer-1 recurrence (emits H1 + fp16 splits)
    rnn_layer<<<RNB, RNT, SM_BYTES>>>(hidden + STEP, W1h, X1, H1, A1H, A1L);

    // Phase E: logits = H1 @ Wout^T + bout   (1-term fp16, 64x128 tiles)
    mma_gemm1<<<dim3((VOCAB + 127)/128, MB/64), 256, ESTAGES*ESTAGE>>>(
        A1H, WoH, bout, out, MB, VOCAB, HID);

    // Tail
    copy_tail<<<(2*STEP + 255)/256, 256>>>(out + (long)SEQ * BATCH * VOCAB);
}

// round 13
// speedup vs baseline: 2.9163x; 1.0346x over previous
#include <cuda_runtime.h>
#include <cuda_fp16.h>
#include <cstdint>

// Problem constants
#define SEQ    128
#define BATCH  64
#define EMB    512
#define HID    1024
#define VOCAB  10000
#define MB     (SEQ*BATCH)        // 8192 rows when time-batched
#define STEP   (BATCH*HID)        // 65536 floats per timestep slab

// Scratch (device globals)
__device__ float g_X0[MB*HID];
__device__ float g_H0[MB*HID];
__device__ float g_X1[MB*HID];
__device__ float g_H1[MB*HID];
__device__ unsigned g_cnt[128];
// fp16 split operands for tensor-core GEMMs
__device__ __half g_EmbH[VOCAB*EMB], g_EmbL[VOCAB*EMB];
__device__ __half g_W0xH[HID*EMB],   g_W0xL[HID*EMB];
__device__ __half g_W1xH[HID*HID],   g_W1xL[HID*HID];
__device__ __half g_WoH[VOCAB*HID];                      // single fp16 (1-term path)
__device__ __half g_A0H[MB*HID],     g_A0L[MB*HID];      // H0 splits
__device__ __half g_A1H[MB*HID],     g_A1L[MB*HID];      // H1 splits

#define GPITCH 80                     // bytes per smem tile row (BK=32 kernels)
#define TILE_B (128*GPITCH)           // 10240 B per 128-row tile

__device__ __forceinline__ void ldsm4(uint32_t* r, uint32_t addr) {
    asm volatile("ldmatrix.sync.aligned.m8n8.x4.shared.b16 {%0,%1,%2,%3}, [%4];"
                 : "=r"(r[0]), "=r"(r[1]), "=r"(r[2]), "=r"(r[3]) : "r"(addr));
}
__device__ __forceinline__ void mma16816(float* d, const uint32_t* a, uint32_t b0, uint32_t b1) {
    asm volatile(
        "mma.sync.aligned.m16n8k16.row.col.f32.f16.f16.f32 "
        "{%0,%1,%2,%3}, {%4,%5,%6,%7}, {%8,%9}, {%0,%1,%2,%3};"
        : "+f"(d[0]), "+f"(d[1]), "+f"(d[2]), "+f"(d[3])
        : "r"(a[0]), "r"(a[1]), "r"(a[2]), "r"(a[3]), "r"(b0), "r"(b1));
}
__device__ __forceinline__ void cpa16(uint32_t dst, const void* src) {
    asm volatile("cp.async.cg.shared.global [%0], [%1], 16;" :: "r"(dst), "l"(src));
}
__device__ __forceinline__ void cpa16z(uint32_t dst, const void* src, uint32_t sz) {
    asm volatile("cp.async.cg.shared.global [%0], [%1], 16, %2;" :: "r"(dst), "l"(src), "r"(sz));
}

// ===========================================================================
// 3-term GEMM (phases A, C): tile 128x128, BK=32, 8 warps (2m x 4n),
// 2-stage pipeline. Term-major MMA order.  (unchanged)
// ===========================================================================
template<bool GATHER>
__global__ __launch_bounds__(256, 2)
void mma_gemm3(const __half* __restrict__ Ah, const __half* __restrict__ Al,
               const int* __restrict__ rows,
               const __half* __restrict__ Bh, const __half* __restrict__ Bl,
               const float* __restrict__ bias, float* __restrict__ C,
               int M, int N, int K)
{
    constexpr uint32_t BUF_B = 4 * TILE_B;
    extern __shared__ char smem[];
    const int tid  = threadIdx.x;
    const int lane = tid & 31;
    const int wid  = tid >> 5;
    const int mw   = wid >> 2;        // 0..1
    const int nw   = wid & 3;         // 0..3
    const int m0   = blockIdx.y * 128;
    const int n0   = blockIdx.x * 128;

    const uint32_t sbase = (uint32_t)__cvta_generic_to_shared(smem);

    float acc[4][4][4];
    #pragma unroll
    for (int f = 0; f < 4; f++)
        #pragma unroll
        for (int g = 0; g < 4; g++)
            #pragma unroll
            for (int e = 0; e < 4; e++) acc[f][g][e] = 0.f;

    const int nchunks = K >> 5;

    auto load_chunk = [&](int kt, int b) {
        const uint32_t tb = sbase + (uint32_t)b * BUF_B;
        #pragma unroll
        for (int i = 0; i < 2; i++) {
            int l  = tid + i * 256;        // 0..511
            int r  = l & 127;
            int cb = l >> 7;               // 0..3
            uint32_t doff = (uint32_t)(r * GPITCH + cb * 16);
            long ar = GATHER ? (long)rows[m0 + r] : (long)(m0 + r);
            cpa16(tb + doff,          Ah + ar * K + kt + cb * 8);
            cpa16(tb + TILE_B + doff, Al + ar * K + kt + cb * 8);
            int nr = n0 + r;
            uint32_t sz = (nr < N) ? 16u : 0u;
            long br = (nr < N) ? (long)nr : (long)(N - 1);
            cpa16z(tb + 2*TILE_B + doff, Bh + br * K + kt + cb * 8, sz);
            cpa16z(tb + 3*TILE_B + doff, Bl + br * K + kt + cb * 8, sz);
        }
        asm volatile("cp.async.commit_group;");
    };

    load_chunk(0, 0);

    #pragma unroll 1
    for (int c = 0; c < nchunks; c++) {
        asm volatile("cp.async.wait_group 0;");
        __syncthreads();
        if (c + 1 < nchunks)
            load_chunk((c + 1) << 5, (c + 1) & 1);

        const uint32_t tb = sbase + (uint32_t)(c & 1) * BUF_B;

        #pragma unroll
        for (int s = 0; s < 2; s++) {
            const uint32_t abase = tb
                + (uint32_t)((mw*64 + (lane & 15)) * GPITCH)
                + (uint32_t)(s*32 + (lane >> 4)*16);
            uint32_t bb[2];
            #pragma unroll
            for (int p = 0; p < 2; p++) {
                uint32_t brow = (uint32_t)(nw*32 + p*16 + (lane & 7) + ((lane >> 4) & 1)*8);
                bb[p] = tb + 2*TILE_B + brow * GPITCH
                      + (uint32_t)(s*32 + ((lane >> 3) & 1)*16);
            }

            uint32_t bh0[4], bh1[4], bl0[4], bl1[4];
            ldsm4(bh0, bb[0]);
            ldsm4(bh1, bb[1]);
            ldsm4(bl0, bb[0] + TILE_B);
            ldsm4(bl1, bb[1] + TILE_B);

            uint32_t aF[4][4];
            #pragma unroll
            for (int f = 0; f < 4; f++)
                ldsm4(aF[f], abase + (uint32_t)(f * 16 * GPITCH));

            // Term 1: Ah x Bh
            #pragma unroll
            for (int f = 0; f < 4; f++) {
                mma16816(acc[f][0], aF[f], bh0[0], bh0[1]);
                mma16816(acc[f][1], aF[f], bh0[2], bh0[3]);
                mma16816(acc[f][2], aF[f], bh1[0], bh1[1]);
                mma16816(acc[f][3], aF[f], bh1[2], bh1[3]);
            }
            // Term 2: Ah x Bl
            #pragma unroll
            for (int f = 0; f < 4; f++) {
                mma16816(acc[f][0], aF[f], bl0[0], bl0[1]);
                mma16816(acc[f][1], aF[f], bl0[2], bl0[3]);
                mma16816(acc[f][2], aF[f], bl1[0], bl1[1]);
                mma16816(acc[f][3], aF[f], bl1[2], bl1[3]);
            }
            // Term 3: Al x Bh
            #pragma unroll
            for (int f = 0; f < 4; f++)
                ldsm4(aF[f], abase + TILE_B + (uint32_t)(f * 16 * GPITCH));
            #pragma unroll
            for (int f = 0; f < 4; f++) {
                mma16816(acc[f][0], aF[f], bh0[0], bh0[1]);
                mma16816(acc[f][1], aF[f], bh0[2], bh0[3]);
                mma16816(acc[f][2], aF[f], bh1[0], bh1[1]);
                mma16816(acc[f][3], aF[f], bh1[2], bh1[3]);
            }
        }
    }

    #pragma unroll
    for (int f = 0; f < 4; f++) {
        long row = m0 + mw*64 + f*16 + (lane >> 2);
        #pragma unroll
        for (int g = 0; g < 4; g++) {
            int col = n0 + nw*32 + g*8 + (lane & 3)*2;
            if (col < N) {
                float bx = bias[col], by = bias[col + 1];
                float2 v0 = make_float2(acc[f][g][0] + bx, acc[f][g][1] + by);
                float2 v1 = make_float2(acc[f][g][2] + bx, acc[f][g][3] + by);
                *reinterpret_cast<float2*>(C + row * N + col)       = v0;
                *reinterpret_cast<float2*>(C + (row + 8) * N + col) = v1;
            }
        }
    }
}

// ===========================================================================
// 1-term GEMM (phase E): C = Ah @ Bh^T + bias.
// CTA tile 128x128, BK=64, 8 warps (2m x 4n), warp tile 64x32.
// Per chunk per warp: 24 ldsm.x4 + 64 MMAs; only 16 chunks (16 syncs).
// Stage = 256 rows x 144 B = 36864 B; 2-stage = 73728 B -> 2 CTAs/SM.
// ===========================================================================
#define EPITCH  144                    // 128 B data (64 halfs) + 16 pad
#define ETILE   (128*EPITCH)           // 18432 B per 128-row tile
#define ESTAGE  (2*ETILE)              // A + B = 36864 B
#define ESTAGES 2

__global__ __launch_bounds__(256, 2)
void mma_gemm1(const __half* __restrict__ Ah,
               const __half* __restrict__ Bh,
               const float* __restrict__ bias, float* __restrict__ C,
               int M, int N, int K)
{
    extern __shared__ char smem[];
    const int tid  = threadIdx.x;
    const int lane = tid & 31;
    const int wid  = tid >> 5;
    const int mw   = wid >> 2;        // 0..1 (m-warp)
    const int nw   = wid & 3;         // 0..3 (n-warp)
    const int m0   = blockIdx.y * 128;
    const int n0   = blockIdx.x * 128;

    const uint32_t sbase = (uint32_t)__cvta_generic_to_shared(smem);

    float acc[4][4][4];
    #pragma unroll
    for (int f = 0; f < 4; f++)
        #pragma unroll
        for (int g = 0; g < 4; g++)
            #pragma unroll
            for (int e = 0; e < 4; e++) acc[f][g][e] = 0.f;

    const int nchunks = K >> 6;        // BK = 64

    // 2048 16B-transfers per stage: 1024 A + 1024 B (8 per thread)
    auto load_chunk = [&](int kt, int b) {
        const uint32_t tb = sbase + (uint32_t)b * ESTAGE;
        #pragma unroll
        for (int i = 0; i < 4; i++) {
            int idx = tid + i * 256;       // 0..1023
            int r  = idx >> 3;
            int cb = idx & 7;              // 0..7 (16B sub-col)
            uint32_t doff = (uint32_t)(r * EPITCH + cb * 16);
            cpa16(tb + doff, Ah + (long)(m0 + r) * K + kt + cb * 8);
            int nr = n0 + r;
            uint32_t sz = (nr < N) ? 16u : 0u;
            long br = (nr < N) ? (long)nr : (long)(N - 1);
            cpa16z(tb + ETILE + doff, Bh + br * K + kt + cb * 8, sz);
        }
        asm volatile("cp.async.commit_group;");
    };

    load_chunk(0, 0);

    #pragma unroll 1
    for (int c = 0; c < nchunks; c++) {
        asm volatile("cp.async.wait_group 0;");
        __syncthreads();
        if (c + 1 < nchunks)
            load_chunk((c + 1) << 6, (c + 1) & 1);

        const uint32_t tb = sbase + (uint32_t)(c & 1) * ESTAGE;

        #pragma unroll
        for (int s = 0; s < 4; s++) {      // 4 k16 steps per 64-chunk
            const uint32_t abase = tb
                + (uint32_t)((mw*64 + (lane & 15)) * EPITCH)
                + (uint32_t)(s*32 + (lane >> 4)*16);
            uint32_t bb[2];
            #pragma unroll
            for (int p = 0; p < 2; p++) {
                uint32_t brow = (uint32_t)(nw*32 + p*16 + (lane & 7) + ((lane >> 4) & 1)*8);
                bb[p] = tb + ETILE + brow * EPITCH
                      + (uint32_t)(s*32 + ((lane >> 3) & 1)*16);
            }

            uint32_t b0[4], b1[4];
            ldsm4(b0, bb[0]);
            ldsm4(b1, bb[1]);

            uint32_t aF[4][4];
            #pragma unroll
            for (int f = 0; f < 4; f++)
                ldsm4(aF[f], abase + (uint32_t)(f * 16 * EPITCH));

            #pragma unroll
            for (int f = 0; f < 4; f++) {
                mma16816(acc[f][0], aF[f], b0[0], b0[1]);
                mma16816(acc[f][1], aF[f], b0[2], b0[3]);
                mma16816(acc[f][2], aF[f], b1[0], b1[1]);
                mma16816(acc[f][3], aF[f], b1[2], b1[3]);
            }
        }
    }

    #pragma unroll
    for (int f = 0; f < 4; f++) {
        long row = m0 + mw*64 + f*16 + (lane >> 2);
        #pragma unroll
        for (int g = 0; g < 4; g++) {
            int col = n0 + nw*32 + g*8 + (lane & 3)*2;
            if (col < N) {
                float bx = bias[col], by = bias[col + 1];
                float2 v0 = make_float2(acc[f][g][0] + bx, acc[f][g][1] + by);
                float2 v1 = make_float2(acc[f][g][2] + bx, acc[f][g][3] + by);
                *reinterpret_cast<float2*>(C + row * N + col)       = v0;
                *reinterpret_cast<float2*>(C + (row + 8) * N + col) = v1;
            }
        }
    }
}

// ===========================================================================
// Persistent recurrence kernel (phases B, D). 256 threads, 8 k-split warps.
// Epilogue emits H[t] fp32 + fp16 hi/lo splits.  (unchanged)
// ===========================================================================
#define TK   128
#define HSP  65
#define RNB  128
#define RNT  256
#define SM_WS   0
#define SM_HS   (8*1024)
#define SM_RED  (SM_HS + 2*TK*HSP)
#define SM_BYTES  131072

__global__ __launch_bounds__(RNT, 1)
void rnn_layer(const float* __restrict__ h0init,
               const float* __restrict__ W,
               const float* __restrict__ X,
               float* __restrict__ H,
               __half* __restrict__ Hh,
               __half* __restrict__ Hl)
{
    extern __shared__ float sm[];
    float* Ws  = sm + SM_WS;
    float* hs  = sm + SM_HS;
    float* red = sm + SM_RED;

    const int tid  = threadIdx.x;
    const int lane = tid & 31;
    const int warp = tid >> 5;
    const int j0   = blockIdx.x * 8;

    for (int i = tid; i < 8*1024/4; i += RNT) {
        int j  = i >> 8;
        int kq = i & 255;
        float4 v = *reinterpret_cast<const float4*>(W + (long)(j0 + j) * HID + kq * 4);
        *reinterpret_cast<float4*>(Ws + j*1024 + kq*4) = v;
    }
    __syncthreads();

    const uint32_t hs_s = (uint32_t)__cvta_generic_to_shared(hs);
    const int lc = tid >> 1;
    const int lh = (tid & 1) * 32;

    for (int t = 0; t < SEQ; t++) {
        const float* hprev = (t == 0) ? h0init : (H + (long)(t-1) * STEP);

        float acc0[8], acc1[8];
        #pragma unroll
        for (int j = 0; j < 8; j++) { acc0[j] = 0.f; acc1[j] = 0.f; }

        {
            const float* src = hprev + (long)lh * HID + lc;
            uint32_t dst = hs_s + (uint32_t)(lc * HSP + lh) * 4u;
            #pragma unroll 16
            for (int b = 0; b < 32; b++)
                asm volatile("cp.async.ca.shared.global [%0], [%1], 4;"
                             :: "r"(dst + b*4u), "l"(src + (long)b*HID));
            asm volatile("cp.async.commit_group;");
        }

        int buf = 0;
        #pragma unroll 1
        for (int tile = 0; tile < 8; tile++) {
            if (tile < 7) {
                const float* src = hprev + (long)lh * HID + (tile+1)*TK + lc;
                uint32_t dst = hs_s + (uint32_t)(((buf^1)*TK + lc) * HSP + lh) * 4u;
                #pragma unroll 16
                for (int b = 0; b < 32; b++)
                    asm volatile("cp.async.ca.shared.global [%0], [%1], 4;"
                                 :: "r"(dst + b*4u), "l"(src + (long)b*HID));
                asm volatile("cp.async.commit_group;");
                asm volatile("cp.async.wait_group 1;");
            } else {
                asm volatile("cp.async.wait_group 0;");
            }
            __syncthreads();

            const float* hb = hs + buf*TK*HSP;
            const int kwarp = warp * 16;
            #pragma unroll
            for (int q = 0; q < 4; q++) {
                const int kl = kwarp + q*4;
                float h0[4], h1[4];
                #pragma unroll
                for (int i = 0; i < 4; i++) {
                    h0[i] = hb[(kl+i)*HSP + lane];
                    h1[i] = hb[(kl+i)*HSP + lane + 32];
                }
                const int kg = tile*TK + kl;
                #pragma unroll
                for (int j = 0; j < 8; j++) {
                    float4 w = *reinterpret_cast<const float4*>(Ws + j*1024 + kg);
                    acc0[j] = fmaf(h0[0], w.x, acc0[j]);
                    acc0[j] = fmaf(h0[1], w.y, acc0[j]);
                    acc0[j] = fmaf(h0[2], w.z, acc0[j]);
                    acc0[j] = fmaf(h0[3], w.w, acc0[j]);
                    acc1[j] = fmaf(h1[0], w.x, acc1[j]);
                    acc1[j] = fmaf(h1[1], w.y, acc1[j]);
                    acc1[j] = fmaf(h1[2], w.z, acc1[j]);
                    acc1[j] = fmaf(h1[3], w.w, acc1[j]);
                }
            }
            __syncthreads();
            buf ^= 1;
        }

        #pragma unroll
        for (int j = 0; j < 8; j++) {
            red[((warp*2 + 0)*32 + lane)*9 + j] = acc0[j];
            red[((warp*2 + 1)*32 + lane)*9 + j] = acc1[j];
        }
        __syncthreads();

        const float* Xt = X + (long)t * STEP;
        float*       Ht = H + (long)t * STEP;
        __half* HhT = Hh + (long)t * STEP;
        __half* HlT = Hl + (long)t * STEP;
        #pragma unroll
        for (int i = 0; i < 2; i++) {
            int o   = tid + i*256;
            int g   = o >> 8;
            int rem = o & 255;
            int l   = rem >> 3;
            int j   = rem & 7;
            float s = 0.f;
            #pragma unroll
            for (int w = 0; w < 8; w++)
                s += red[((w*2 + g)*32 + l)*9 + j];
            int b   = g*32 + l;
            int col = j0 + j;
            long idx = (long)b*HID + col;
            float hv = tanhf(s + Xt[idx]);
            Ht[idx] = hv;
            __half hi = __float2half_rn(hv);
            HhT[idx] = hi;
            HlT[idx] = __float2half_rn(hv - __half2float(hi));
        }

        __threadfence();
        __syncthreads();
        if (tid == 0) {
            atomicAdd(&g_cnt[t], 1u);
            while (*((volatile unsigned*)&g_cnt[t]) < (unsigned)RNB) {
                __nanosleep(40);
            }
            if (blockIdx.x == 0)
                atomicExch(&g_cnt[(t + 126) & 127], 0u);
        }
        __syncthreads();
        __threadfence();
    }
}

// ===========================================================================
// One merged prep kernel: all weight/embedding fp16 conversions.
// ===========================================================================
#define N_EMBV (VOCAB*EMB)
#define N_W0X  (HID*EMB)
#define N_W1X  (HID*HID)
#define N_WO   (VOCAB*HID)
#define N_PREP (N_EMBV + N_W0X + N_W1X + N_WO)

__global__ void prep_weights(const float* __restrict__ emb, const float* __restrict__ W0x,
                             const float* __restrict__ W1x, const float* __restrict__ Wout,
                             __half* __restrict__ EmbH, __half* __restrict__ EmbL,
                             __half* __restrict__ W0xH, __half* __restrict__ W0xL,
                             __half* __restrict__ W1xH, __half* __restrict__ W1xL,
                             __half* __restrict__ WoH)
{
    long i = (long)blockIdx.x * blockDim.x + threadIdx.x;
    if (i < N_EMBV) {
        float x = emb[i];
        __half h = __float2half_rn(x);
        EmbH[i] = h;
        EmbL[i] = __float2half_rn(x - __half2float(h));
    } else if (i < N_EMBV + N_W0X) {
        long k = i - N_EMBV;
        float x = W0x[k];
        __half h = __float2half_rn(x);
        W0xH[k] = h;
        W0xL[k] = __float2half_rn(x - __half2float(h));
    } else if (i < N_EMBV + N_W0X + N_W1X) {
        long k = i - N_EMBV - N_W0X;
        float x = W1x[k];
        __half h = __float2half_rn(x);
        W1xH[k] = h;
        W1xL[k] = __float2half_rn(x - __half2float(h));
    } else if (i < N_PREP) {
        long k = i - N_EMBV - N_W0X - N_W1X;
        WoH[k] = __float2half_rn(Wout[k]);
    }
}

// ---------------------------------------------------------------------------
__global__ void copy_tail(float* __restrict__ dst)
{
    int i = blockIdx.x * blockDim.x + threadIdx.x;
    if (i < STEP)          dst[i] = g_H0[(long)(SEQ - 1) * STEP + i];
    else if (i < 2 * STEP) dst[i] = g_H1[(long)(SEQ - 1) * STEP + (i - STEP)];
}

// ---------------------------------------------------------------------------
extern "C" void kernel_launch(void* const* d_in, const int* in_sizes, int n_in,
                              void* d_out, int out_size)
{
    const int*   tok    = (const int*)  d_in[0];
    const float* hidden = (const float*)d_in[1];
    const float* emb    = (const float*)d_in[2];
    const float* W0x    = (const float*)d_in[3];
    const float* W0h    = (const float*)d_in[4];
    const float* b0     = (const float*)d_in[5];
    const float* W1x    = (const float*)d_in[6];
    const float* W1h    = (const float*)d_in[7];
    const float* b1     = (const float*)d_in[8];
    const float* Wout   = (const float*)d_in[9];
    const float* bout   = (const float*)d_in[10];
    float* out = (float*)d_out;

    float *X0, *H0, *X1, *H1;
    __half *EmbH, *EmbL, *W0xH, *W0xL, *W1xH, *W1xL, *WoH;
    __half *A0H, *A0L, *A1H, *A1L;
    cudaGetSymbolAddress((void**)&X0, g_X0);
    cudaGetSymbolAddress((void**)&H0, g_H0);
    cudaGetSymbolAddress((void**)&X1, g_X1);
    cudaGetSymbolAddress((void**)&H1, g_H1);
    cudaGetSymbolAddress((void**)&EmbH, g_EmbH);
    cudaGetSymbolAddress((void**)&EmbL, g_EmbL);
    cudaGetSymbolAddress((void**)&W0xH, g_W0xH);
    cudaGetSymbolAddress((void**)&W0xL, g_W0xL);
    cudaGetSymbolAddress((void**)&W1xH, g_W1xH);
    cudaGetSymbolAddress((void**)&W1xL, g_W1xL);
    cudaGetSymbolAddress((void**)&WoH, g_WoH);
    cudaGetSymbolAddress((void**)&A0H, g_A0H);
    cudaGetSymbolAddress((void**)&A0L, g_A0L);
    cudaGetSymbolAddress((void**)&A1H, g_A1H);
    cudaGetSymbolAddress((void**)&A1L, g_A1L);

    static bool attr_set = false;
    if (!attr_set) {
        cudaFuncSetAttribute(rnn_layer,
                             cudaFuncAttributeMaxDynamicSharedMemorySize, SM_BYTES);
        cudaFuncSetAttribute(mma_gemm3<true>,
                             cudaFuncAttributeMaxDynamicSharedMemorySize, 2*4*TILE_B);
        cudaFuncSetAttribute(mma_gemm3<false>,
                             cudaFuncAttributeMaxDynamicSharedMemorySize, 2*4*TILE_B);
        cudaFuncSetAttribute(mma_gemm1,
                             cudaFuncAttributeMaxDynamicSharedMemorySize, ESTAGES*ESTAGE);
        attr_set = true;
    }

    // Prep: all weight/embedding conversions in one launch
    prep_weights<<<(N_PREP + 255)/256, 256>>>(emb, W0x, W1x, Wout,
        EmbH, EmbL, W0xH, W0xL, W1xH, W1xL, WoH);

    // Phase A: X0 = emb[tok] @ W0x^T + b0   (3-term, gathered)
    mma_gemm3<true><<<dim3(HID/128, MB/128), 256, 2*4*TILE_B>>>(
        EmbH, EmbL, tok, W0xH, W0xL, b0, X0, MB, HID, EMB);

    // Phase B: layer-0 recurrence (emits H0 + fp16 splits)
    rnn_layer<<<RNB, RNT, SM_BYTES>>>(hidden, W0h, X0, H0, A0H, A0L);

    // Phase C: X1 = H0 @ W1x^T + b1   (3-term)
    mma_gemm3<false><<<dim3(HID/128, MB/128), 256, 2*4*TILE_B>>>(
        A0H, A0L, nullptr, W1xH, W1xL, b1, X1, MB, HID, HID);

    // Phase D: layer-1 recurrence (emits H1 + fp16 splits)
    rnn_layer<<<RNB, RNT, SM_BYTES>>>(hidden + STEP, W1h, X1, H1, A1H, A1L);

    // Phase E: logits = H1 @ Wout^T + bout   (1-term fp16, 128x128, BK=64)
    mma_gemm1<<<dim3((VOCAB + 127)/128, MB/128), 256, ESTAGES*ESTAGE>>>(
        A1H, WoH, bout, out, MB, VOCAB, HID);

    // Tail
    copy_tail<<<(2*STEP + 255)/256, 256>>>(out + (long)SEQ * BATCH * VOCAB);
}